// round 1
// baseline (speedup 1.0000x reference)
#include <cuda_runtime.h>
#include <math.h>

// Problem constants
#define BB    4
#define NTOK  4096
#define DD    1024
#define HH    16
#define MM    128
#define DHH   64
#define SCALE 0.125f           // DH^-0.5 = 1/8
#define ROWS  (BB*NTOK)        // 16384
#define BH    (BB*HH)          // 64

// ---------------- device scratch (static, allowed) ----------------
__device__ float g_qkv[ROWS * 3072];            // (B*N, 3D): q|k|v interleaved per row
__device__ float g_qa [BH * NTOK * MM];         // (B,H,N,M) qa_sim -> softmax -> mixed (in place)
__device__ float g_ak [BH * MM * NTOK];         // (B,H,M,N) ak_sim -> softmax -> mixed (in place)
__device__ float g_gpart[8 * BH * MM * DHH];    // k-split partials for agent_gathered
__device__ float g_gather[BH * MM * DHH];       // (B,H,M,DH)
__device__ float g_gates[ROWS * HH];            // (B*N, H)
__device__ float g_out1[ROWS * DD];             // (B,N,D) gated, pre-W_out

// ---------------- generic 128x128x8 SIMT SGEMM (row-major, NN) ----------------
__global__ __launch_bounds__(256) void sgemm128(const float* __restrict__ A,
                                                const float* __restrict__ Bm,
                                                float* __restrict__ C,
                                                int Nc, int Kd) {
    __shared__ float As[8][128];
    __shared__ float Bs[8][128];
    int tid = threadIdx.x;
    const float* Ab = A + (size_t)blockIdx.y * 128 * Kd;
    const float* Bb = Bm + blockIdx.x * 128;
    float* Cb = C + (size_t)blockIdx.y * 128 * Nc + blockIdx.x * 128;
    int aRow = tid >> 1, aCol = (tid & 1) << 2;
    int bRow = tid >> 5, bCol = (tid & 31) << 2;
    int ty = tid >> 4, tx = tid & 15;
    float acc[8][8];
#pragma unroll
    for (int i = 0; i < 8; i++)
#pragma unroll
        for (int j = 0; j < 8; j++) acc[i][j] = 0.f;

    for (int k0 = 0; k0 < Kd; k0 += 8) {
        float4 av = *(const float4*)(Ab + (size_t)aRow * Kd + k0 + aCol);
        As[aCol + 0][aRow] = av.x; As[aCol + 1][aRow] = av.y;
        As[aCol + 2][aRow] = av.z; As[aCol + 3][aRow] = av.w;
        *(float4*)&Bs[bRow][bCol] = *(const float4*)(Bb + (size_t)(k0 + bRow) * Nc + bCol);
        __syncthreads();
#pragma unroll
        for (int k = 0; k < 8; k++) {
            float4 a0 = *(float4*)&As[k][ty * 8];
            float4 a1 = *(float4*)&As[k][ty * 8 + 4];
            float4 b0 = *(float4*)&Bs[k][tx * 8];
            float4 b1 = *(float4*)&Bs[k][tx * 8 + 4];
            float ar[8] = {a0.x, a0.y, a0.z, a0.w, a1.x, a1.y, a1.z, a1.w};
            float br[8] = {b0.x, b0.y, b0.z, b0.w, b1.x, b1.y, b1.z, b1.w};
#pragma unroll
            for (int i = 0; i < 8; i++)
#pragma unroll
                for (int j = 0; j < 8; j++) acc[i][j] += ar[i] * br[j];
        }
        __syncthreads();
    }
#pragma unroll
    for (int i = 0; i < 8; i++) {
        float* cr = Cb + (size_t)(ty * 8 + i) * Nc + tx * 8;
        *(float4*)cr       = make_float4(acc[i][0], acc[i][1], acc[i][2], acc[i][3]);
        *(float4*)(cr + 4) = make_float4(acc[i][4], acc[i][5], acc[i][6], acc[i][7]);
    }
}

// ---------------- gates: sigmoid(x @ W_gate + b) ----------------
__global__ __launch_bounds__(256) void gates_kernel(const float* __restrict__ x,
                                                    const float* __restrict__ Wg,
                                                    const float* __restrict__ bg) {
    __shared__ float xs[1024];
    int row = blockIdx.x;
    int tid = threadIdx.x;
    ((float4*)xs)[tid] = ((const float4*)(x + (size_t)row * 1024))[tid];
    __syncthreads();
    int w = tid >> 5, lane = tid & 31;
    float s0 = 0.f, s1 = 0.f;
    for (int d = lane; d < 1024; d += 32) {
        float xv = xs[d];
        s0 += xv * Wg[d * 16 + w];
        s1 += xv * Wg[d * 16 + w + 8];
    }
#pragma unroll
    for (int o = 16; o; o >>= 1) {
        s0 += __shfl_xor_sync(0xffffffffu, s0, o);
        s1 += __shfl_xor_sync(0xffffffffu, s1, o);
    }
    if (lane == 0) {
        g_gates[(size_t)row * 16 + w]     = 1.f / (1.f + expf(-(s0 + bg[w])));
        g_gates[(size_t)row * 16 + w + 8] = 1.f / (1.f + expf(-(s1 + bg[w + 8])));
    }
}

// ---------------- qa_sim: (4096x128) = Q(4096x64) @ (SCALE*a)^T ----------------
__global__ __launch_bounds__(256) void qa_sim_kernel(const float* __restrict__ agent) {
    int bh = blockIdx.y, b = bh >> 4, h = bh & 15;
    int n0 = blockIdx.x * 128;
    const float* Qb = g_qkv + ((size_t)(b * NTOK + n0)) * 3072 + h * 64;
    const float* Ab = agent + (size_t)h * MM * DHH;
    __shared__ float Qs[8][128];
    __shared__ float As[8][128];
    int tid = threadIdx.x;
    int r = tid >> 1, c = (tid & 1) << 2;
    int ty = tid >> 4, tx = tid & 15;
    float acc[8][8];
#pragma unroll
    for (int i = 0; i < 8; i++)
#pragma unroll
        for (int j = 0; j < 8; j++) acc[i][j] = 0.f;

    for (int k0 = 0; k0 < 64; k0 += 8) {
        float4 qv = *(const float4*)(Qb + (size_t)r * 3072 + k0 + c);
        Qs[c + 0][r] = qv.x; Qs[c + 1][r] = qv.y; Qs[c + 2][r] = qv.z; Qs[c + 3][r] = qv.w;
        float4 av = *(const float4*)(Ab + r * 64 + k0 + c);
        As[c + 0][r] = av.x * SCALE; As[c + 1][r] = av.y * SCALE;
        As[c + 2][r] = av.z * SCALE; As[c + 3][r] = av.w * SCALE;
        __syncthreads();
#pragma unroll
        for (int k = 0; k < 8; k++) {
            float4 a0 = *(float4*)&Qs[k][ty * 8];
            float4 a1 = *(float4*)&Qs[k][ty * 8 + 4];
            float4 b0 = *(float4*)&As[k][tx * 8];
            float4 b1 = *(float4*)&As[k][tx * 8 + 4];
            float ar[8] = {a0.x, a0.y, a0.z, a0.w, a1.x, a1.y, a1.z, a1.w};
            float br[8] = {b0.x, b0.y, b0.z, b0.w, b1.x, b1.y, b1.z, b1.w};
#pragma unroll
            for (int i = 0; i < 8; i++)
#pragma unroll
                for (int j = 0; j < 8; j++) acc[i][j] += ar[i] * br[j];
        }
        __syncthreads();
    }
    float* Ob = g_qa + ((size_t)bh * NTOK + n0) * 128;
#pragma unroll
    for (int i = 0; i < 8; i++) {
        float* cr = Ob + (size_t)(ty * 8 + i) * 128 + tx * 8;
        *(float4*)cr       = make_float4(acc[i][0], acc[i][1], acc[i][2], acc[i][3]);
        *(float4*)(cr + 4) = make_float4(acc[i][4], acc[i][5], acc[i][6], acc[i][7]);
    }
}

// ---------------- ak_sim: (128x4096) = (SCALE*a)(128x64) @ K^T ----------------
__global__ __launch_bounds__(256) void ak_sim_kernel(const float* __restrict__ agent) {
    int bh = blockIdx.y, b = bh >> 4, h = bh & 15;
    int n0 = blockIdx.x * 128;
    const float* Kb = g_qkv + ((size_t)(b * NTOK + n0)) * 3072 + 1024 + h * 64;
    const float* Ab = agent + (size_t)h * MM * DHH;
    __shared__ float As[8][128];   // a (m-dim)
    __shared__ float Ks[8][128];   // k (n-dim)
    int tid = threadIdx.x;
    int r = tid >> 1, c = (tid & 1) << 2;
    int ty = tid >> 4, tx = tid & 15;
    float acc[8][8];
#pragma unroll
    for (int i = 0; i < 8; i++)
#pragma unroll
        for (int j = 0; j < 8; j++) acc[i][j] = 0.f;

    for (int k0 = 0; k0 < 64; k0 += 8) {
        float4 av = *(const float4*)(Ab + r * 64 + k0 + c);
        As[c + 0][r] = av.x * SCALE; As[c + 1][r] = av.y * SCALE;
        As[c + 2][r] = av.z * SCALE; As[c + 3][r] = av.w * SCALE;
        float4 kv = *(const float4*)(Kb + (size_t)r * 3072 + k0 + c);
        Ks[c + 0][r] = kv.x; Ks[c + 1][r] = kv.y; Ks[c + 2][r] = kv.z; Ks[c + 3][r] = kv.w;
        __syncthreads();
#pragma unroll
        for (int k = 0; k < 8; k++) {
            float4 a0 = *(float4*)&As[k][ty * 8];
            float4 a1 = *(float4*)&As[k][ty * 8 + 4];
            float4 b0 = *(float4*)&Ks[k][tx * 8];
            float4 b1 = *(float4*)&Ks[k][tx * 8 + 4];
            float ar[8] = {a0.x, a0.y, a0.z, a0.w, a1.x, a1.y, a1.z, a1.w};
            float br[8] = {b0.x, b0.y, b0.z, b0.w, b1.x, b1.y, b1.z, b1.w};
#pragma unroll
            for (int i = 0; i < 8; i++)
#pragma unroll
                for (int j = 0; j < 8; j++) acc[i][j] += ar[i] * br[j];
        }
        __syncthreads();
    }
    float* Ob = g_ak + (size_t)bh * MM * NTOK + n0;
#pragma unroll
    for (int i = 0; i < 8; i++) {
        float* cr = Ob + (size_t)(ty * 8 + i) * NTOK + tx * 8;
        *(float4*)cr       = make_float4(acc[i][0], acc[i][1], acc[i][2], acc[i][3]);
        *(float4*)(cr + 4) = make_float4(acc[i][4], acc[i][5], acc[i][6], acc[i][7]);
    }
}

// ---------------- softmax over rows of 128 (one warp per row) ----------------
__global__ __launch_bounds__(256) void softmax128(float* __restrict__ p) {
    int warp = blockIdx.x * 8 + (threadIdx.x >> 5);
    int lane = threadIdx.x & 31;
    float4* row = (float4*)(p + (size_t)warp * 128);
    float4 v = row[lane];
    float mx = fmaxf(fmaxf(v.x, v.y), fmaxf(v.z, v.w));
#pragma unroll
    for (int o = 16; o; o >>= 1) mx = fmaxf(mx, __shfl_xor_sync(0xffffffffu, mx, o));
    v.x = expf(v.x - mx); v.y = expf(v.y - mx); v.z = expf(v.z - mx); v.w = expf(v.w - mx);
    float s = v.x + v.y + v.z + v.w;
#pragma unroll
    for (int o = 16; o; o >>= 1) s += __shfl_xor_sync(0xffffffffu, s, o);
    float inv = 1.f / s;
    v.x *= inv; v.y *= inv; v.z *= inv; v.w *= inv;
    row[lane] = v;
}

// ---------------- softmax over rows of 4096 (one block per row) ----------------
__global__ __launch_bounds__(256) void softmax4096(float* __restrict__ p) {
    __shared__ float redm[8];
    __shared__ float reds[8];
    float4* rp = (float4*)(p + (size_t)blockIdx.x * 4096);
    int tid = threadIdx.x, lane = tid & 31, w = tid >> 5;
    float4 v[4];
    float mx = -1e30f;
#pragma unroll
    for (int l = 0; l < 4; l++) {
        v[l] = rp[tid + l * 256];
        mx = fmaxf(mx, fmaxf(fmaxf(v[l].x, v[l].y), fmaxf(v[l].z, v[l].w)));
    }
#pragma unroll
    for (int o = 16; o; o >>= 1) mx = fmaxf(mx, __shfl_xor_sync(0xffffffffu, mx, o));
    if (lane == 0) redm[w] = mx;
    __syncthreads();
    mx = redm[0];
#pragma unroll
    for (int i = 1; i < 8; i++) mx = fmaxf(mx, redm[i]);
    float s = 0.f;
#pragma unroll
    for (int l = 0; l < 4; l++) {
        v[l].x = expf(v[l].x - mx); v[l].y = expf(v[l].y - mx);
        v[l].z = expf(v[l].z - mx); v[l].w = expf(v[l].w - mx);
        s += v[l].x + v[l].y + v[l].z + v[l].w;
    }
#pragma unroll
    for (int o = 16; o; o >>= 1) s += __shfl_xor_sync(0xffffffffu, s, o);
    if (lane == 0) reds[w] = s;
    __syncthreads();
    s = 0.f;
#pragma unroll
    for (int i = 0; i < 8; i++) s += reds[i];
    float inv = 1.f / s;
#pragma unroll
    for (int l = 0; l < 4; l++) {
        v[l].x *= inv; v[l].y *= inv; v[l].z *= inv; v[l].w *= inv;
        rp[tid + l * 256] = v[l];
    }
}

// ---------------- talking heads, in place: dst[g] = sum_h W[g,h]*src[h] ----------------
__global__ __launch_bounds__(256) void th_mix(float* __restrict__ data,
                                              const float* __restrict__ W) {
    __shared__ float Ws[256];
    Ws[threadIdx.x] = W[threadIdx.x];
    __syncthreads();
    size_t t = (size_t)blockIdx.x * 256 + threadIdx.x;   // < B * inner
    const size_t inner = (size_t)NTOK * MM;              // 524288 = 2^19
    size_t b = t >> 19;
    size_t idx = t & (inner - 1);
    float* p = data + b * 16 * inner + idx;
    float in[16];
#pragma unroll
    for (int h = 0; h < 16; h++) in[h] = p[(size_t)h * inner];
#pragma unroll
    for (int g = 0; g < 16; g++) {
        float a = 0.f;
#pragma unroll
        for (int h = 0; h < 16; h++) a += Ws[g * 16 + h] * in[h];
        p[(size_t)g * inner] = a;
    }
}

// ---------------- agent_gathered partials: (128x64) += ak2(128 x nslice) @ V ----------------
__global__ __launch_bounds__(256) void gather_kernel() {
    int bh = blockIdx.y, b = bh >> 4, h = bh & 15;
    int split = blockIdx.x;   // 0..7, each 512 n's
    const float* At = g_ak + (size_t)bh * MM * NTOK;
    const float* Vb = g_qkv + (size_t)b * NTOK * 3072 + 2048 + h * 64;
    __shared__ float As[16][128];
    __shared__ float Vs[16][64];
    int tid = threadIdx.x, ty = tid >> 4, tx = tid & 15;
    float acc[8][4];
#pragma unroll
    for (int i = 0; i < 8; i++)
#pragma unroll
        for (int j = 0; j < 4; j++) acc[i][j] = 0.f;

    for (int n0 = split * 512; n0 < split * 512 + 512; n0 += 16) {
#pragma unroll
        for (int l = 0; l < 2; l++) {
            int idx = tid + l * 256;
            int m = idx >> 2, c = (idx & 3) << 2;
            float4 v = *(const float4*)(At + (size_t)m * NTOK + n0 + c);
            As[c + 0][m] = v.x; As[c + 1][m] = v.y; As[c + 2][m] = v.z; As[c + 3][m] = v.w;
        }
        {
            int rr = tid >> 4, cc = (tid & 15) << 2;
            *(float4*)&Vs[rr][cc] = *(const float4*)(Vb + (size_t)(n0 + rr) * 3072 + cc);
        }
        __syncthreads();
#pragma unroll
        for (int k = 0; k < 16; k++) {
            float4 a0 = *(float4*)&As[k][ty * 8];
            float4 a1 = *(float4*)&As[k][ty * 8 + 4];
            float ar[8] = {a0.x, a0.y, a0.z, a0.w, a1.x, a1.y, a1.z, a1.w};
            float4 bv = *(float4*)&Vs[k][tx * 4];
            float br[4] = {bv.x, bv.y, bv.z, bv.w};
#pragma unroll
            for (int i = 0; i < 8; i++)
#pragma unroll
                for (int j = 0; j < 4; j++) acc[i][j] += ar[i] * br[j];
        }
        __syncthreads();
    }
    float* Ob = g_gpart + (size_t)split * BH * MM * DHH + (size_t)bh * MM * DHH;
#pragma unroll
    for (int i = 0; i < 8; i++)
        *(float4*)(Ob + (size_t)(ty * 8 + i) * 64 + tx * 4) =
            make_float4(acc[i][0], acc[i][1], acc[i][2], acc[i][3]);
}

// ---------------- reduce partials -> g_gather + write to output tail ----------------
__global__ __launch_bounds__(256) void reduce_gather(float* __restrict__ outtail) {
    int t = blockIdx.x * 256 + threadIdx.x;   // < 524288
    float s = 0.f;
#pragma unroll
    for (int i = 0; i < 8; i++) s += g_gpart[(size_t)i * (BH * MM * DHH) + t];
    g_gather[t] = s;
    outtail[t] = s;
}

// ---------------- out stage: (4096x64) = qa2(4096x128) @ gather(128x64), gated ----------------
__global__ __launch_bounds__(256) void outstage_kernel() {
    int bh = blockIdx.y, b = bh >> 4, h = bh & 15;
    int n0 = blockIdx.x * 128;
    const float* At = g_qa + ((size_t)bh * NTOK + n0) * 128;
    const float* Gb = g_gather + (size_t)bh * MM * DHH;
    __shared__ float As[16][128];
    __shared__ float Gs[16][64];
    int tid = threadIdx.x, ty = tid >> 4, tx = tid & 15;
    float acc[8][4];
#pragma unroll
    for (int i = 0; i < 8; i++)
#pragma unroll
        for (int j = 0; j < 4; j++) acc[i][j] = 0.f;

    for (int m0 = 0; m0 < 128; m0 += 16) {
#pragma unroll
        for (int l = 0; l < 2; l++) {
            int idx = tid + l * 256;
            int n = idx >> 2, c = (idx & 3) << 2;
            float4 v = *(const float4*)(At + (size_t)n * 128 + m0 + c);
            As[c + 0][n] = v.x; As[c + 1][n] = v.y; As[c + 2][n] = v.z; As[c + 3][n] = v.w;
        }
        {
            int rr = tid >> 4, cc = (tid & 15) << 2;
            *(float4*)&Gs[rr][cc] = *(const float4*)(Gb + (size_t)(m0 + rr) * 64 + cc);
        }
        __syncthreads();
#pragma unroll
        for (int k = 0; k < 16; k++) {
            float4 a0 = *(float4*)&As[k][ty * 8];
            float4 a1 = *(float4*)&As[k][ty * 8 + 4];
            float ar[8] = {a0.x, a0.y, a0.z, a0.w, a1.x, a1.y, a1.z, a1.w};
            float4 bv = *(float4*)&Gs[k][tx * 4];
            float br[4] = {bv.x, bv.y, bv.z, bv.w};
#pragma unroll
            for (int i = 0; i < 8; i++)
#pragma unroll
                for (int j = 0; j < 4; j++) acc[i][j] += ar[i] * br[j];
        }
        __syncthreads();
    }
#pragma unroll
    for (int i = 0; i < 8; i++) {
        int n = n0 + ty * 8 + i;
        float gt = g_gates[((size_t)b * NTOK + n) * 16 + h];
        *(float4*)(g_out1 + ((size_t)b * NTOK + n) * 1024 + h * 64 + tx * 4) =
            make_float4(acc[i][0] * gt, acc[i][1] * gt, acc[i][2] * gt, acc[i][3] * gt);
    }
}

// ---------------- launch ----------------
extern "C" void kernel_launch(void* const* d_in, const int* in_sizes, int n_in,
                              void* d_out, int out_size) {
    const float* x      = (const float*)d_in[0];
    const float* W_qkv  = (const float*)d_in[1];
    const float* W_gate = (const float*)d_in[2];
    const float* b_gate = (const float*)d_in[3];
    const float* agent  = (const float*)d_in[4];
    const float* W_qa   = (const float*)d_in[5];
    const float* W_ak   = (const float*)d_in[6];
    const float* W_out  = (const float*)d_in[7];
    float* out = (float*)d_out;

    float *qkv, *qa, *ak, *out1;
    cudaGetSymbolAddress((void**)&qkv,  g_qkv);
    cudaGetSymbolAddress((void**)&qa,   g_qa);
    cudaGetSymbolAddress((void**)&ak,   g_ak);
    cudaGetSymbolAddress((void**)&out1, g_out1);

    // 1. QKV projection: (16384x1024) @ (1024x3072)
    sgemm128<<<dim3(3072 / 128, ROWS / 128), 256>>>(x, W_qkv, qkv, 3072, 1024);
    // 2. gates
    gates_kernel<<<ROWS, 256>>>(x, W_gate, b_gate);
    // 3. qa_sim, ak_sim
    qa_sim_kernel<<<dim3(NTOK / 128, BH), 256>>>(agent);
    ak_sim_kernel<<<dim3(NTOK / 128, BH), 256>>>(agent);
    // 4. softmaxes (in place)
    softmax128<<<(BH * NTOK) / 8, 256>>>(qa);
    softmax4096<<<BH * MM, 256>>>(ak);
    // 5. talking heads (in place)
    th_mix<<<(BB * NTOK * MM) / 256, 256>>>(qa, W_qa);
    th_mix<<<(BB * MM * NTOK) / 256, 256>>>(ak, W_ak);
    // 6. agent_gathered = ak2 @ v (8-way deterministic k-split + reduce)
    gather_kernel<<<dim3(8, BH), 256>>>();
    reduce_gather<<<(BH * MM * DHH) / 256, 256>>>(out + (size_t)ROWS * DD);
    // 7. out stage (fused gating) -> g_out1 in (B,N,D) layout
    outstage_kernel<<<dim3(NTOK / 128, BH), 256>>>();
    // 8. final projection -> d_out
    sgemm128<<<dim3(DD / 128, ROWS / 128), 256>>>(out1, W_out, out, DD, 1024);
}

// round 4
// speedup vs baseline: 1.3450x; 1.3450x over previous
#include <cuda_runtime.h>
#include <math.h>
#include <stdint.h>

// Problem constants
#define BB    4
#define NTOK  4096
#define DD    1024
#define HH    16
#define MM    128
#define DHH   64
#define SCALE 0.125f
#define ROWS  (BB*NTOK)        // 16384
#define BH    (BB*HH)          // 64

// ---------------- device scratch (static, allowed) ----------------
__device__ float g_qkv[ROWS * 3072];
__device__ float g_qa [BH * NTOK * MM];
__device__ float g_ak [BH * MM * NTOK];
__device__ float g_gpart[8 * BH * MM * DHH];
__device__ float g_gather[BH * MM * DHH];
__device__ float g_gates[ROWS * HH];
__device__ float g_out1[ROWS * DD];
__device__ float g_wt1[3072 * 1024];   // W_qkv transposed (N-major, K contiguous)
__device__ float g_wt2[1024 * 1024];   // W_out transposed

__device__ __forceinline__ uint32_t smem_u32(const void* p) {
    uint32_t a;
    asm("{ .reg .u64 t; cvta.to.shared.u64 t, %1; cvt.u32.u64 %0, t; }" : "=r"(a) : "l"(p));
    return a;
}
__device__ __forceinline__ void cp16(uint32_t dst, const void* src) {
    asm volatile("cp.async.cg.shared.global [%0], [%1], 16;" :: "r"(dst), "l"(src) : "memory");
}
__device__ __forceinline__ void mma_tf32(float* d, const uint32_t* a, const uint32_t* b) {
    asm volatile(
        "mma.sync.aligned.m16n8k8.row.col.f32.tf32.tf32.f32 "
        "{%0,%1,%2,%3}, {%4,%5,%6,%7}, {%8,%9}, {%0,%1,%2,%3};\n"
        : "+f"(d[0]), "+f"(d[1]), "+f"(d[2]), "+f"(d[3])
        : "r"(a[0]), "r"(a[1]), "r"(a[2]), "r"(a[3]), "r"(b[0]), "r"(b[1]));
}
// split v into tf32 hi + tf32 lo (3xTF32 precision recovery)
__device__ __forceinline__ void tf32_split(float v, uint32_t& hi, uint32_t& lo) {
    asm("cvt.rn.tf32.f32 %0, %1;" : "=r"(hi) : "f"(v));
    float res = v - __uint_as_float(hi);
    asm("cvt.rn.tf32.f32 %0, %1;" : "=r"(lo) : "f"(res));
}

// ================= 3xTF32 mma.sync GEMM =================
// C[M][Nc] = A[M][1024] @ Bt[Nc][1024]^T ; tiles 128x128, kchunk 32, 3-stage cp.async
#define KDIM 1024
#define KCH  32
#define NKCH (KDIM / KCH)          // 32
#define SROW 36                    // padded stride (floats): 144B, 16B-aligned, conflict-free
#define STAGE_FLOATS (256 * SROW)  // A(128 rows) + B(128 rows)
#define MMA_SMEM (3 * STAGE_FLOATS * 4)

__device__ __forceinline__ void ld_stage(const float* __restrict__ A,
                                         const float* __restrict__ Bt,
                                         int m0, int n0, int kc,
                                         uint32_t sbase, int tid) {
    uint32_t sb = sbase + (uint32_t)(kc % 3) * (STAGE_FLOATS * 4);
    const float* ag = A + (size_t)m0 * KDIM + kc * KCH;
#pragma unroll
    for (int i = 0; i < 4; i++) {
        int idx = tid + i * 256;
        int r = idx >> 3, f = idx & 7;
        cp16(sb + (uint32_t)(r * SROW * 4 + f * 16), ag + (size_t)r * KDIM + f * 4);
    }
    const float* bg = Bt + (size_t)n0 * KDIM + kc * KCH;
#pragma unroll
    for (int i = 0; i < 4; i++) {
        int idx = tid + i * 256;
        int r = idx >> 3, f = idx & 7;
        cp16(sb + (uint32_t)((128 + r) * SROW * 4 + f * 16), bg + (size_t)r * KDIM + f * 4);
    }
    asm volatile("cp.async.commit_group;" ::: "memory");
}

__global__ __launch_bounds__(256) void mma_gemm(const float* __restrict__ A,
                                                const float* __restrict__ Bt,
                                                float* __restrict__ C, int Nc) {
    extern __shared__ float sm[];
    const int tid = threadIdx.x, wid = tid >> 5, lane = tid & 31;
    const int m0 = blockIdx.y * 128, n0 = blockIdx.x * 128;
    const int wm = (wid & 3) * 32, wn = (wid >> 2) * 64;
    const int g = lane >> 2, t = lane & 3;
    uint32_t sbase = smem_u32(sm);

    ld_stage(A, Bt, m0, n0, 0, sbase, tid);
    ld_stage(A, Bt, m0, n0, 1, sbase, tid);

    float acc[2][8][4];
#pragma unroll
    for (int i = 0; i < 2; i++)
#pragma unroll
        for (int j = 0; j < 8; j++)
#pragma unroll
            for (int q = 0; q < 4; q++) acc[i][j][q] = 0.f;

    for (int kc = 0; kc < NKCH; kc++) {
        if (kc + 2 < NKCH) {
            ld_stage(A, Bt, m0, n0, kc + 2, sbase, tid);
            asm volatile("cp.async.wait_group 2;" ::: "memory");
        } else if (kc == NKCH - 2) {
            asm volatile("cp.async.wait_group 1;" ::: "memory");
        } else {
            asm volatile("cp.async.wait_group 0;" ::: "memory");
        }
        __syncthreads();
        const float* sA = sm + (kc % 3) * STAGE_FLOATS;
        const float* sB = sA + 128 * SROW;
#pragma unroll
        for (int ks = 0; ks < 4; ks++) {
            const int k = ks * 8;
            uint32_t ah[2][4], al[2][4], bh[8][2], bl[8][2];
#pragma unroll
            for (int i = 0; i < 2; i++) {
                const float* ap = sA + (size_t)(wm + i * 16 + g) * SROW + k + t;
                tf32_split(ap[0],            ah[i][0], al[i][0]);
                tf32_split(ap[8 * SROW],     ah[i][1], al[i][1]);
                tf32_split(ap[4],            ah[i][2], al[i][2]);
                tf32_split(ap[8 * SROW + 4], ah[i][3], al[i][3]);
            }
#pragma unroll
            for (int j = 0; j < 8; j++) {
                const float* bp = sB + (size_t)(wn + j * 8 + g) * SROW + k + t;
                tf32_split(bp[0], bh[j][0], bl[j][0]);
                tf32_split(bp[4], bh[j][1], bl[j][1]);
            }
#pragma unroll
            for (int i = 0; i < 2; i++)
#pragma unroll
                for (int j = 0; j < 8; j++) {
                    mma_tf32(acc[i][j], ah[i], bl[j]);   // hi*lo
                    mma_tf32(acc[i][j], al[i], bh[j]);   // lo*hi
                    mma_tf32(acc[i][j], ah[i], bh[j]);   // hi*hi (last: largest term)
                }
        }
        __syncthreads();
    }

#pragma unroll
    for (int i = 0; i < 2; i++) {
#pragma unroll
        for (int j = 0; j < 8; j++) {
            size_t r0 = (size_t)(m0 + wm + i * 16 + g);
            int c = n0 + wn + j * 8 + 2 * t;
            *(float2*)(C + r0 * Nc + c)       = make_float2(acc[i][j][0], acc[i][j][1]);
            *(float2*)(C + (r0 + 8) * Nc + c) = make_float2(acc[i][j][2], acc[i][j][3]);
        }
    }
}

// ---------------- transpose: src[K][N] -> dst[N][K] ----------------
__global__ __launch_bounds__(256) void transpose32(const float* __restrict__ src,
                                                   float* __restrict__ dst, int K, int N) {
    __shared__ float t[32][33];
    int bx = blockIdx.x * 32, by = blockIdx.y * 32;
    int lx = threadIdx.x & 31, ly = threadIdx.x >> 5;
#pragma unroll
    for (int i = 0; i < 32; i += 8)
        t[ly + i][lx] = src[(size_t)(by + ly + i) * N + bx + lx];
    __syncthreads();
#pragma unroll
    for (int i = 0; i < 32; i += 8)
        dst[(size_t)(bx + ly + i) * K + by + lx] = t[lx][ly + i];
}

// ---------------- gates ----------------
__global__ __launch_bounds__(256) void gates_kernel(const float* __restrict__ x,
                                                    const float* __restrict__ Wg,
                                                    const float* __restrict__ bg) {
    __shared__ float xs[1024];
    int row = blockIdx.x;
    int tid = threadIdx.x;
    ((float4*)xs)[tid] = ((const float4*)(x + (size_t)row * 1024))[tid];
    __syncthreads();
    int w = tid >> 5, lane = tid & 31;
    float s0 = 0.f, s1 = 0.f;
    for (int d = lane; d < 1024; d += 32) {
        float xv = xs[d];
        s0 += xv * Wg[d * 16 + w];
        s1 += xv * Wg[d * 16 + w + 8];
    }
#pragma unroll
    for (int o = 16; o; o >>= 1) {
        s0 += __shfl_xor_sync(0xffffffffu, s0, o);
        s1 += __shfl_xor_sync(0xffffffffu, s1, o);
    }
    if (lane == 0) {
        g_gates[(size_t)row * 16 + w]     = 1.f / (1.f + expf(-(s0 + bg[w])));
        g_gates[(size_t)row * 16 + w + 8] = 1.f / (1.f + expf(-(s1 + bg[w + 8])));
    }
}

// ---------------- qa_sim ----------------
__global__ __launch_bounds__(256) void qa_sim_kernel(const float* __restrict__ agent) {
    int bh = blockIdx.y, b = bh >> 4, h = bh & 15;
    int n0 = blockIdx.x * 128;
    const float* Qb = g_qkv + ((size_t)(b * NTOK + n0)) * 3072 + h * 64;
    const float* Ab = agent + (size_t)h * MM * DHH;
    __shared__ float Qs[8][128];
    __shared__ float As[8][128];
    int tid = threadIdx.x;
    int r = tid >> 1, c = (tid & 1) << 2;
    int ty = tid >> 4, tx = tid & 15;
    float acc[8][8];
#pragma unroll
    for (int i = 0; i < 8; i++)
#pragma unroll
        for (int j = 0; j < 8; j++) acc[i][j] = 0.f;

    for (int k0 = 0; k0 < 64; k0 += 8) {
        float4 qv = *(const float4*)(Qb + (size_t)r * 3072 + k0 + c);
        Qs[c + 0][r] = qv.x; Qs[c + 1][r] = qv.y; Qs[c + 2][r] = qv.z; Qs[c + 3][r] = qv.w;
        float4 av = *(const float4*)(Ab + r * 64 + k0 + c);
        As[c + 0][r] = av.x * SCALE; As[c + 1][r] = av.y * SCALE;
        As[c + 2][r] = av.z * SCALE; As[c + 3][r] = av.w * SCALE;
        __syncthreads();
#pragma unroll
        for (int k = 0; k < 8; k++) {
            float4 a0 = *(float4*)&Qs[k][ty * 8];
            float4 a1 = *(float4*)&Qs[k][ty * 8 + 4];
            float4 b0 = *(float4*)&As[k][tx * 8];
            float4 b1 = *(float4*)&As[k][tx * 8 + 4];
            float ar[8] = {a0.x, a0.y, a0.z, a0.w, a1.x, a1.y, a1.z, a1.w};
            float br[8] = {b0.x, b0.y, b0.z, b0.w, b1.x, b1.y, b1.z, b1.w};
#pragma unroll
            for (int i = 0; i < 8; i++)
#pragma unroll
                for (int j = 0; j < 8; j++) acc[i][j] += ar[i] * br[j];
        }
        __syncthreads();
    }
    float* Ob = g_qa + ((size_t)bh * NTOK + n0) * 128;
#pragma unroll
    for (int i = 0; i < 8; i++) {
        float* cr = Ob + (size_t)(ty * 8 + i) * 128 + tx * 8;
        *(float4*)cr       = make_float4(acc[i][0], acc[i][1], acc[i][2], acc[i][3]);
        *(float4*)(cr + 4) = make_float4(acc[i][4], acc[i][5], acc[i][6], acc[i][7]);
    }
}

// ---------------- ak_sim ----------------
__global__ __launch_bounds__(256) void ak_sim_kernel(const float* __restrict__ agent) {
    int bh = blockIdx.y, b = bh >> 4, h = bh & 15;
    int n0 = blockIdx.x * 128;
    const float* Kb = g_qkv + ((size_t)(b * NTOK + n0)) * 3072 + 1024 + h * 64;
    const float* Ab = agent + (size_t)h * MM * DHH;
    __shared__ float As[8][128];
    __shared__ float Ks[8][128];
    int tid = threadIdx.x;
    int r = tid >> 1, c = (tid & 1) << 2;
    int ty = tid >> 4, tx = tid & 15;
    float acc[8][8];
#pragma unroll
    for (int i = 0; i < 8; i++)
#pragma unroll
        for (int j = 0; j < 8; j++) acc[i][j] = 0.f;

    for (int k0 = 0; k0 < 64; k0 += 8) {
        float4 av = *(const float4*)(Ab + r * 64 + k0 + c);
        As[c + 0][r] = av.x * SCALE; As[c + 1][r] = av.y * SCALE;
        As[c + 2][r] = av.z * SCALE; As[c + 3][r] = av.w * SCALE;
        float4 kv = *(const float4*)(Kb + (size_t)r * 3072 + k0 + c);
        Ks[c + 0][r] = kv.x; Ks[c + 1][r] = kv.y; Ks[c + 2][r] = kv.z; Ks[c + 3][r] = kv.w;
        __syncthreads();
#pragma unroll
        for (int k = 0; k < 8; k++) {
            float4 a0 = *(float4*)&As[k][ty * 8];
            float4 a1 = *(float4*)&As[k][ty * 8 + 4];
            float4 b0 = *(float4*)&Ks[k][tx * 8];
            float4 b1 = *(float4*)&Ks[k][tx * 8 + 4];
            float ar[8] = {a0.x, a0.y, a0.z, a0.w, a1.x, a1.y, a1.z, a1.w};
            float br[8] = {b0.x, b0.y, b0.z, b0.w, b1.x, b1.y, b1.z, b1.w};
#pragma unroll
            for (int i = 0; i < 8; i++)
#pragma unroll
                for (int j = 0; j < 8; j++) acc[i][j] += ar[i] * br[j];
        }
        __syncthreads();
    }
    float* Ob = g_ak + (size_t)bh * MM * NTOK + n0;
#pragma unroll
    for (int i = 0; i < 8; i++) {
        float* cr = Ob + (size_t)(ty * 8 + i) * NTOK + tx * 8;
        *(float4*)cr       = make_float4(acc[i][0], acc[i][1], acc[i][2], acc[i][3]);
        *(float4*)(cr + 4) = make_float4(acc[i][4], acc[i][5], acc[i][6], acc[i][7]);
    }
}

// ---------------- softmax over rows of 128 ----------------
__global__ __launch_bounds__(256) void softmax128(float* __restrict__ p) {
    int warp = blockIdx.x * 8 + (threadIdx.x >> 5);
    int lane = threadIdx.x & 31;
    float4* row = (float4*)(p + (size_t)warp * 128);
    float4 v = row[lane];
    float mx = fmaxf(fmaxf(v.x, v.y), fmaxf(v.z, v.w));
#pragma unroll
    for (int o = 16; o; o >>= 1) mx = fmaxf(mx, __shfl_xor_sync(0xffffffffu, mx, o));
    v.x = expf(v.x - mx); v.y = expf(v.y - mx); v.z = expf(v.z - mx); v.w = expf(v.w - mx);
    float s = v.x + v.y + v.z + v.w;
#pragma unroll
    for (int o = 16; o; o >>= 1) s += __shfl_xor_sync(0xffffffffu, s, o);
    float inv = 1.f / s;
    v.x *= inv; v.y *= inv; v.z *= inv; v.w *= inv;
    row[lane] = v;
}

// ---------------- softmax over rows of 4096 ----------------
__global__ __launch_bounds__(256) void softmax4096(float* __restrict__ p) {
    __shared__ float redm[8];
    __shared__ float reds[8];
    float4* rp = (float4*)(p + (size_t)blockIdx.x * 4096);
    int tid = threadIdx.x, lane = tid & 31, w = tid >> 5;
    float4 v[4];
    float mx = -1e30f;
#pragma unroll
    for (int l = 0; l < 4; l++) {
        v[l] = rp[tid + l * 256];
        mx = fmaxf(mx, fmaxf(fmaxf(v[l].x, v[l].y), fmaxf(v[l].z, v[l].w)));
    }
#pragma unroll
    for (int o = 16; o; o >>= 1) mx = fmaxf(mx, __shfl_xor_sync(0xffffffffu, mx, o));
    if (lane == 0) redm[w] = mx;
    __syncthreads();
    mx = redm[0];
#pragma unroll
    for (int i = 1; i < 8; i++) mx = fmaxf(mx, redm[i]);
    float s = 0.f;
#pragma unroll
    for (int l = 0; l < 4; l++) {
        v[l].x = expf(v[l].x - mx); v[l].y = expf(v[l].y - mx);
        v[l].z = expf(v[l].z - mx); v[l].w = expf(v[l].w - mx);
        s += v[l].x + v[l].y + v[l].z + v[l].w;
    }
#pragma unroll
    for (int o = 16; o; o >>= 1) s += __shfl_xor_sync(0xffffffffu, s, o);
    if (lane == 0) reds[w] = s;
    __syncthreads();
    s = 0.f;
#pragma unroll
    for (int i = 0; i < 8; i++) s += reds[i];
    float inv = 1.f / s;
#pragma unroll
    for (int l = 0; l < 4; l++) {
        v[l].x *= inv; v[l].y *= inv; v[l].z *= inv; v[l].w *= inv;
        rp[tid + l * 256] = v[l];
    }
}

// ---------------- talking heads, in place ----------------
__global__ __launch_bounds__(256) void th_mix(float* __restrict__ data,
                                              const float* __restrict__ W) {
    __shared__ float Ws[256];
    Ws[threadIdx.x] = W[threadIdx.x];
    __syncthreads();
    size_t t = (size_t)blockIdx.x * 256 + threadIdx.x;
    const size_t inner = (size_t)NTOK * MM;
    size_t b = t >> 19;
    size_t idx = t & (inner - 1);
    float* p = data + b * 16 * inner + idx;
    float in[16];
#pragma unroll
    for (int h = 0; h < 16; h++) in[h] = p[(size_t)h * inner];
#pragma unroll
    for (int g = 0; g < 16; g++) {
        float a = 0.f;
#pragma unroll
        for (int h = 0; h < 16; h++) a += Ws[g * 16 + h] * in[h];
        p[(size_t)g * inner] = a;
    }
}

// ---------------- agent_gathered partials ----------------
__global__ __launch_bounds__(256) void gather_kernel() {
    int bh = blockIdx.y, b = bh >> 4, h = bh & 15;
    int split = blockIdx.x;
    const float* At = g_ak + (size_t)bh * MM * NTOK;
    const float* Vb = g_qkv + (size_t)b * NTOK * 3072 + 2048 + h * 64;
    __shared__ float As[16][128];
    __shared__ float Vs[16][64];
    int tid = threadIdx.x, ty = tid >> 4, tx = tid & 15;
    float acc[8][4];
#pragma unroll
    for (int i = 0; i < 8; i++)
#pragma unroll
        for (int j = 0; j < 4; j++) acc[i][j] = 0.f;

    for (int n0 = split * 512; n0 < split * 512 + 512; n0 += 16) {
#pragma unroll
        for (int l = 0; l < 2; l++) {
            int idx = tid + l * 256;
            int m = idx >> 2, c = (idx & 3) << 2;
            float4 v = *(const float4*)(At + (size_t)m * NTOK + n0 + c);
            As[c + 0][m] = v.x; As[c + 1][m] = v.y; As[c + 2][m] = v.z; As[c + 3][m] = v.w;
        }
        {
            int rr = tid >> 4, cc = (tid & 15) << 2;
            *(float4*)&Vs[rr][cc] = *(const float4*)(Vb + (size_t)(n0 + rr) * 3072 + cc);
        }
        __syncthreads();
#pragma unroll
        for (int k = 0; k < 16; k++) {
            float4 a0 = *(float4*)&As[k][ty * 8];
            float4 a1 = *(float4*)&As[k][ty * 8 + 4];
            float ar[8] = {a0.x, a0.y, a0.z, a0.w, a1.x, a1.y, a1.z, a1.w};
            float4 bv = *(float4*)&Vs[k][tx * 4];
            float br[4] = {bv.x, bv.y, bv.z, bv.w};
#pragma unroll
            for (int i = 0; i < 8; i++)
#pragma unroll
                for (int j = 0; j < 4; j++) acc[i][j] += ar[i] * br[j];
        }
        __syncthreads();
    }
    float* Ob = g_gpart + (size_t)split * BH * MM * DHH + (size_t)bh * MM * DHH;
#pragma unroll
    for (int i = 0; i < 8; i++)
        *(float4*)(Ob + (size_t)(ty * 8 + i) * 64 + tx * 4) =
            make_float4(acc[i][0], acc[i][1], acc[i][2], acc[i][3]);
}

// ---------------- reduce partials ----------------
__global__ __launch_bounds__(256) void reduce_gather(float* __restrict__ outtail) {
    int t = blockIdx.x * 256 + threadIdx.x;
    float s = 0.f;
#pragma unroll
    for (int i = 0; i < 8; i++) s += g_gpart[(size_t)i * (BH * MM * DHH) + t];
    g_gather[t] = s;
    outtail[t] = s;
}

// ---------------- out stage ----------------
__global__ __launch_bounds__(256) void outstage_kernel() {
    int bh = blockIdx.y, b = bh >> 4, h = bh & 15;
    int n0 = blockIdx.x * 128;
    const float* At = g_qa + ((size_t)bh * NTOK + n0) * 128;
    const float* Gb = g_gather + (size_t)bh * MM * DHH;
    __shared__ float As[16][128];
    __shared__ float Gs[16][64];
    int tid = threadIdx.x, ty = tid >> 4, tx = tid & 15;
    float acc[8][4];
#pragma unroll
    for (int i = 0; i < 8; i++)
#pragma unroll
        for (int j = 0; j < 4; j++) acc[i][j] = 0.f;

    for (int m0 = 0; m0 < 128; m0 += 16) {
#pragma unroll
        for (int l = 0; l < 2; l++) {
            int idx = tid + l * 256;
            int n = idx >> 2, c = (idx & 3) << 2;
            float4 v = *(const float4*)(At + (size_t)n * 128 + m0 + c);
            As[c + 0][n] = v.x; As[c + 1][n] = v.y; As[c + 2][n] = v.z; As[c + 3][n] = v.w;
        }
        {
            int rr = tid >> 4, cc = (tid & 15) << 2;
            *(float4*)&Gs[rr][cc] = *(const float4*)(Gb + (size_t)(m0 + rr) * 64 + cc);
        }
        __syncthreads();
#pragma unroll
        for (int k = 0; k < 16; k++) {
            float4 a0 = *(float4*)&As[k][ty * 8];
            float4 a1 = *(float4*)&As[k][ty * 8 + 4];
            float ar[8] = {a0.x, a0.y, a0.z, a0.w, a1.x, a1.y, a1.z, a1.w};
            float4 bv = *(float4*)&Gs[k][tx * 4];
            float br[4] = {bv.x, bv.y, bv.z, bv.w};
#pragma unroll
            for (int i = 0; i < 8; i++)
#pragma unroll
                for (int j = 0; j < 4; j++) acc[i][j] += ar[i] * br[j];
        }
        __syncthreads();
    }
#pragma unroll
    for (int i = 0; i < 8; i++) {
        int n = n0 + ty * 8 + i;
        float gt = g_gates[((size_t)b * NTOK + n) * 16 + h];
        *(float4*)(g_out1 + ((size_t)b * NTOK + n) * 1024 + h * 64 + tx * 4) =
            make_float4(acc[i][0] * gt, acc[i][1] * gt, acc[i][2] * gt, acc[i][3] * gt);
    }
}

// ---------------- launch ----------------
extern "C" void kernel_launch(void* const* d_in, const int* in_sizes, int n_in,
                              void* d_out, int out_size) {
    const float* x      = (const float*)d_in[0];
    const float* W_qkv  = (const float*)d_in[1];
    const float* W_gate = (const float*)d_in[2];
    const float* b_gate = (const float*)d_in[3];
    const float* agent  = (const float*)d_in[4];
    const float* W_qa   = (const float*)d_in[5];
    const float* W_ak   = (const float*)d_in[6];
    const float* W_out  = (const float*)d_in[7];
    float* out = (float*)d_out;

    float *qkv, *qa, *ak, *out1, *wt1, *wt2;
    cudaGetSymbolAddress((void**)&qkv,  g_qkv);
    cudaGetSymbolAddress((void**)&qa,   g_qa);
    cudaGetSymbolAddress((void**)&ak,   g_ak);
    cudaGetSymbolAddress((void**)&out1, g_out1);
    cudaGetSymbolAddress((void**)&wt1,  g_wt1);
    cudaGetSymbolAddress((void**)&wt2,  g_wt2);

    cudaFuncSetAttribute(mma_gemm, cudaFuncAttributeMaxDynamicSharedMemorySize, MMA_SMEM);

    // 0. transpose weights to N-major (K contiguous)
    transpose32<<<dim3(3072 / 32, 1024 / 32), 256>>>(W_qkv, wt1, 1024, 3072);
    transpose32<<<dim3(1024 / 32, 1024 / 32), 256>>>(W_out, wt2, 1024, 1024);
    // 1. QKV projection (3xTF32 mma.sync)
    mma_gemm<<<dim3(3072 / 128, ROWS / 128), 256, MMA_SMEM>>>(x, wt1, qkv, 3072);
    // 2. gates
    gates_kernel<<<ROWS, 256>>>(x, W_gate, b_gate);
    // 3. qa_sim, ak_sim
    qa_sim_kernel<<<dim3(NTOK / 128, BH), 256>>>(agent);
    ak_sim_kernel<<<dim3(NTOK / 128, BH), 256>>>(agent);
    // 4. softmaxes
    softmax128<<<(BH * NTOK) / 8, 256>>>(qa);
    softmax4096<<<BH * MM, 256>>>(ak);
    // 5. talking heads
    th_mix<<<(BB * NTOK * MM) / 256, 256>>>(qa, W_qa);
    th_mix<<<(BB * MM * NTOK) / 256, 256>>>(ak, W_ak);
    // 6. agent_gathered
    gather_kernel<<<dim3(8, BH), 256>>>();
    reduce_gather<<<(BH * MM * DHH) / 256, 256>>>(out + (size_t)ROWS * DD);
    // 7. out stage (fused gating)
    outstage_kernel<<<dim3(NTOK / 128, BH), 256>>>();
    // 8. final projection (3xTF32 mma.sync)
    mma_gemm<<<dim3(DD / 128, ROWS / 128), 256, MMA_SMEM>>>(out1, wt2, out, DD);
}

// round 5
// speedup vs baseline: 1.6118x; 1.1983x over previous
#include <cuda_runtime.h>
#include <math.h>
#include <stdint.h>

// Problem constants
#define BB    4
#define NTOK  4096
#define DD    1024
#define HH    16
#define MM    128
#define DHH   64
#define SCALE 0.125f
#define ROWS  (BB*NTOK)        // 16384
#define BH    (BB*HH)          // 64
#define GSPLIT 32

// ---------------- device scratch (static, allowed) ----------------
__device__ float g_qkv[ROWS * 3072];
__device__ float g_qa [BH * NTOK * MM];
__device__ float g_ak [BH * MM * NTOK];
__device__ float g_gpart[GSPLIT * BH * MM * DHH];
__device__ float g_gather[BH * MM * DHH];
__device__ float g_gates[ROWS * HH];
__device__ float g_out1[ROWS * DD];
__device__ float g_wt1[3072 * 1024];   // W_qkv transposed (N-major, K contiguous)
__device__ float g_wt2[1024 * 1024];   // W_out transposed
__device__ float g_wgt[HH * 1024];     // W_gate transposed (H-major)

__device__ __forceinline__ uint32_t smem_u32(const void* p) {
    uint32_t a;
    asm("{ .reg .u64 t; cvta.to.shared.u64 t, %1; cvt.u32.u64 %0, t; }" : "=r"(a) : "l"(p));
    return a;
}
__device__ __forceinline__ void cp16(uint32_t dst, const void* src) {
    asm volatile("cp.async.cg.shared.global [%0], [%1], 16;" :: "r"(dst), "l"(src) : "memory");
}
__device__ __forceinline__ void mma_tf32(float* d, const uint32_t* a, const uint32_t* b) {
    asm volatile(
        "mma.sync.aligned.m16n8k8.row.col.f32.tf32.tf32.f32 "
        "{%0,%1,%2,%3}, {%4,%5,%6,%7}, {%8,%9}, {%0,%1,%2,%3};\n"
        : "+f"(d[0]), "+f"(d[1]), "+f"(d[2]), "+f"(d[3])
        : "r"(a[0]), "r"(a[1]), "r"(a[2]), "r"(a[3]), "r"(b[0]), "r"(b[1]));
}
__device__ __forceinline__ void tf32_split(float v, uint32_t& hi, uint32_t& lo) {
    asm("cvt.rn.tf32.f32 %0, %1;" : "=r"(hi) : "f"(v));
    float res = v - __uint_as_float(hi);
    asm("cvt.rn.tf32.f32 %0, %1;" : "=r"(lo) : "f"(res));
}

// ================= 3xTF32 mma.sync GEMM =================
#define KDIM 1024
#define KCH  32
#define NKCH (KDIM / KCH)
#define SROW 36
#define STAGE_FLOATS (256 * SROW)
#define MMA_SMEM (3 * STAGE_FLOATS * 4)

__device__ __forceinline__ void ld_stage(const float* __restrict__ A,
                                         const float* __restrict__ Bt,
                                         int m0, int n0, int kc,
                                         uint32_t sbase, int tid) {
    uint32_t sb = sbase + (uint32_t)(kc % 3) * (STAGE_FLOATS * 4);
    const float* ag = A + (size_t)m0 * KDIM + kc * KCH;
#pragma unroll
    for (int i = 0; i < 4; i++) {
        int idx = tid + i * 256;
        int r = idx >> 3, f = idx & 7;
        cp16(sb + (uint32_t)(r * SROW * 4 + f * 16), ag + (size_t)r * KDIM + f * 4);
    }
    const float* bg = Bt + (size_t)n0 * KDIM + kc * KCH;
#pragma unroll
    for (int i = 0; i < 4; i++) {
        int idx = tid + i * 256;
        int r = idx >> 3, f = idx & 7;
        cp16(sb + (uint32_t)((128 + r) * SROW * 4 + f * 16), bg + (size_t)r * KDIM + f * 4);
    }
    asm volatile("cp.async.commit_group;" ::: "memory");
}

__global__ __launch_bounds__(256) void mma_gemm(const float* __restrict__ A,
                                                const float* __restrict__ Bt,
                                                float* __restrict__ C, int Nc) {
    extern __shared__ float sm[];
    const int tid = threadIdx.x, wid = tid >> 5, lane = tid & 31;
    const int m0 = blockIdx.y * 128, n0 = blockIdx.x * 128;
    const int wm = (wid & 3) * 32, wn = (wid >> 2) * 64;
    const int g = lane >> 2, t = lane & 3;
    uint32_t sbase = smem_u32(sm);

    ld_stage(A, Bt, m0, n0, 0, sbase, tid);
    ld_stage(A, Bt, m0, n0, 1, sbase, tid);

    float acc[2][8][4];
#pragma unroll
    for (int i = 0; i < 2; i++)
#pragma unroll
        for (int j = 0; j < 8; j++)
#pragma unroll
            for (int q = 0; q < 4; q++) acc[i][j][q] = 0.f;

    for (int kc = 0; kc < NKCH; kc++) {
        if (kc + 2 < NKCH) {
            ld_stage(A, Bt, m0, n0, kc + 2, sbase, tid);
            asm volatile("cp.async.wait_group 2;" ::: "memory");
        } else if (kc == NKCH - 2) {
            asm volatile("cp.async.wait_group 1;" ::: "memory");
        } else {
            asm volatile("cp.async.wait_group 0;" ::: "memory");
        }
        __syncthreads();
        const float* sA = sm + (kc % 3) * STAGE_FLOATS;
        const float* sB = sA + 128 * SROW;
#pragma unroll
        for (int ks = 0; ks < 4; ks++) {
            const int k = ks * 8;
            uint32_t ah[2][4], al[2][4], bh[8][2], bl[8][2];
#pragma unroll
            for (int i = 0; i < 2; i++) {
                const float* ap = sA + (size_t)(wm + i * 16 + g) * SROW + k + t;
                tf32_split(ap[0],            ah[i][0], al[i][0]);
                tf32_split(ap[8 * SROW],     ah[i][1], al[i][1]);
                tf32_split(ap[4],            ah[i][2], al[i][2]);
                tf32_split(ap[8 * SROW + 4], ah[i][3], al[i][3]);
            }
#pragma unroll
            for (int j = 0; j < 8; j++) {
                const float* bp = sB + (size_t)(wn + j * 8 + g) * SROW + k + t;
                tf32_split(bp[0], bh[j][0], bl[j][0]);
                tf32_split(bp[4], bh[j][1], bl[j][1]);
            }
#pragma unroll
            for (int i = 0; i < 2; i++)
#pragma unroll
                for (int j = 0; j < 8; j++) {
                    mma_tf32(acc[i][j], ah[i], bl[j]);
                    mma_tf32(acc[i][j], al[i], bh[j]);
                    mma_tf32(acc[i][j], ah[i], bh[j]);
                }
        }
        __syncthreads();
    }

#pragma unroll
    for (int i = 0; i < 2; i++) {
#pragma unroll
        for (int j = 0; j < 8; j++) {
            size_t r0 = (size_t)(m0 + wm + i * 16 + g);
            int c = n0 + wn + j * 8 + 2 * t;
            *(float2*)(C + r0 * Nc + c)       = make_float2(acc[i][j][0], acc[i][j][1]);
            *(float2*)(C + (r0 + 8) * Nc + c) = make_float2(acc[i][j][2], acc[i][j][3]);
        }
    }
}

// ---------------- transpose: src[K][N] -> dst[N][K] ----------------
__global__ __launch_bounds__(256) void transpose32(const float* __restrict__ src,
                                                   float* __restrict__ dst, int K, int N) {
    __shared__ float t[32][33];
    int bx = blockIdx.x * 32, by = blockIdx.y * 32;
    int lx = threadIdx.x & 31, ly = threadIdx.x >> 5;
#pragma unroll
    for (int i = 0; i < 32; i += 8)
        t[ly + i][lx] = src[(size_t)(by + ly + i) * N + bx + lx];
    __syncthreads();
#pragma unroll
    for (int i = 0; i < 32; i += 8)
        dst[(size_t)(bx + ly + i) * K + by + lx] = t[lx][ly + i];
}

// ---------------- W_gate transpose: (1024,16) -> (16,1024) ----------------
__global__ __launch_bounds__(256) void wgate_t(const float* __restrict__ Wg) {
    int t = blockIdx.x * 256 + threadIdx.x;   // < 16384
    int d = t >> 4, h = t & 15;
    g_wgt[h * 1024 + d] = Wg[t];
}

// ---------------- gates: one warp per row, coalesced Wgt ----------------
__global__ __launch_bounds__(256) void gates_kernel(const float* __restrict__ x,
                                                    const float* __restrict__ bg) {
    int wid = threadIdx.x >> 5, lane = threadIdx.x & 31;
    int row = blockIdx.x * 8 + wid;
    const float* xr = x + (size_t)row * 1024;
    float acc[16];
#pragma unroll
    for (int h = 0; h < 16; h++) acc[h] = 0.f;
#pragma unroll 4
    for (int i = 0; i < 32; i++) {
        int d = i * 32 + lane;
        float xv = xr[d];
#pragma unroll
        for (int h = 0; h < 16; h++) acc[h] += xv * g_wgt[h * 1024 + d];
    }
#pragma unroll
    for (int h = 0; h < 16; h++) {
#pragma unroll
        for (int o = 16; o; o >>= 1) acc[h] += __shfl_xor_sync(0xffffffffu, acc[h], o);
    }
    if (lane < 16)
        g_gates[(size_t)row * 16 + lane] = 1.f / (1.f + expf(-(acc[lane] + bg[lane])));
}

// ---------------- qa_sim + fused row softmax ----------------
__global__ __launch_bounds__(256) void qa_sim_kernel(const float* __restrict__ agent) {
    int bh = blockIdx.y, b = bh >> 4, h = bh & 15;
    int n0 = blockIdx.x * 128;
    const float* Qb = g_qkv + ((size_t)(b * NTOK + n0)) * 3072 + h * 64;
    const float* Ab = agent + (size_t)h * MM * DHH;
    __shared__ float Qs[8][128];
    __shared__ float As[8][128];
    int tid = threadIdx.x;
    int r = tid >> 1, c = (tid & 1) << 2;
    int ty = tid >> 4, tx = tid & 15;
    float acc[8][8];
#pragma unroll
    for (int i = 0; i < 8; i++)
#pragma unroll
        for (int j = 0; j < 8; j++) acc[i][j] = 0.f;

    for (int k0 = 0; k0 < 64; k0 += 8) {
        float4 qv = *(const float4*)(Qb + (size_t)r * 3072 + k0 + c);
        Qs[c + 0][r] = qv.x; Qs[c + 1][r] = qv.y; Qs[c + 2][r] = qv.z; Qs[c + 3][r] = qv.w;
        float4 av = *(const float4*)(Ab + r * 64 + k0 + c);
        As[c + 0][r] = av.x * SCALE; As[c + 1][r] = av.y * SCALE;
        As[c + 2][r] = av.z * SCALE; As[c + 3][r] = av.w * SCALE;
        __syncthreads();
#pragma unroll
        for (int k = 0; k < 8; k++) {
            float4 a0 = *(float4*)&Qs[k][ty * 8];
            float4 a1 = *(float4*)&Qs[k][ty * 8 + 4];
            float4 b0 = *(float4*)&As[k][tx * 8];
            float4 b1 = *(float4*)&As[k][tx * 8 + 4];
            float ar[8] = {a0.x, a0.y, a0.z, a0.w, a1.x, a1.y, a1.z, a1.w};
            float br[8] = {b0.x, b0.y, b0.z, b0.w, b1.x, b1.y, b1.z, b1.w};
#pragma unroll
            for (int i = 0; i < 8; i++)
#pragma unroll
                for (int j = 0; j < 8; j++) acc[i][j] += ar[i] * br[j];
        }
        __syncthreads();
    }
    // fused softmax over the 128-dim: row (ty*8+i) spans 16 tx lanes x 8 j
    float* Ob = g_qa + ((size_t)bh * NTOK + n0) * 128;
#pragma unroll
    for (int i = 0; i < 8; i++) {
        float mx = acc[i][0];
#pragma unroll
        for (int j = 1; j < 8; j++) mx = fmaxf(mx, acc[i][j]);
#pragma unroll
        for (int o = 8; o; o >>= 1) mx = fmaxf(mx, __shfl_xor_sync(0xffffffffu, mx, o, 16));
        float s = 0.f;
#pragma unroll
        for (int j = 0; j < 8; j++) { acc[i][j] = expf(acc[i][j] - mx); s += acc[i][j]; }
#pragma unroll
        for (int o = 8; o; o >>= 1) s += __shfl_xor_sync(0xffffffffu, s, o, 16);
        float inv = 1.f / s;
        float* cr = Ob + (size_t)(ty * 8 + i) * 128 + tx * 8;
        *(float4*)cr       = make_float4(acc[i][0] * inv, acc[i][1] * inv,
                                         acc[i][2] * inv, acc[i][3] * inv);
        *(float4*)(cr + 4) = make_float4(acc[i][4] * inv, acc[i][5] * inv,
                                         acc[i][6] * inv, acc[i][7] * inv);
    }
}

// ---------------- ak_sim ----------------
__global__ __launch_bounds__(256) void ak_sim_kernel(const float* __restrict__ agent) {
    int bh = blockIdx.y, b = bh >> 4, h = bh & 15;
    int n0 = blockIdx.x * 128;
    const float* Kb = g_qkv + ((size_t)(b * NTOK + n0)) * 3072 + 1024 + h * 64;
    const float* Ab = agent + (size_t)h * MM * DHH;
    __shared__ float As[8][128];
    __shared__ float Ks[8][128];
    int tid = threadIdx.x;
    int r = tid >> 1, c = (tid & 1) << 2;
    int ty = tid >> 4, tx = tid & 15;
    float acc[8][8];
#pragma unroll
    for (int i = 0; i < 8; i++)
#pragma unroll
        for (int j = 0; j < 8; j++) acc[i][j] = 0.f;

    for (int k0 = 0; k0 < 64; k0 += 8) {
        float4 av = *(const float4*)(Ab + r * 64 + k0 + c);
        As[c + 0][r] = av.x * SCALE; As[c + 1][r] = av.y * SCALE;
        As[c + 2][r] = av.z * SCALE; As[c + 3][r] = av.w * SCALE;
        float4 kv = *(const float4*)(Kb + (size_t)r * 3072 + k0 + c);
        Ks[c + 0][r] = kv.x; Ks[c + 1][r] = kv.y; Ks[c + 2][r] = kv.z; Ks[c + 3][r] = kv.w;
        __syncthreads();
#pragma unroll
        for (int k = 0; k < 8; k++) {
            float4 a0 = *(float4*)&As[k][ty * 8];
            float4 a1 = *(float4*)&As[k][ty * 8 + 4];
            float4 b0 = *(float4*)&Ks[k][tx * 8];
            float4 b1 = *(float4*)&Ks[k][tx * 8 + 4];
            float ar[8] = {a0.x, a0.y, a0.z, a0.w, a1.x, a1.y, a1.z, a1.w};
            float br[8] = {b0.x, b0.y, b0.z, b0.w, b1.x, b1.y, b1.z, b1.w};
#pragma unroll
            for (int i = 0; i < 8; i++)
#pragma unroll
                for (int j = 0; j < 8; j++) acc[i][j] += ar[i] * br[j];
        }
        __syncthreads();
    }
    float* Ob = g_ak + (size_t)bh * MM * NTOK + n0;
#pragma unroll
    for (int i = 0; i < 8; i++) {
        float* cr = Ob + (size_t)(ty * 8 + i) * NTOK + tx * 8;
        *(float4*)cr       = make_float4(acc[i][0], acc[i][1], acc[i][2], acc[i][3]);
        *(float4*)(cr + 4) = make_float4(acc[i][4], acc[i][5], acc[i][6], acc[i][7]);
    }
}

// ---------------- softmax over rows of 4096 ----------------
__global__ __launch_bounds__(256) void softmax4096(float* __restrict__ p) {
    __shared__ float redm[8];
    __shared__ float reds[8];
    float4* rp = (float4*)(p + (size_t)blockIdx.x * 4096);
    int tid = threadIdx.x, lane = tid & 31, w = tid >> 5;
    float4 v[4];
    float mx = -1e30f;
#pragma unroll
    for (int l = 0; l < 4; l++) {
        v[l] = rp[tid + l * 256];
        mx = fmaxf(mx, fmaxf(fmaxf(v[l].x, v[l].y), fmaxf(v[l].z, v[l].w)));
    }
#pragma unroll
    for (int o = 16; o; o >>= 1) mx = fmaxf(mx, __shfl_xor_sync(0xffffffffu, mx, o));
    if (lane == 0) redm[w] = mx;
    __syncthreads();
    mx = redm[0];
#pragma unroll
    for (int i = 1; i < 8; i++) mx = fmaxf(mx, redm[i]);
    float s = 0.f;
#pragma unroll
    for (int l = 0; l < 4; l++) {
        v[l].x = expf(v[l].x - mx); v[l].y = expf(v[l].y - mx);
        v[l].z = expf(v[l].z - mx); v[l].w = expf(v[l].w - mx);
        s += v[l].x + v[l].y + v[l].z + v[l].w;
    }
#pragma unroll
    for (int o = 16; o; o >>= 1) s += __shfl_xor_sync(0xffffffffu, s, o);
    if (lane == 0) reds[w] = s;
    __syncthreads();
    s = 0.f;
#pragma unroll
    for (int i = 0; i < 8; i++) s += reds[i];
    float inv = 1.f / s;
#pragma unroll
    for (int l = 0; l < 4; l++) {
        v[l].x *= inv; v[l].y *= inv; v[l].z *= inv; v[l].w *= inv;
        rp[tid + l * 256] = v[l];
    }
}

// ---------------- talking heads, in place ----------------
__global__ __launch_bounds__(256) void th_mix(float* __restrict__ data,
                                              const float* __restrict__ W) {
    __shared__ float Ws[256];
    Ws[threadIdx.x] = W[threadIdx.x];
    __syncthreads();
    size_t t = (size_t)blockIdx.x * 256 + threadIdx.x;
    const size_t inner = (size_t)NTOK * MM;
    size_t b = t >> 19;
    size_t idx = t & (inner - 1);
    float* p = data + b * 16 * inner + idx;
    float in[16];
#pragma unroll
    for (int h = 0; h < 16; h++) in[h] = p[(size_t)h * inner];
#pragma unroll
    for (int g = 0; g < 16; g++) {
        float a = 0.f;
#pragma unroll
        for (int h = 0; h < 16; h++) a += Ws[g * 16 + h] * in[h];
        p[(size_t)g * inner] = a;
    }
}

// ---------------- agent_gathered partials (32-way k-split) ----------------
__global__ __launch_bounds__(256) void gather_kernel() {
    int bh = blockIdx.y, b = bh >> 4, h = bh & 15;
    int split = blockIdx.x;   // 0..31, each 128 n's
    const float* At = g_ak + (size_t)bh * MM * NTOK;
    const float* Vb = g_qkv + (size_t)b * NTOK * 3072 + 2048 + h * 64;
    __shared__ float As[16][128];
    __shared__ float Vs[16][64];
    int tid = threadIdx.x, ty = tid >> 4, tx = tid & 15;
    float acc[8][4];
#pragma unroll
    for (int i = 0; i < 8; i++)
#pragma unroll
        for (int j = 0; j < 4; j++) acc[i][j] = 0.f;

    for (int n0 = split * 128; n0 < split * 128 + 128; n0 += 16) {
#pragma unroll
        for (int l = 0; l < 2; l++) {
            int idx = tid + l * 256;
            int m = idx >> 2, c = (idx & 3) << 2;
            float4 v = *(const float4*)(At + (size_t)m * NTOK + n0 + c);
            As[c + 0][m] = v.x; As[c + 1][m] = v.y; As[c + 2][m] = v.z; As[c + 3][m] = v.w;
        }
        {
            int rr = tid >> 4, cc = (tid & 15) << 2;
            *(float4*)&Vs[rr][cc] = *(const float4*)(Vb + (size_t)(n0 + rr) * 3072 + cc);
        }
        __syncthreads();
#pragma unroll
        for (int k = 0; k < 16; k++) {
            float4 a0 = *(float4*)&As[k][ty * 8];
            float4 a1 = *(float4*)&As[k][ty * 8 + 4];
            float ar[8] = {a0.x, a0.y, a0.z, a0.w, a1.x, a1.y, a1.z, a1.w};
            float4 bv = *(float4*)&Vs[k][tx * 4];
            float br[4] = {bv.x, bv.y, bv.z, bv.w};
#pragma unroll
            for (int i = 0; i < 8; i++)
#pragma unroll
                for (int j = 0; j < 4; j++) acc[i][j] += ar[i] * br[j];
        }
        __syncthreads();
    }
    float* Ob = g_gpart + (size_t)split * BH * MM * DHH + (size_t)bh * MM * DHH;
#pragma unroll
    for (int i = 0; i < 8; i++)
        *(float4*)(Ob + (size_t)(ty * 8 + i) * 64 + tx * 4) =
            make_float4(acc[i][0], acc[i][1], acc[i][2], acc[i][3]);
}

// ---------------- reduce partials ----------------
__global__ __launch_bounds__(256) void reduce_gather(float* __restrict__ outtail) {
    int t = blockIdx.x * 256 + threadIdx.x;
    float s = 0.f;
#pragma unroll
    for (int i = 0; i < GSPLIT; i++) s += g_gpart[(size_t)i * (BH * MM * DHH) + t];
    g_gather[t] = s;
    outtail[t] = s;
}

// ---------------- out stage ----------------
__global__ __launch_bounds__(256) void outstage_kernel() {
    int bh = blockIdx.y, b = bh >> 4, h = bh & 15;
    int n0 = blockIdx.x * 128;
    const float* At = g_qa + ((size_t)bh * NTOK + n0) * 128;
    const float* Gb = g_gather + (size_t)bh * MM * DHH;
    __shared__ float As[16][128];
    __shared__ float Gs[16][64];
    int tid = threadIdx.x, ty = tid >> 4, tx = tid & 15;
    float acc[8][4];
#pragma unroll
    for (int i = 0; i < 8; i++)
#pragma unroll
        for (int j = 0; j < 4; j++) acc[i][j] = 0.f;

    for (int m0 = 0; m0 < 128; m0 += 16) {
#pragma unroll
        for (int l = 0; l < 2; l++) {
            int idx = tid + l * 256;
            int n = idx >> 2, c = (idx & 3) << 2;
            float4 v = *(const float4*)(At + (size_t)n * 128 + m0 + c);
            As[c + 0][n] = v.x; As[c + 1][n] = v.y; As[c + 2][n] = v.z; As[c + 3][n] = v.w;
        }
        {
            int rr = tid >> 4, cc = (tid & 15) << 2;
            *(float4*)&Gs[rr][cc] = *(const float4*)(Gb + (size_t)(m0 + rr) * 64 + cc);
        }
        __syncthreads();
#pragma unroll
        for (int k = 0; k < 16; k++) {
            float4 a0 = *(float4*)&As[k][ty * 8];
            float4 a1 = *(float4*)&As[k][ty * 8 + 4];
            float ar[8] = {a0.x, a0.y, a0.z, a0.w, a1.x, a1.y, a1.z, a1.w};
            float4 bv = *(float4*)&Gs[k][tx * 4];
            float br[4] = {bv.x, bv.y, bv.z, bv.w};
#pragma unroll
            for (int i = 0; i < 8; i++)
#pragma unroll
                for (int j = 0; j < 4; j++) acc[i][j] += ar[i] * br[j];
        }
        __syncthreads();
    }
#pragma unroll
    for (int i = 0; i < 8; i++) {
        int n = n0 + ty * 8 + i;
        float gt = g_gates[((size_t)b * NTOK + n) * 16 + h];
        *(float4*)(g_out1 + ((size_t)b * NTOK + n) * 1024 + h * 64 + tx * 4) =
            make_float4(acc[i][0] * gt, acc[i][1] * gt, acc[i][2] * gt, acc[i][3] * gt);
    }
}

// ---------------- launch ----------------
extern "C" void kernel_launch(void* const* d_in, const int* in_sizes, int n_in,
                              void* d_out, int out_size) {
    const float* x      = (const float*)d_in[0];
    const float* W_qkv  = (const float*)d_in[1];
    const float* W_gate = (const float*)d_in[2];
    const float* b_gate = (const float*)d_in[3];
    const float* agent  = (const float*)d_in[4];
    const float* W_qa   = (const float*)d_in[5];
    const float* W_ak   = (const float*)d_in[6];
    const float* W_out  = (const float*)d_in[7];
    float* out = (float*)d_out;

    float *qkv, *qa, *ak, *out1, *wt1, *wt2;
    cudaGetSymbolAddress((void**)&qkv,  g_qkv);
    cudaGetSymbolAddress((void**)&qa,   g_qa);
    cudaGetSymbolAddress((void**)&ak,   g_ak);
    cudaGetSymbolAddress((void**)&out1, g_out1);
    cudaGetSymbolAddress((void**)&wt1,  g_wt1);
    cudaGetSymbolAddress((void**)&wt2,  g_wt2);

    cudaFuncSetAttribute(mma_gemm, cudaFuncAttributeMaxDynamicSharedMemorySize, MMA_SMEM);

    // 0. weight transposes
    transpose32<<<dim3(3072 / 32, 1024 / 32), 256>>>(W_qkv, wt1, 1024, 3072);
    transpose32<<<dim3(1024 / 32, 1024 / 32), 256>>>(W_out, wt2, 1024, 1024);
    wgate_t<<<64, 256>>>(W_gate);
    // 1. QKV projection (3xTF32 mma.sync)
    mma_gemm<<<dim3(3072 / 128, ROWS / 128), 256, MMA_SMEM>>>(x, wt1, qkv, 3072);
    // 2. gates (coalesced)
    gates_kernel<<<ROWS / 8, 256>>>(x, b_gate);
    // 3. qa_sim (+fused softmax), ak_sim
    qa_sim_kernel<<<dim3(NTOK / 128, BH), 256>>>(agent);
    ak_sim_kernel<<<dim3(NTOK / 128, BH), 256>>>(agent);
    // 4. ak softmax
    softmax4096<<<BH * MM, 256>>>(ak);
    // 5. talking heads
    th_mix<<<(BB * NTOK * MM) / 256, 256>>>(qa, W_qa);
    th_mix<<<(BB * MM * NTOK) / 256, 256>>>(ak, W_ak);
    // 6. agent_gathered (32-way split)
    gather_kernel<<<dim3(GSPLIT, BH), 256>>>();
    reduce_gather<<<(BH * MM * DHH) / 256, 256>>>(out + (size_t)ROWS * DD);
    // 7. out stage (fused gating)
    outstage_kernel<<<dim3(NTOK / 128, BH), 256>>>();
    // 8. final projection (3xTF32 mma.sync)
    mma_gemm<<<dim3(DD / 128, ROWS / 128), 256, MMA_SMEM>>>(out1, wt2, out, DD);
}

// round 6
// speedup vs baseline: 2.1943x; 1.3614x over previous
#include <cuda_runtime.h>
#include <cuda_fp16.h>
#include <math.h>
#include <stdint.h>

// Problem constants
#define BB    4
#define NTOK  4096
#define DD    1024
#define HH    16
#define MM    128
#define DHH   64
#define SCALE 0.125f
#define ROWS  (BB*NTOK)        // 16384
#define BH    (BB*HH)          // 64
#define GSPLIT 32

// ---------------- device scratch (static, allowed) ----------------
__device__ float g_qkv[ROWS * 3072];
__device__ float g_qa [BH * NTOK * MM];
__device__ float g_ak [BH * MM * NTOK];
__device__ float g_gpart[GSPLIT * BH * MM * DHH];
__device__ float g_gather[BH * MM * DHH];
__device__ float g_gates[ROWS * HH];
__device__ float g_wgt[HH * 1024];        // W_gate transposed (H-major)
// fp16 split operand arrays
__device__ __half g_xh[ROWS * 1024];      // x hi/lo
__device__ __half g_xl[ROWS * 1024];
__device__ __half g_w1h[3072 * 1024];     // W_qkv^T hi/lo (N-major, K contiguous)
__device__ __half g_w1l[3072 * 1024];
__device__ __half g_w2h[1024 * 1024];     // W_out^T hi/lo
__device__ __half g_w2l[1024 * 1024];
__device__ __half g_o1h[ROWS * 1024];     // gated attention output hi/lo
__device__ __half g_o1l[ROWS * 1024];

__device__ __forceinline__ uint32_t smem_u32(const void* p) {
    uint32_t a;
    asm("{ .reg .u64 t; cvta.to.shared.u64 t, %1; cvt.u32.u64 %0, t; }" : "=r"(a) : "l"(p));
    return a;
}
__device__ __forceinline__ void cp16(uint32_t dst, const void* src) {
    asm volatile("cp.async.cg.shared.global [%0], [%1], 16;" :: "r"(dst), "l"(src) : "memory");
}
__device__ __forceinline__ void mma_f16(float* d, const uint32_t* a, const uint32_t* b) {
    asm volatile(
        "mma.sync.aligned.m16n8k16.row.col.f32.f16.f16.f32 "
        "{%0,%1,%2,%3}, {%4,%5,%6,%7}, {%8,%9}, {%0,%1,%2,%3};\n"
        : "+f"(d[0]), "+f"(d[1]), "+f"(d[2]), "+f"(d[3])
        : "r"(a[0]), "r"(a[1]), "r"(a[2]), "r"(a[3]), "r"(b[0]), "r"(b[1]));
}

// ================= fp16 2-way split GEMM =================
// C[M][Nc] = A[M][1024] @ Bt[Nc][1024]^T  (A,Bt given as hi/lo half arrays)
// tiles 128x128, k-chunk 64 halves, 3-stage cp.async
#define KDIM 1024
#define NK16 16                   // 1024 / 64
#define STAGE_BYTES16 73728       // 512 rows * 144 B
#define MMA16_SMEM (3 * STAGE_BYTES16)

__device__ __forceinline__ void ld_stage16(const __half* __restrict__ Ah,
                                           const __half* __restrict__ Al,
                                           const __half* __restrict__ Bh,
                                           const __half* __restrict__ Bl,
                                           int m0, int n0, int kc,
                                           uint32_t sbase, int tid) {
    uint32_t sb = sbase + (uint32_t)(kc % 3) * STAGE_BYTES16;
#pragma unroll
    for (int i = 0; i < 4; i++) {
        int id = tid + i * 256; int r = id >> 3, f = id & 7;
        cp16(sb + (uint32_t)(r * 144 + f * 16), Ah + (size_t)(m0 + r) * KDIM + kc * 64 + f * 8);
    }
#pragma unroll
    for (int i = 0; i < 4; i++) {
        int id = tid + i * 256; int r = id >> 3, f = id & 7;
        cp16(sb + (uint32_t)((128 + r) * 144 + f * 16), Al + (size_t)(m0 + r) * KDIM + kc * 64 + f * 8);
    }
#pragma unroll
    for (int i = 0; i < 4; i++) {
        int id = tid + i * 256; int r = id >> 3, f = id & 7;
        cp16(sb + (uint32_t)((256 + r) * 144 + f * 16), Bh + (size_t)(n0 + r) * KDIM + kc * 64 + f * 8);
    }
#pragma unroll
    for (int i = 0; i < 4; i++) {
        int id = tid + i * 256; int r = id >> 3, f = id & 7;
        cp16(sb + (uint32_t)((384 + r) * 144 + f * 16), Bl + (size_t)(n0 + r) * KDIM + kc * 64 + f * 8);
    }
    asm volatile("cp.async.commit_group;" ::: "memory");
}

__global__ __launch_bounds__(256) void mma_gemm16(const __half* __restrict__ Ah,
                                                  const __half* __restrict__ Al,
                                                  const __half* __restrict__ Bth,
                                                  const __half* __restrict__ Btl,
                                                  float* __restrict__ C, int Nc) {
    extern __shared__ char smv[];
    const int tid = threadIdx.x, wid = tid >> 5, lane = tid & 31;
    const int m0 = blockIdx.y * 128, n0 = blockIdx.x * 128;
    const int wm = (wid & 3) * 32, wn = (wid >> 2) * 64;
    const int g = lane >> 2, t = lane & 3;
    uint32_t sbase = smem_u32(smv);

    ld_stage16(Ah, Al, Bth, Btl, m0, n0, 0, sbase, tid);
    ld_stage16(Ah, Al, Bth, Btl, m0, n0, 1, sbase, tid);

    float acc[2][8][4];
#pragma unroll
    for (int i = 0; i < 2; i++)
#pragma unroll
        for (int j = 0; j < 8; j++)
#pragma unroll
            for (int q = 0; q < 4; q++) acc[i][j][q] = 0.f;

    for (int kc = 0; kc < NK16; kc++) {
        if (kc + 2 < NK16) {
            ld_stage16(Ah, Al, Bth, Btl, m0, n0, kc + 2, sbase, tid);
            asm volatile("cp.async.wait_group 2;" ::: "memory");
        } else if (kc == NK16 - 2) {
            asm volatile("cp.async.wait_group 1;" ::: "memory");
        } else {
            asm volatile("cp.async.wait_group 0;" ::: "memory");
        }
        __syncthreads();
        const uint32_t* S = (const uint32_t*)(smv + (kc % 3) * STAGE_BYTES16);
#pragma unroll
        for (int ks = 0; ks < 4; ks++) {
            const int ko = ks * 8 + t;
            uint32_t ah[2][4], al[2][4];
#pragma unroll
            for (int i = 0; i < 2; i++) {
                const uint32_t* p = S + (wm + i * 16 + g) * 36 + ko;
                ah[i][0] = p[0]; ah[i][1] = p[288]; ah[i][2] = p[4]; ah[i][3] = p[292];
                const uint32_t* q = p + 128 * 36;
                al[i][0] = q[0]; al[i][1] = q[288]; al[i][2] = q[4]; al[i][3] = q[292];
            }
#pragma unroll
            for (int j = 0; j < 8; j++) {
                const uint32_t* pb = S + (256 + wn + j * 8 + g) * 36 + ko;
                uint32_t bhv[2] = {pb[0], pb[4]};
                uint32_t blv[2] = {pb[128 * 36], pb[128 * 36 + 4]};
#pragma unroll
                for (int i = 0; i < 2; i++) {
                    mma_f16(acc[i][j], ah[i], blv);   // hi*lo
                    mma_f16(acc[i][j], al[i], bhv);   // lo*hi
                    mma_f16(acc[i][j], ah[i], bhv);   // hi*hi
                }
            }
        }
        __syncthreads();
    }

#pragma unroll
    for (int i = 0; i < 2; i++) {
#pragma unroll
        for (int j = 0; j < 8; j++) {
            size_t r0 = (size_t)(m0 + wm + i * 16 + g);
            int c = n0 + wn + j * 8 + 2 * t;
            *(float2*)(C + r0 * Nc + c)       = make_float2(acc[i][j][0], acc[i][j][1]);
            *(float2*)(C + (r0 + 8) * Nc + c) = make_float2(acc[i][j][2], acc[i][j][3]);
        }
    }
}

// ---------------- elementwise fp16 split ----------------
__global__ __launch_bounds__(256) void split_fp16(const float* __restrict__ src,
                                                  __half* __restrict__ hi,
                                                  __half* __restrict__ lo) {
    size_t i = (size_t)blockIdx.x * 256 + threadIdx.x;   // per float4
    float4 v = ((const float4*)src)[i];
    __half hx = __float2half_rn(v.x), hy = __float2half_rn(v.y);
    __half hz = __float2half_rn(v.z), hw = __float2half_rn(v.w);
    ((__half2*)hi)[2 * i]     = __halves2half2(hx, hy);
    ((__half2*)hi)[2 * i + 1] = __halves2half2(hz, hw);
    ((__half2*)lo)[2 * i]     = __halves2half2(__float2half_rn(v.x - __half2float(hx)),
                                               __float2half_rn(v.y - __half2float(hy)));
    ((__half2*)lo)[2 * i + 1] = __halves2half2(__float2half_rn(v.z - __half2float(hz)),
                                               __float2half_rn(v.w - __half2float(hw)));
}

// ---------------- transpose + fp16 split: src[K][N] -> dst[N][K] ----------------
__global__ __launch_bounds__(256) void transpose_split(const float* __restrict__ src,
                                                       __half* __restrict__ dh,
                                                       __half* __restrict__ dl,
                                                       int K, int N) {
    __shared__ float t[32][33];
    int bx = blockIdx.x * 32, by = blockIdx.y * 32;
    int lx = threadIdx.x & 31, ly = threadIdx.x >> 5;
#pragma unroll
    for (int i = 0; i < 32; i += 8)
        t[ly + i][lx] = src[(size_t)(by + ly + i) * N + bx + lx];
    __syncthreads();
#pragma unroll
    for (int i = 0; i < 32; i += 8) {
        float v = t[lx][ly + i];
        __half h = __float2half_rn(v);
        size_t o = (size_t)(bx + ly + i) * K + by + lx;
        dh[o] = h;
        dl[o] = __float2half_rn(v - __half2float(h));
    }
}

// ---------------- W_gate transpose ----------------
__global__ __launch_bounds__(256) void wgate_t(const float* __restrict__ Wg) {
    int t = blockIdx.x * 256 + threadIdx.x;
    int d = t >> 4, h = t & 15;
    g_wgt[h * 1024 + d] = Wg[t];
}

// ---------------- gates: one warp per row, coalesced ----------------
__global__ __launch_bounds__(256) void gates_kernel(const float* __restrict__ x,
                                                    const float* __restrict__ bg) {
    int wid = threadIdx.x >> 5, lane = threadIdx.x & 31;
    int row = blockIdx.x * 8 + wid;
    const float* xr = x + (size_t)row * 1024;
    float acc[16];
#pragma unroll
    for (int h = 0; h < 16; h++) acc[h] = 0.f;
#pragma unroll 4
    for (int i = 0; i < 32; i++) {
        int d = i * 32 + lane;
        float xv = xr[d];
#pragma unroll
        for (int h = 0; h < 16; h++) acc[h] += xv * g_wgt[h * 1024 + d];
    }
#pragma unroll
    for (int h = 0; h < 16; h++) {
#pragma unroll
        for (int o = 16; o; o >>= 1) acc[h] += __shfl_xor_sync(0xffffffffu, acc[h], o);
    }
    if (lane < 16)
        g_gates[(size_t)row * 16 + lane] = 1.f / (1.f + expf(-(acc[lane] + bg[lane])));
}

// ---------------- qa_sim + fused row softmax ----------------
__global__ __launch_bounds__(256) void qa_sim_kernel(const float* __restrict__ agent) {
    int bh = blockIdx.y, b = bh >> 4, h = bh & 15;
    int n0 = blockIdx.x * 128;
    const float* Qb = g_qkv + ((size_t)(b * NTOK + n0)) * 3072 + h * 64;
    const float* Ab = agent + (size_t)h * MM * DHH;
    __shared__ float Qs[8][128];
    __shared__ float As[8][128];
    int tid = threadIdx.x;
    int r = tid >> 1, c = (tid & 1) << 2;
    int ty = tid >> 4, tx = tid & 15;
    float acc[8][8];
#pragma unroll
    for (int i = 0; i < 8; i++)
#pragma unroll
        for (int j = 0; j < 8; j++) acc[i][j] = 0.f;

    for (int k0 = 0; k0 < 64; k0 += 8) {
        float4 qv = *(const float4*)(Qb + (size_t)r * 3072 + k0 + c);
        Qs[c + 0][r] = qv.x; Qs[c + 1][r] = qv.y; Qs[c + 2][r] = qv.z; Qs[c + 3][r] = qv.w;
        float4 av = *(const float4*)(Ab + r * 64 + k0 + c);
        As[c + 0][r] = av.x * SCALE; As[c + 1][r] = av.y * SCALE;
        As[c + 2][r] = av.z * SCALE; As[c + 3][r] = av.w * SCALE;
        __syncthreads();
#pragma unroll
        for (int k = 0; k < 8; k++) {
            float4 a0 = *(float4*)&Qs[k][ty * 8];
            float4 a1 = *(float4*)&Qs[k][ty * 8 + 4];
            float4 b0 = *(float4*)&As[k][tx * 8];
            float4 b1 = *(float4*)&As[k][tx * 8 + 4];
            float ar[8] = {a0.x, a0.y, a0.z, a0.w, a1.x, a1.y, a1.z, a1.w};
            float br[8] = {b0.x, b0.y, b0.z, b0.w, b1.x, b1.y, b1.z, b1.w};
#pragma unroll
            for (int i = 0; i < 8; i++)
#pragma unroll
                for (int j = 0; j < 8; j++) acc[i][j] += ar[i] * br[j];
        }
        __syncthreads();
    }
    float* Ob = g_qa + ((size_t)bh * NTOK + n0) * 128;
#pragma unroll
    for (int i = 0; i < 8; i++) {
        float mx = acc[i][0];
#pragma unroll
        for (int j = 1; j < 8; j++) mx = fmaxf(mx, acc[i][j]);
#pragma unroll
        for (int o = 8; o; o >>= 1) mx = fmaxf(mx, __shfl_xor_sync(0xffffffffu, mx, o, 16));
        float s = 0.f;
#pragma unroll
        for (int j = 0; j < 8; j++) { acc[i][j] = expf(acc[i][j] - mx); s += acc[i][j]; }
#pragma unroll
        for (int o = 8; o; o >>= 1) s += __shfl_xor_sync(0xffffffffu, s, o, 16);
        float inv = 1.f / s;
        float* cr = Ob + (size_t)(ty * 8 + i) * 128 + tx * 8;
        *(float4*)cr       = make_float4(acc[i][0] * inv, acc[i][1] * inv,
                                         acc[i][2] * inv, acc[i][3] * inv);
        *(float4*)(cr + 4) = make_float4(acc[i][4] * inv, acc[i][5] * inv,
                                         acc[i][6] * inv, acc[i][7] * inv);
    }
}

// ---------------- ak_sim ----------------
__global__ __launch_bounds__(256) void ak_sim_kernel(const float* __restrict__ agent) {
    int bh = blockIdx.y, b = bh >> 4, h = bh & 15;
    int n0 = blockIdx.x * 128;
    const float* Kb = g_qkv + ((size_t)(b * NTOK + n0)) * 3072 + 1024 + h * 64;
    const float* Ab = agent + (size_t)h * MM * DHH;
    __shared__ float As[8][128];
    __shared__ float Ks[8][128];
    int tid = threadIdx.x;
    int r = tid >> 1, c = (tid & 1) << 2;
    int ty = tid >> 4, tx = tid & 15;
    float acc[8][8];
#pragma unroll
    for (int i = 0; i < 8; i++)
#pragma unroll
        for (int j = 0; j < 8; j++) acc[i][j] = 0.f;

    for (int k0 = 0; k0 < 64; k0 += 8) {
        float4 av = *(const float4*)(Ab + r * 64 + k0 + c);
        As[c + 0][r] = av.x * SCALE; As[c + 1][r] = av.y * SCALE;
        As[c + 2][r] = av.z * SCALE; As[c + 3][r] = av.w * SCALE;
        float4 kv = *(const float4*)(Kb + (size_t)r * 3072 + k0 + c);
        Ks[c + 0][r] = kv.x; Ks[c + 1][r] = kv.y; Ks[c + 2][r] = kv.z; Ks[c + 3][r] = kv.w;
        __syncthreads();
#pragma unroll
        for (int k = 0; k < 8; k++) {
            float4 a0 = *(float4*)&As[k][ty * 8];
            float4 a1 = *(float4*)&As[k][ty * 8 + 4];
            float4 b0 = *(float4*)&Ks[k][tx * 8];
            float4 b1 = *(float4*)&Ks[k][tx * 8 + 4];
            float ar[8] = {a0.x, a0.y, a0.z, a0.w, a1.x, a1.y, a1.z, a1.w};
            float br[8] = {b0.x, b0.y, b0.z, b0.w, b1.x, b1.y, b1.z, b1.w};
#pragma unroll
            for (int i = 0; i < 8; i++)
#pragma unroll
                for (int j = 0; j < 8; j++) acc[i][j] += ar[i] * br[j];
        }
        __syncthreads();
    }
    float* Ob = g_ak + (size_t)bh * MM * NTOK + n0;
#pragma unroll
    for (int i = 0; i < 8; i++) {
        float* cr = Ob + (size_t)(ty * 8 + i) * NTOK + tx * 8;
        *(float4*)cr       = make_float4(acc[i][0], acc[i][1], acc[i][2], acc[i][3]);
        *(float4*)(cr + 4) = make_float4(acc[i][4], acc[i][5], acc[i][6], acc[i][7]);
    }
}

// ---------------- softmax over rows of 4096 ----------------
__global__ __launch_bounds__(256) void softmax4096(float* __restrict__ p) {
    __shared__ float redm[8];
    __shared__ float reds[8];
    float4* rp = (float4*)(p + (size_t)blockIdx.x * 4096);
    int tid = threadIdx.x, lane = tid & 31, w = tid >> 5;
    float4 v[4];
    float mx = -1e30f;
#pragma unroll
    for (int l = 0; l < 4; l++) {
        v[l] = rp[tid + l * 256];
        mx = fmaxf(mx, fmaxf(fmaxf(v[l].x, v[l].y), fmaxf(v[l].z, v[l].w)));
    }
#pragma unroll
    for (int o = 16; o; o >>= 1) mx = fmaxf(mx, __shfl_xor_sync(0xffffffffu, mx, o));
    if (lane == 0) redm[w] = mx;
    __syncthreads();
    mx = redm[0];
#pragma unroll
    for (int i = 1; i < 8; i++) mx = fmaxf(mx, redm[i]);
    float s = 0.f;
#pragma unroll
    for (int l = 0; l < 4; l++) {
        v[l].x = expf(v[l].x - mx); v[l].y = expf(v[l].y - mx);
        v[l].z = expf(v[l].z - mx); v[l].w = expf(v[l].w - mx);
        s += v[l].x + v[l].y + v[l].z + v[l].w;
    }
#pragma unroll
    for (int o = 16; o; o >>= 1) s += __shfl_xor_sync(0xffffffffu, s, o);
    if (lane == 0) reds[w] = s;
    __syncthreads();
    s = 0.f;
#pragma unroll
    for (int i = 0; i < 8; i++) s += reds[i];
    float inv = 1.f / s;
#pragma unroll
    for (int l = 0; l < 4; l++) {
        v[l].x *= inv; v[l].y *= inv; v[l].z *= inv; v[l].w *= inv;
        rp[tid + l * 256] = v[l];
    }
}

// ---------------- talking heads, in place ----------------
__global__ __launch_bounds__(256) void th_mix(float* __restrict__ data,
                                              const float* __restrict__ W) {
    __shared__ float Ws[256];
    Ws[threadIdx.x] = W[threadIdx.x];
    __syncthreads();
    size_t t = (size_t)blockIdx.x * 256 + threadIdx.x;
    const size_t inner = (size_t)NTOK * MM;
    size_t b = t >> 19;
    size_t idx = t & (inner - 1);
    float* p = data + b * 16 * inner + idx;
    float in[16];
#pragma unroll
    for (int h = 0; h < 16; h++) in[h] = p[(size_t)h * inner];
#pragma unroll
    for (int g = 0; g < 16; g++) {
        float a = 0.f;
#pragma unroll
        for (int h = 0; h < 16; h++) a += Ws[g * 16 + h] * in[h];
        p[(size_t)g * inner] = a;
    }
}

// ---------------- agent_gathered partials (32-way k-split) ----------------
__global__ __launch_bounds__(256) void gather_kernel() {
    int bh = blockIdx.y, b = bh >> 4, h = bh & 15;
    int split = blockIdx.x;
    const float* At = g_ak + (size_t)bh * MM * NTOK;
    const float* Vb = g_qkv + (size_t)b * NTOK * 3072 + 2048 + h * 64;
    __shared__ float As[16][128];
    __shared__ float Vs[16][64];
    int tid = threadIdx.x, ty = tid >> 4, tx = tid & 15;
    float acc[8][4];
#pragma unroll
    for (int i = 0; i < 8; i++)
#pragma unroll
        for (int j = 0; j < 4; j++) acc[i][j] = 0.f;

    for (int n0 = split * 128; n0 < split * 128 + 128; n0 += 16) {
#pragma unroll
        for (int l = 0; l < 2; l++) {
            int idx = tid + l * 256;
            int m = idx >> 2, c = (idx & 3) << 2;
            float4 v = *(const float4*)(At + (size_t)m * NTOK + n0 + c);
            As[c + 0][m] = v.x; As[c + 1][m] = v.y; As[c + 2][m] = v.z; As[c + 3][m] = v.w;
        }
        {
            int rr = tid >> 4, cc = (tid & 15) << 2;
            *(float4*)&Vs[rr][cc] = *(const float4*)(Vb + (size_t)(n0 + rr) * 3072 + cc);
        }
        __syncthreads();
#pragma unroll
        for (int k = 0; k < 16; k++) {
            float4 a0 = *(float4*)&As[k][ty * 8];
            float4 a1 = *(float4*)&As[k][ty * 8 + 4];
            float ar[8] = {a0.x, a0.y, a0.z, a0.w, a1.x, a1.y, a1.z, a1.w};
            float4 bv = *(float4*)&Vs[k][tx * 4];
            float br[4] = {bv.x, bv.y, bv.z, bv.w};
#pragma unroll
            for (int i = 0; i < 8; i++)
#pragma unroll
                for (int j = 0; j < 4; j++) acc[i][j] += ar[i] * br[j];
        }
        __syncthreads();
    }
    float* Ob = g_gpart + (size_t)split * BH * MM * DHH + (size_t)bh * MM * DHH;
#pragma unroll
    for (int i = 0; i < 8; i++)
        *(float4*)(Ob + (size_t)(ty * 8 + i) * 64 + tx * 4) =
            make_float4(acc[i][0], acc[i][1], acc[i][2], acc[i][3]);
}

// ---------------- reduce partials ----------------
__global__ __launch_bounds__(256) void reduce_gather(float* __restrict__ outtail) {
    int t = blockIdx.x * 256 + threadIdx.x;
    float s = 0.f;
#pragma unroll
    for (int i = 0; i < GSPLIT; i++) s += g_gpart[(size_t)i * (BH * MM * DHH) + t];
    g_gather[t] = s;
    outtail[t] = s;
}

// ---------------- out stage: gated write + fp16 split epilogue ----------------
__global__ __launch_bounds__(256) void outstage_kernel() {
    int bh = blockIdx.y, b = bh >> 4, h = bh & 15;
    int n0 = blockIdx.x * 128;
    const float* At = g_qa + ((size_t)bh * NTOK + n0) * 128;
    const float* Gb = g_gather + (size_t)bh * MM * DHH;
    __shared__ float As[16][128];
    __shared__ float Gs[16][64];
    int tid = threadIdx.x, ty = tid >> 4, tx = tid & 15;
    float acc[8][4];
#pragma unroll
    for (int i = 0; i < 8; i++)
#pragma unroll
        for (int j = 0; j < 4; j++) acc[i][j] = 0.f;

    for (int m0 = 0; m0 < 128; m0 += 16) {
#pragma unroll
        for (int l = 0; l < 2; l++) {
            int idx = tid + l * 256;
            int n = idx >> 2, c = (idx & 3) << 2;
            float4 v = *(const float4*)(At + (size_t)n * 128 + m0 + c);
            As[c + 0][n] = v.x; As[c + 1][n] = v.y; As[c + 2][n] = v.z; As[c + 3][n] = v.w;
        }
        {
            int rr = tid >> 4, cc = (tid & 15) << 2;
            *(float4*)&Gs[rr][cc] = *(const float4*)(Gb + (size_t)(m0 + rr) * 64 + cc);
        }
        __syncthreads();
#pragma unroll
        for (int k = 0; k < 16; k++) {
            float4 a0 = *(float4*)&As[k][ty * 8];
            float4 a1 = *(float4*)&As[k][ty * 8 + 4];
            float ar[8] = {a0.x, a0.y, a0.z, a0.w, a1.x, a1.y, a1.z, a1.w};
            float4 bv = *(float4*)&Gs[k][tx * 4];
            float br[4] = {bv.x, bv.y, bv.z, bv.w};
#pragma unroll
            for (int i = 0; i < 8; i++)
#pragma unroll
                for (int j = 0; j < 4; j++) acc[i][j] += ar[i] * br[j];
        }
        __syncthreads();
    }
#pragma unroll
    for (int i = 0; i < 8; i++) {
        int n = n0 + ty * 8 + i;
        float gt = g_gates[((size_t)b * NTOK + n) * 16 + h];
        size_t o = ((size_t)b * NTOK + n) * 1024 + h * 64 + tx * 4;
        __half2 hv[2], lv[2];
#pragma unroll
        for (int q = 0; q < 2; q++) {
            float v0 = acc[i][2 * q] * gt, v1 = acc[i][2 * q + 1] * gt;
            __half h0 = __float2half_rn(v0), h1 = __float2half_rn(v1);
            hv[q] = __halves2half2(h0, h1);
            lv[q] = __halves2half2(__float2half_rn(v0 - __half2float(h0)),
                                   __float2half_rn(v1 - __half2float(h1)));
        }
        *(__half2*)(g_o1h + o)     = hv[0];
        *(__half2*)(g_o1h + o + 2) = hv[1];
        *(__half2*)(g_o1l + o)     = lv[0];
        *(__half2*)(g_o1l + o + 2) = lv[1];
    }
}

// ---------------- launch ----------------
extern "C" void kernel_launch(void* const* d_in, const int* in_sizes, int n_in,
                              void* d_out, int out_size) {
    const float* x      = (const float*)d_in[0];
    const float* W_qkv  = (const float*)d_in[1];
    const float* W_gate = (const float*)d_in[2];
    const float* b_gate = (const float*)d_in[3];
    const float* agent  = (const float*)d_in[4];
    const float* W_qa   = (const float*)d_in[5];
    const float* W_ak   = (const float*)d_in[6];
    const float* W_out  = (const float*)d_in[7];
    float* out = (float*)d_out;

    float *qkv, *qa, *ak;
    __half *xh, *xl, *w1h, *w1l, *w2h, *w2l, *o1h, *o1l;
    cudaGetSymbolAddress((void**)&qkv, g_qkv);
    cudaGetSymbolAddress((void**)&qa,  g_qa);
    cudaGetSymbolAddress((void**)&ak,  g_ak);
    cudaGetSymbolAddress((void**)&xh,  g_xh);
    cudaGetSymbolAddress((void**)&xl,  g_xl);
    cudaGetSymbolAddress((void**)&w1h, g_w1h);
    cudaGetSymbolAddress((void**)&w1l, g_w1l);
    cudaGetSymbolAddress((void**)&w2h, g_w2h);
    cudaGetSymbolAddress((void**)&w2l, g_w2l);
    cudaGetSymbolAddress((void**)&o1h, g_o1h);
    cudaGetSymbolAddress((void**)&o1l, g_o1l);

    cudaFuncSetAttribute(mma_gemm16, cudaFuncAttributeMaxDynamicSharedMemorySize, MMA16_SMEM);

    // 0. operand prep: splits + transposes
    split_fp16<<<(ROWS * 1024 / 4) / 256, 256>>>(x, xh, xl);
    transpose_split<<<dim3(3072 / 32, 1024 / 32), 256>>>(W_qkv, w1h, w1l, 1024, 3072);
    transpose_split<<<dim3(1024 / 32, 1024 / 32), 256>>>(W_out, w2h, w2l, 1024, 1024);
    wgate_t<<<64, 256>>>(W_gate);
    // 1. QKV projection (fp16 2-way split mma)
    mma_gemm16<<<dim3(3072 / 128, ROWS / 128), 256, MMA16_SMEM>>>(xh, xl, w1h, w1l, qkv, 3072);
    // 2. gates
    gates_kernel<<<ROWS / 8, 256>>>(x, b_gate);
    // 3. qa_sim (+fused softmax), ak_sim
    qa_sim_kernel<<<dim3(NTOK / 128, BH), 256>>>(agent);
    ak_sim_kernel<<<dim3(NTOK / 128, BH), 256>>>(agent);
    // 4. ak softmax
    softmax4096<<<BH * MM, 256>>>(ak);
    // 5. talking heads
    th_mix<<<(BB * NTOK * MM) / 256, 256>>>(qa, W_qa);
    th_mix<<<(BB * MM * NTOK) / 256, 256>>>(ak, W_ak);
    // 6. agent_gathered
    gather_kernel<<<dim3(GSPLIT, BH), 256>>>();
    reduce_gather<<<(BH * MM * DHH) / 256, 256>>>(out + (size_t)ROWS * DD);
    // 7. out stage (fused gating + fp16 split)
    outstage_kernel<<<dim3(NTOK / 128, BH), 256>>>();
    // 8. final projection (fp16 2-way split mma)
    mma_gemm16<<<dim3(DD / 128, ROWS / 128), 256, MMA16_SMEM>>>(o1h, o1l, w2h, w2l, out, DD);
}

// round 7
// speedup vs baseline: 2.2123x; 1.0082x over previous
#include <cuda_runtime.h>
#include <cuda_bf16.h>
#include <math.h>
#include <stdint.h>

// Problem constants
#define BB    4
#define NTOK  4096
#define DD    1024
#define HH    16
#define MM    128
#define DHH   64
#define SCALE 0.125f
#define ROWS  (BB*NTOK)        // 16384
#define BH    (BB*HH)          // 64
#define GSPLIT 32

typedef __nv_bfloat16 bf16;

// ---------------- device scratch (static, allowed) ----------------
__device__ float g_qkv[ROWS * 3072];
__device__ float g_qa [BH * NTOK * MM];
__device__ float g_ak [BH * MM * NTOK];
__device__ float g_akmx[BH * MM];
__device__ float g_akinv[BH * MM];
__device__ float g_gpart[GSPLIT * BH * MM * DHH];
__device__ float g_gather[BH * MM * DHH];
__device__ float g_gates[ROWS * HH];
__device__ float g_wgt[HH * 1024];        // W_gate transposed (H-major)
// bf16 split operand arrays
__device__ bf16 g_xh[ROWS * 1024];
__device__ bf16 g_xl[ROWS * 1024];
__device__ bf16 g_w1h[3072 * 1024];
__device__ bf16 g_w1l[3072 * 1024];
__device__ bf16 g_w2h[1024 * 1024];
__device__ bf16 g_w2l[1024 * 1024];
__device__ bf16 g_o1h[ROWS * 1024];
__device__ bf16 g_o1l[ROWS * 1024];

__device__ __forceinline__ uint32_t smem_u32(const void* p) {
    uint32_t a;
    asm("{ .reg .u64 t; cvta.to.shared.u64 t, %1; cvt.u32.u64 %0, t; }" : "=r"(a) : "l"(p));
    return a;
}
__device__ __forceinline__ void cp16(uint32_t dst, const void* src) {
    asm volatile("cp.async.cg.shared.global [%0], [%1], 16;" :: "r"(dst), "l"(src) : "memory");
}
__device__ __forceinline__ void mma_bf16(float* d, const uint32_t* a, const uint32_t* b) {
    asm volatile(
        "mma.sync.aligned.m16n8k16.row.col.f32.bf16.bf16.f32 "
        "{%0,%1,%2,%3}, {%4,%5,%6,%7}, {%8,%9}, {%0,%1,%2,%3};\n"
        : "+f"(d[0]), "+f"(d[1]), "+f"(d[2]), "+f"(d[3])
        : "r"(a[0]), "r"(a[1]), "r"(a[2]), "r"(a[3]), "r"(b[0]), "r"(b[1]));
}

// ================= bf16 2-way split GEMM =================
#define KDIM 1024
#define NK16 16                   // 1024 / 64
#define STAGE_BYTES16 73728       // 512 rows * 144 B
#define MMA16_SMEM (3 * STAGE_BYTES16)

__device__ __forceinline__ void ld_stage16(const bf16* __restrict__ Ah,
                                           const bf16* __restrict__ Al,
                                           const bf16* __restrict__ Bh,
                                           const bf16* __restrict__ Bl,
                                           int m0, int n0, int kc,
                                           uint32_t sbase, int tid) {
    uint32_t sb = sbase + (uint32_t)(kc % 3) * STAGE_BYTES16;
#pragma unroll
    for (int i = 0; i < 4; i++) {
        int id = tid + i * 256; int r = id >> 3, f = id & 7;
        cp16(sb + (uint32_t)(r * 144 + f * 16), Ah + (size_t)(m0 + r) * KDIM + kc * 64 + f * 8);
    }
#pragma unroll
    for (int i = 0; i < 4; i++) {
        int id = tid + i * 256; int r = id >> 3, f = id & 7;
        cp16(sb + (uint32_t)((128 + r) * 144 + f * 16), Al + (size_t)(m0 + r) * KDIM + kc * 64 + f * 8);
    }
#pragma unroll
    for (int i = 0; i < 4; i++) {
        int id = tid + i * 256; int r = id >> 3, f = id & 7;
        cp16(sb + (uint32_t)((256 + r) * 144 + f * 16), Bh + (size_t)(n0 + r) * KDIM + kc * 64 + f * 8);
    }
#pragma unroll
    for (int i = 0; i < 4; i++) {
        int id = tid + i * 256; int r = id >> 3, f = id & 7;
        cp16(sb + (uint32_t)((384 + r) * 144 + f * 16), Bl + (size_t)(n0 + r) * KDIM + kc * 64 + f * 8);
    }
    asm volatile("cp.async.commit_group;" ::: "memory");
}

__global__ __launch_bounds__(256) void mma_gemm16(const bf16* __restrict__ Ah,
                                                  const bf16* __restrict__ Al,
                                                  const bf16* __restrict__ Bth,
                                                  const bf16* __restrict__ Btl,
                                                  float* __restrict__ C, int Nc) {
    extern __shared__ char smv[];
    const int tid = threadIdx.x, wid = tid >> 5, lane = tid & 31;
    const int m0 = blockIdx.y * 128, n0 = blockIdx.x * 128;
    const int wm = (wid & 3) * 32, wn = (wid >> 2) * 64;
    const int g = lane >> 2, t = lane & 3;
    uint32_t sbase = smem_u32(smv);

    ld_stage16(Ah, Al, Bth, Btl, m0, n0, 0, sbase, tid);
    ld_stage16(Ah, Al, Bth, Btl, m0, n0, 1, sbase, tid);

    float acc[2][8][4];
#pragma unroll
    for (int i = 0; i < 2; i++)
#pragma unroll
        for (int j = 0; j < 8; j++)
#pragma unroll
            for (int q = 0; q < 4; q++) acc[i][j][q] = 0.f;

    for (int kc = 0; kc < NK16; kc++) {
        if (kc + 2 < NK16) {
            ld_stage16(Ah, Al, Bth, Btl, m0, n0, kc + 2, sbase, tid);
            asm volatile("cp.async.wait_group 2;" ::: "memory");
        } else if (kc == NK16 - 2) {
            asm volatile("cp.async.wait_group 1;" ::: "memory");
        } else {
            asm volatile("cp.async.wait_group 0;" ::: "memory");
        }
        __syncthreads();
        const uint32_t* S = (const uint32_t*)(smv + (kc % 3) * STAGE_BYTES16);
#pragma unroll
        for (int ks = 0; ks < 4; ks++) {
            const int ko = ks * 8 + t;
            uint32_t ah[2][4], al[2][4];
#pragma unroll
            for (int i = 0; i < 2; i++) {
                const uint32_t* p = S + (wm + i * 16 + g) * 36 + ko;
                ah[i][0] = p[0]; ah[i][1] = p[288]; ah[i][2] = p[4]; ah[i][3] = p[292];
                const uint32_t* q = p + 128 * 36;
                al[i][0] = q[0]; al[i][1] = q[288]; al[i][2] = q[4]; al[i][3] = q[292];
            }
#pragma unroll
            for (int j = 0; j < 8; j++) {
                const uint32_t* pb = S + (256 + wn + j * 8 + g) * 36 + ko;
                uint32_t bhv[2] = {pb[0], pb[4]};
                uint32_t blv[2] = {pb[128 * 36], pb[128 * 36 + 4]};
#pragma unroll
                for (int i = 0; i < 2; i++) {
                    mma_bf16(acc[i][j], ah[i], blv);   // hi*lo
                    mma_bf16(acc[i][j], al[i], bhv);   // lo*hi
                    mma_bf16(acc[i][j], ah[i], bhv);   // hi*hi
                }
            }
        }
        __syncthreads();
    }

#pragma unroll
    for (int i = 0; i < 2; i++) {
#pragma unroll
        for (int j = 0; j < 8; j++) {
            size_t r0 = (size_t)(m0 + wm + i * 16 + g);
            int c = n0 + wn + j * 8 + 2 * t;
            *(float2*)(C + r0 * Nc + c)       = make_float2(acc[i][j][0], acc[i][j][1]);
            *(float2*)(C + (r0 + 8) * Nc + c) = make_float2(acc[i][j][2], acc[i][j][3]);
        }
    }
}

// ---------------- elementwise bf16 split ----------------
__global__ __launch_bounds__(256) void split_bf16(const float* __restrict__ src,
                                                  bf16* __restrict__ hi,
                                                  bf16* __restrict__ lo) {
    size_t i = (size_t)blockIdx.x * 256 + threadIdx.x;   // per float4
    float4 v = ((const float4*)src)[i];
    bf16 hx = __float2bfloat16_rn(v.x), hy = __float2bfloat16_rn(v.y);
    bf16 hz = __float2bfloat16_rn(v.z), hw = __float2bfloat16_rn(v.w);
    ((__nv_bfloat162*)hi)[2 * i]     = __nv_bfloat162(hx, hy);
    ((__nv_bfloat162*)hi)[2 * i + 1] = __nv_bfloat162(hz, hw);
    ((__nv_bfloat162*)lo)[2 * i]     = __nv_bfloat162(
        __float2bfloat16_rn(v.x - __bfloat162float(hx)),
        __float2bfloat16_rn(v.y - __bfloat162float(hy)));
    ((__nv_bfloat162*)lo)[2 * i + 1] = __nv_bfloat162(
        __float2bfloat16_rn(v.z - __bfloat162float(hz)),
        __float2bfloat16_rn(v.w - __bfloat162float(hw)));
}

// ---------------- transpose + bf16 split ----------------
__global__ __launch_bounds__(256) void transpose_split(const float* __restrict__ src,
                                                       bf16* __restrict__ dh,
                                                       bf16* __restrict__ dl,
                                                       int K, int N) {
    __shared__ float t[32][33];
    int bx = blockIdx.x * 32, by = blockIdx.y * 32;
    int lx = threadIdx.x & 31, ly = threadIdx.x >> 5;
#pragma unroll
    for (int i = 0; i < 32; i += 8)
        t[ly + i][lx] = src[(size_t)(by + ly + i) * N + bx + lx];
    __syncthreads();
#pragma unroll
    for (int i = 0; i < 32; i += 8) {
        float v = t[lx][ly + i];
        bf16 h = __float2bfloat16_rn(v);
        size_t o = (size_t)(bx + ly + i) * K + by + lx;
        dh[o] = h;
        dl[o] = __float2bfloat16_rn(v - __bfloat162float(h));
    }
}

// ---------------- W_gate transpose ----------------
__global__ __launch_bounds__(256) void wgate_t(const float* __restrict__ Wg) {
    int t = blockIdx.x * 256 + threadIdx.x;
    int d = t >> 4, h = t & 15;
    g_wgt[h * 1024 + d] = Wg[t];
}

// ---------------- gates ----------------
__global__ __launch_bounds__(256) void gates_kernel(const float* __restrict__ x,
                                                    const float* __restrict__ bg) {
    int wid = threadIdx.x >> 5, lane = threadIdx.x & 31;
    int row = blockIdx.x * 8 + wid;
    const float* xr = x + (size_t)row * 1024;
    float acc[16];
#pragma unroll
    for (int h = 0; h < 16; h++) acc[h] = 0.f;
#pragma unroll 4
    for (int i = 0; i < 32; i++) {
        int d = i * 32 + lane;
        float xv = xr[d];
#pragma unroll
        for (int h = 0; h < 16; h++) acc[h] += xv * g_wgt[h * 1024 + d];
    }
#pragma unroll
    for (int h = 0; h < 16; h++) {
#pragma unroll
        for (int o = 16; o; o >>= 1) acc[h] += __shfl_xor_sync(0xffffffffu, acc[h], o);
    }
    if (lane < 16)
        g_gates[(size_t)row * 16 + lane] = 1.f / (1.f + expf(-(acc[lane] + bg[lane])));
}

// ---------------- qa_sim + fused row softmax ----------------
__global__ __launch_bounds__(256) void qa_sim_kernel(const float* __restrict__ agent) {
    int bh = blockIdx.y, b = bh >> 4, h = bh & 15;
    int n0 = blockIdx.x * 128;
    const float* Qb = g_qkv + ((size_t)(b * NTOK + n0)) * 3072 + h * 64;
    const float* Ab = agent + (size_t)h * MM * DHH;
    __shared__ float Qs[8][128];
    __shared__ float As[8][128];
    int tid = threadIdx.x;
    int r = tid >> 1, c = (tid & 1) << 2;
    int ty = tid >> 4, tx = tid & 15;
    float acc[8][8];
#pragma unroll
    for (int i = 0; i < 8; i++)
#pragma unroll
        for (int j = 0; j < 8; j++) acc[i][j] = 0.f;

    for (int k0 = 0; k0 < 64; k0 += 8) {
        float4 qv = *(const float4*)(Qb + (size_t)r * 3072 + k0 + c);
        Qs[c + 0][r] = qv.x; Qs[c + 1][r] = qv.y; Qs[c + 2][r] = qv.z; Qs[c + 3][r] = qv.w;
        float4 av = *(const float4*)(Ab + r * 64 + k0 + c);
        As[c + 0][r] = av.x * SCALE; As[c + 1][r] = av.y * SCALE;
        As[c + 2][r] = av.z * SCALE; As[c + 3][r] = av.w * SCALE;
        __syncthreads();
#pragma unroll
        for (int k = 0; k < 8; k++) {
            float4 a0 = *(float4*)&Qs[k][ty * 8];
            float4 a1 = *(float4*)&Qs[k][ty * 8 + 4];
            float4 b0 = *(float4*)&As[k][tx * 8];
            float4 b1 = *(float4*)&As[k][tx * 8 + 4];
            float ar[8] = {a0.x, a0.y, a0.z, a0.w, a1.x, a1.y, a1.z, a1.w};
            float br[8] = {b0.x, b0.y, b0.z, b0.w, b1.x, b1.y, b1.z, b1.w};
#pragma unroll
            for (int i = 0; i < 8; i++)
#pragma unroll
                for (int j = 0; j < 8; j++) acc[i][j] += ar[i] * br[j];
        }
        __syncthreads();
    }
    float* Ob = g_qa + ((size_t)bh * NTOK + n0) * 128;
#pragma unroll
    for (int i = 0; i < 8; i++) {
        float mx = acc[i][0];
#pragma unroll
        for (int j = 1; j < 8; j++) mx = fmaxf(mx, acc[i][j]);
#pragma unroll
        for (int o = 8; o; o >>= 1) mx = fmaxf(mx, __shfl_xor_sync(0xffffffffu, mx, o, 16));
        float s = 0.f;
#pragma unroll
        for (int j = 0; j < 8; j++) { acc[i][j] = expf(acc[i][j] - mx); s += acc[i][j]; }
#pragma unroll
        for (int o = 8; o; o >>= 1) s += __shfl_xor_sync(0xffffffffu, s, o, 16);
        float inv = 1.f / s;
        float* cr = Ob + (size_t)(ty * 8 + i) * 128 + tx * 8;
        *(float4*)cr       = make_float4(acc[i][0] * inv, acc[i][1] * inv,
                                         acc[i][2] * inv, acc[i][3] * inv);
        *(float4*)(cr + 4) = make_float4(acc[i][4] * inv, acc[i][5] * inv,
                                         acc[i][6] * inv, acc[i][7] * inv);
    }
}

// ---------------- ak_sim ----------------
__global__ __launch_bounds__(256) void ak_sim_kernel(const float* __restrict__ agent) {
    int bh = blockIdx.y, b = bh >> 4, h = bh & 15;
    int n0 = blockIdx.x * 128;
    const float* Kb = g_qkv + ((size_t)(b * NTOK + n0)) * 3072 + 1024 + h * 64;
    const float* Ab = agent + (size_t)h * MM * DHH;
    __shared__ float As[8][128];
    __shared__ float Ks[8][128];
    int tid = threadIdx.x;
    int r = tid >> 1, c = (tid & 1) << 2;
    int ty = tid >> 4, tx = tid & 15;
    float acc[8][8];
#pragma unroll
    for (int i = 0; i < 8; i++)
#pragma unroll
        for (int j = 0; j < 8; j++) acc[i][j] = 0.f;

    for (int k0 = 0; k0 < 64; k0 += 8) {
        float4 av = *(const float4*)(Ab + r * 64 + k0 + c);
        As[c + 0][r] = av.x * SCALE; As[c + 1][r] = av.y * SCALE;
        As[c + 2][r] = av.z * SCALE; As[c + 3][r] = av.w * SCALE;
        float4 kv = *(const float4*)(Kb + (size_t)r * 3072 + k0 + c);
        Ks[c + 0][r] = kv.x; Ks[c + 1][r] = kv.y; Ks[c + 2][r] = kv.z; Ks[c + 3][r] = kv.w;
        __syncthreads();
#pragma unroll
        for (int k = 0; k < 8; k++) {
            float4 a0 = *(float4*)&As[k][ty * 8];
            float4 a1 = *(float4*)&As[k][ty * 8 + 4];
            float4 b0 = *(float4*)&Ks[k][tx * 8];
            float4 b1 = *(float4*)&Ks[k][tx * 8 + 4];
            float ar[8] = {a0.x, a0.y, a0.z, a0.w, a1.x, a1.y, a1.z, a1.w};
            float br[8] = {b0.x, b0.y, b0.z, b0.w, b1.x, b1.y, b1.z, b1.w};
#pragma unroll
            for (int i = 0; i < 8; i++)
#pragma unroll
                for (int j = 0; j < 8; j++) acc[i][j] += ar[i] * br[j];
        }
        __syncthreads();
    }
    float* Ob = g_ak + (size_t)bh * MM * NTOK + n0;
#pragma unroll
    for (int i = 0; i < 8; i++) {
        float* cr = Ob + (size_t)(ty * 8 + i) * NTOK + tx * 8;
        *(float4*)cr       = make_float4(acc[i][0], acc[i][1], acc[i][2], acc[i][3]);
        *(float4*)(cr + 4) = make_float4(acc[i][4], acc[i][5], acc[i][6], acc[i][7]);
    }
}

// ---------------- ak row stats (max + inv-sum), read-only ----------------
__global__ __launch_bounds__(256) void ak_stats() {
    __shared__ float redm[8];
    __shared__ float reds[8];
    const float4* rp = (const float4*)(g_ak + (size_t)blockIdx.x * 4096);
    int tid = threadIdx.x, lane = tid & 31, w = tid >> 5;
    float4 v[4];
    float mx = -1e30f;
#pragma unroll
    for (int l = 0; l < 4; l++) {
        v[l] = rp[tid + l * 256];
        mx = fmaxf(mx, fmaxf(fmaxf(v[l].x, v[l].y), fmaxf(v[l].z, v[l].w)));
    }
#pragma unroll
    for (int o = 16; o; o >>= 1) mx = fmaxf(mx, __shfl_xor_sync(0xffffffffu, mx, o));
    if (lane == 0) redm[w] = mx;
    __syncthreads();
    mx = redm[0];
#pragma unroll
    for (int i = 1; i < 8; i++) mx = fmaxf(mx, redm[i]);
    float s = 0.f;
#pragma unroll
    for (int l = 0; l < 4; l++)
        s += expf(v[l].x - mx) + expf(v[l].y - mx) + expf(v[l].z - mx) + expf(v[l].w - mx);
#pragma unroll
    for (int o = 16; o; o >>= 1) s += __shfl_xor_sync(0xffffffffu, s, o);
    if (lane == 0) reds[w] = s;
    __syncthreads();
    if (tid == 0) {
        s = 0.f;
#pragma unroll
        for (int i = 0; i < 8; i++) s += reds[i];
        g_akmx[blockIdx.x] = mx;
        g_akinv[blockIdx.x] = 1.f / s;
    }
}

// ---------------- fused ak softmax-apply + talking heads (in place) ----------------
__global__ __launch_bounds__(256) void th_mix_ak(const float* __restrict__ W) {
    __shared__ float Ws[256];
    __shared__ float smx[16], sinv[16];
    int tid = threadIdx.x;
    Ws[tid] = W[tid];
    size_t t = (size_t)blockIdx.x * 256 + tid;
    const size_t inner = (size_t)MM * NTOK;          // 524288 = 2^19
    size_t b = t >> 19;
    size_t rdx = t & (inner - 1);
    int m = (int)(rdx >> 12);                        // NTOK = 4096
    if (tid < 16) {
        int row = ((int)b * 16 + tid) * 128 + m;     // same m for whole block
        smx[tid] = g_akmx[row];
        sinv[tid] = g_akinv[row];
    }
    __syncthreads();
    float* p = g_ak + b * 16 * inner + rdx;
    float e[16];
#pragma unroll
    for (int h = 0; h < 16; h++)
        e[h] = expf(p[(size_t)h * inner] - smx[h]) * sinv[h];
#pragma unroll
    for (int g = 0; g < 16; g++) {
        float a = 0.f;
#pragma unroll
        for (int h = 0; h < 16; h++) a += Ws[g * 16 + h] * e[h];
        p[(size_t)g * inner] = a;
    }
}

// ---------------- talking heads for qa (in place) ----------------
__global__ __launch_bounds__(256) void th_mix(float* __restrict__ data,
                                              const float* __restrict__ W) {
    __shared__ float Ws[256];
    Ws[threadIdx.x] = W[threadIdx.x];
    __syncthreads();
    size_t t = (size_t)blockIdx.x * 256 + threadIdx.x;
    const size_t inner = (size_t)NTOK * MM;
    size_t b = t >> 19;
    size_t idx = t & (inner - 1);
    float* p = data + b * 16 * inner + idx;
    float in[16];
#pragma unroll
    for (int h = 0; h < 16; h++) in[h] = p[(size_t)h * inner];
#pragma unroll
    for (int g = 0; g < 16; g++) {
        float a = 0.f;
#pragma unroll
        for (int h = 0; h < 16; h++) a += Ws[g * 16 + h] * in[h];
        p[(size_t)g * inner] = a;
    }
}

// ---------------- agent_gathered partials (32-way k-split) ----------------
__global__ __launch_bounds__(256) void gather_kernel() {
    int bh = blockIdx.y, b = bh >> 4, h = bh & 15;
    int split = blockIdx.x;
    const float* At = g_ak + (size_t)bh * MM * NTOK;
    const float* Vb = g_qkv + (size_t)b * NTOK * 3072 + 2048 + h * 64;
    __shared__ float As[16][128];
    __shared__ float Vs[16][64];
    int tid = threadIdx.x, ty = tid >> 4, tx = tid & 15;
    float acc[8][4];
#pragma unroll
    for (int i = 0; i < 8; i++)
#pragma unroll
        for (int j = 0; j < 4; j++) acc[i][j] = 0.f;

    for (int n0 = split * 128; n0 < split * 128 + 128; n0 += 16) {
#pragma unroll
        for (int l = 0; l < 2; l++) {
            int idx = tid + l * 256;
            int m = idx >> 2, c = (idx & 3) << 2;
            float4 v = *(const float4*)(At + (size_t)m * NTOK + n0 + c);
            As[c + 0][m] = v.x; As[c + 1][m] = v.y; As[c + 2][m] = v.z; As[c + 3][m] = v.w;
        }
        {
            int rr = tid >> 4, cc = (tid & 15) << 2;
            *(float4*)&Vs[rr][cc] = *(const float4*)(Vb + (size_t)(n0 + rr) * 3072 + cc);
        }
        __syncthreads();
#pragma unroll
        for (int k = 0; k < 16; k++) {
            float4 a0 = *(float4*)&As[k][ty * 8];
            float4 a1 = *(float4*)&As[k][ty * 8 + 4];
            float ar[8] = {a0.x, a0.y, a0.z, a0.w, a1.x, a1.y, a1.z, a1.w};
            float4 bv = *(float4*)&Vs[k][tx * 4];
            float br[4] = {bv.x, bv.y, bv.z, bv.w};
#pragma unroll
            for (int i = 0; i < 8; i++)
#pragma unroll
                for (int j = 0; j < 4; j++) acc[i][j] += ar[i] * br[j];
        }
        __syncthreads();
    }
    float* Ob = g_gpart + (size_t)split * BH * MM * DHH + (size_t)bh * MM * DHH;
#pragma unroll
    for (int i = 0; i < 8; i++)
        *(float4*)(Ob + (size_t)(ty * 8 + i) * 64 + tx * 4) =
            make_float4(acc[i][0], acc[i][1], acc[i][2], acc[i][3]);
}

// ---------------- reduce partials ----------------
__global__ __launch_bounds__(256) void reduce_gather(float* __restrict__ outtail) {
    int t = blockIdx.x * 256 + threadIdx.x;
    float s = 0.f;
#pragma unroll
    for (int i = 0; i < GSPLIT; i++) s += g_gpart[(size_t)i * (BH * MM * DHH) + t];
    g_gather[t] = s;
    outtail[t] = s;
}

// ---------------- out stage: gated write + bf16 split epilogue ----------------
__global__ __launch_bounds__(256) void outstage_kernel() {
    int bh = blockIdx.y, b = bh >> 4, h = bh & 15;
    int n0 = blockIdx.x * 128;
    const float* At = g_qa + ((size_t)bh * NTOK + n0) * 128;
    const float* Gb = g_gather + (size_t)bh * MM * DHH;
    __shared__ float As[16][128];
    __shared__ float Gs[16][64];
    int tid = threadIdx.x, ty = tid >> 4, tx = tid & 15;
    float acc[8][4];
#pragma unroll
    for (int i = 0; i < 8; i++)
#pragma unroll
        for (int j = 0; j < 4; j++) acc[i][j] = 0.f;

    for (int m0 = 0; m0 < 128; m0 += 16) {
#pragma unroll
        for (int l = 0; l < 2; l++) {
            int idx = tid + l * 256;
            int n = idx >> 2, c = (idx & 3) << 2;
            float4 v = *(const float4*)(At + (size_t)n * 128 + m0 + c);
            As[c + 0][n] = v.x; As[c + 1][n] = v.y; As[c + 2][n] = v.z; As[c + 3][n] = v.w;
        }
        {
            int rr = tid >> 4, cc = (tid & 15) << 2;
            *(float4*)&Gs[rr][cc] = *(const float4*)(Gb + (size_t)(m0 + rr) * 64 + cc);
        }
        __syncthreads();
#pragma unroll
        for (int k = 0; k < 16; k++) {
            float4 a0 = *(float4*)&As[k][ty * 8];
            float4 a1 = *(float4*)&As[k][ty * 8 + 4];
            float ar[8] = {a0.x, a0.y, a0.z, a0.w, a1.x, a1.y, a1.z, a1.w};
            float4 bv = *(float4*)&Gs[k][tx * 4];
            float br[4] = {bv.x, bv.y, bv.z, bv.w};
#pragma unroll
            for (int i = 0; i < 8; i++)
#pragma unroll
                for (int j = 0; j < 4; j++) acc[i][j] += ar[i] * br[j];
        }
        __syncthreads();
    }
#pragma unroll
    for (int i = 0; i < 8; i++) {
        int n = n0 + ty * 8 + i;
        float gt = g_gates[((size_t)b * NTOK + n) * 16 + h];
        size_t o = ((size_t)b * NTOK + n) * 1024 + h * 64 + tx * 4;
#pragma unroll
        for (int q = 0; q < 2; q++) {
            float v0 = acc[i][2 * q] * gt, v1 = acc[i][2 * q + 1] * gt;
            bf16 h0 = __float2bfloat16_rn(v0), h1 = __float2bfloat16_rn(v1);
            *(__nv_bfloat162*)(g_o1h + o + 2 * q) = __nv_bfloat162(h0, h1);
            *(__nv_bfloat162*)(g_o1l + o + 2 * q) = __nv_bfloat162(
                __float2bfloat16_rn(v0 - __bfloat162float(h0)),
                __float2bfloat16_rn(v1 - __bfloat162float(h1)));
        }
    }
}

// ---------------- launch ----------------
extern "C" void kernel_launch(void* const* d_in, const int* in_sizes, int n_in,
                              void* d_out, int out_size) {
    const float* x      = (const float*)d_in[0];
    const float* W_qkv  = (const float*)d_in[1];
    const float* W_gate = (const float*)d_in[2];
    const float* b_gate = (const float*)d_in[3];
    const float* agent  = (const float*)d_in[4];
    const float* W_qa   = (const float*)d_in[5];
    const float* W_ak   = (const float*)d_in[6];
    const float* W_out  = (const float*)d_in[7];
    float* out = (float*)d_out;

    float *qkv, *qa;
    bf16 *xh, *xl, *w1h, *w1l, *w2h, *w2l, *o1h, *o1l;
    cudaGetSymbolAddress((void**)&qkv, g_qkv);
    cudaGetSymbolAddress((void**)&qa,  g_qa);
    cudaGetSymbolAddress((void**)&xh,  g_xh);
    cudaGetSymbolAddress((void**)&xl,  g_xl);
    cudaGetSymbolAddress((void**)&w1h, g_w1h);
    cudaGetSymbolAddress((void**)&w1l, g_w1l);
    cudaGetSymbolAddress((void**)&w2h, g_w2h);
    cudaGetSymbolAddress((void**)&w2l, g_w2l);
    cudaGetSymbolAddress((void**)&o1h, g_o1h);
    cudaGetSymbolAddress((void**)&o1l, g_o1l);

    cudaFuncSetAttribute(mma_gemm16, cudaFuncAttributeMaxDynamicSharedMemorySize, MMA16_SMEM);

    // 0. operand prep
    split_bf16<<<(ROWS * 1024 / 4) / 256, 256>>>(x, xh, xl);
    transpose_split<<<dim3(3072 / 32, 1024 / 32), 256>>>(W_qkv, w1h, w1l, 1024, 3072);
    transpose_split<<<dim3(1024 / 32, 1024 / 32), 256>>>(W_out, w2h, w2l, 1024, 1024);
    wgate_t<<<64, 256>>>(W_gate);
    // 1. QKV projection (bf16 2-way split mma)
    mma_gemm16<<<dim3(3072 / 128, ROWS / 128), 256, MMA16_SMEM>>>(xh, xl, w1h, w1l, qkv, 3072);
    // 2. gates
    gates_kernel<<<ROWS / 8, 256>>>(x, b_gate);
    // 3. qa_sim (+fused softmax), ak_sim
    qa_sim_kernel<<<dim3(NTOK / 128, BH), 256>>>(agent);
    ak_sim_kernel<<<dim3(NTOK / 128, BH), 256>>>(agent);
    // 4. ak stats + fused softmax-apply/talking-heads
    ak_stats<<<BH * MM, 256>>>();
    th_mix_ak<<<(BB * MM * NTOK) / 256, 256>>>(W_ak);
    // 5. talking heads for qa
    th_mix<<<(BB * NTOK * MM) / 256, 256>>>(qa, W_qa);
    // 6. agent_gathered
    gather_kernel<<<dim3(GSPLIT, BH), 256>>>();
    reduce_gather<<<(BH * MM * DHH) / 256, 256>>>(out + (size_t)ROWS * DD);
    // 7. out stage (fused gating + bf16 split)
    outstage_kernel<<<dim3(NTOK / 128, BH), 256>>>();
    // 8. final projection (bf16 2-way split mma)
    mma_gemm16<<<dim3(DD / 128, ROWS / 128), 256, MMA16_SMEM>>>(o1h, o1l, w2h, w2l, out, DD);
}

// round 8
// speedup vs baseline: 2.3733x; 1.0728x over previous
#include <cuda_runtime.h>
#include <cuda_bf16.h>
#include <math.h>
#include <stdint.h>

// Problem constants
#define BB    4
#define NTOK  4096
#define DD    1024
#define HH    16
#define MM    128
#define DHH   64
#define SCALE 0.125f
#define ROWS  (BB*NTOK)        // 16384
#define BH    (BB*HH)          // 64
#define GSPLIT 32

typedef __nv_bfloat16 bf16;

// ---------------- device scratch (static, allowed) ----------------
__device__ float g_qkv[ROWS * 3072];
__device__ float g_qa [BH * NTOK * MM];
__device__ float g_ak [BH * MM * NTOK];
__device__ float g_akmx[BH * MM];
__device__ float g_akinv[BH * MM];
__device__ float g_gpart[GSPLIT * BH * MM * DHH];
__device__ float g_gather[BH * MM * DHH];
__device__ float g_gates[ROWS * HH];
__device__ float g_wgt[HH * 1024];
__device__ bf16 g_xh[ROWS * 1024];
__device__ bf16 g_xl[ROWS * 1024];
__device__ bf16 g_w1h[3072 * 1024];
__device__ bf16 g_w1l[3072 * 1024];
__device__ bf16 g_w2h[1024 * 1024];
__device__ bf16 g_w2l[1024 * 1024];
__device__ bf16 g_o1h[ROWS * 1024];
__device__ bf16 g_o1l[ROWS * 1024];

__device__ __forceinline__ uint32_t smem_u32(const void* p) {
    uint32_t a;
    asm("{ .reg .u64 t; cvta.to.shared.u64 t, %1; cvt.u32.u64 %0, t; }" : "=r"(a) : "l"(p));
    return a;
}
__device__ __forceinline__ void cp16(uint32_t dst, const void* src) {
    asm volatile("cp.async.cg.shared.global [%0], [%1], 16;" :: "r"(dst), "l"(src) : "memory");
}
__device__ __forceinline__ void mma_bf16(float* d, const uint32_t* a, const uint32_t* b) {
    asm volatile(
        "mma.sync.aligned.m16n8k16.row.col.f32.bf16.bf16.f32 "
        "{%0,%1,%2,%3}, {%4,%5,%6,%7}, {%8,%9}, {%0,%1,%2,%3};\n"
        : "+f"(d[0]), "+f"(d[1]), "+f"(d[2]), "+f"(d[3])
        : "r"(a[0]), "r"(a[1]), "r"(a[2]), "r"(a[3]), "r"(b[0]), "r"(b[1]));
}
// split a float4 into bf16 hi/lo pairs, store 8 bytes to each of two smem ptrs
__device__ __forceinline__ void store_split4(char* hp, char* lp, float4 v) {
    bf16 h0 = __float2bfloat16_rn(v.x), h1 = __float2bfloat16_rn(v.y);
    bf16 h2 = __float2bfloat16_rn(v.z), h3 = __float2bfloat16_rn(v.w);
    *(__nv_bfloat162*)hp       = __nv_bfloat162(h0, h1);
    *(__nv_bfloat162*)(hp + 4) = __nv_bfloat162(h2, h3);
    *(__nv_bfloat162*)lp       = __nv_bfloat162(
        __float2bfloat16_rn(v.x - __bfloat162float(h0)),
        __float2bfloat16_rn(v.y - __bfloat162float(h1)));
    *(__nv_bfloat162*)(lp + 4) = __nv_bfloat162(
        __float2bfloat16_rn(v.z - __bfloat162float(h2)),
        __float2bfloat16_rn(v.w - __bfloat162float(h3)));
}

// ================= bf16 2-way split GEMM (dense projections) =================
#define KDIM 1024
#define NK16 16
#define STAGE_BYTES16 73728
#define MMA16_SMEM (3 * STAGE_BYTES16)

__device__ __forceinline__ void ld_stage16(const bf16* __restrict__ Ah,
                                           const bf16* __restrict__ Al,
                                           const bf16* __restrict__ Bh,
                                           const bf16* __restrict__ Bl,
                                           int m0, int n0, int kc,
                                           uint32_t sbase, int tid) {
    uint32_t sb = sbase + (uint32_t)(kc % 3) * STAGE_BYTES16;
#pragma unroll
    for (int i = 0; i < 4; i++) {
        int id = tid + i * 256; int r = id >> 3, f = id & 7;
        cp16(sb + (uint32_t)(r * 144 + f * 16), Ah + (size_t)(m0 + r) * KDIM + kc * 64 + f * 8);
    }
#pragma unroll
    for (int i = 0; i < 4; i++) {
        int id = tid + i * 256; int r = id >> 3, f = id & 7;
        cp16(sb + (uint32_t)((128 + r) * 144 + f * 16), Al + (size_t)(m0 + r) * KDIM + kc * 64 + f * 8);
    }
#pragma unroll
    for (int i = 0; i < 4; i++) {
        int id = tid + i * 256; int r = id >> 3, f = id & 7;
        cp16(sb + (uint32_t)((256 + r) * 144 + f * 16), Bh + (size_t)(n0 + r) * KDIM + kc * 64 + f * 8);
    }
#pragma unroll
    for (int i = 0; i < 4; i++) {
        int id = tid + i * 256; int r = id >> 3, f = id & 7;
        cp16(sb + (uint32_t)((384 + r) * 144 + f * 16), Bl + (size_t)(n0 + r) * KDIM + kc * 64 + f * 8);
    }
    asm volatile("cp.async.commit_group;" ::: "memory");
}

__global__ __launch_bounds__(256) void mma_gemm16(const bf16* __restrict__ Ah,
                                                  const bf16* __restrict__ Al,
                                                  const bf16* __restrict__ Bth,
                                                  const bf16* __restrict__ Btl,
                                                  float* __restrict__ C, int Nc) {
    extern __shared__ char smv[];
    const int tid = threadIdx.x, wid = tid >> 5, lane = tid & 31;
    const int m0 = blockIdx.y * 128, n0 = blockIdx.x * 128;
    const int wm = (wid & 3) * 32, wn = (wid >> 2) * 64;
    const int g = lane >> 2, t = lane & 3;
    uint32_t sbase = smem_u32(smv);

    ld_stage16(Ah, Al, Bth, Btl, m0, n0, 0, sbase, tid);
    ld_stage16(Ah, Al, Bth, Btl, m0, n0, 1, sbase, tid);

    float acc[2][8][4];
#pragma unroll
    for (int i = 0; i < 2; i++)
#pragma unroll
        for (int j = 0; j < 8; j++)
#pragma unroll
            for (int q = 0; q < 4; q++) acc[i][j][q] = 0.f;

    for (int kc = 0; kc < NK16; kc++) {
        if (kc + 2 < NK16) {
            ld_stage16(Ah, Al, Bth, Btl, m0, n0, kc + 2, sbase, tid);
            asm volatile("cp.async.wait_group 2;" ::: "memory");
        } else if (kc == NK16 - 2) {
            asm volatile("cp.async.wait_group 1;" ::: "memory");
        } else {
            asm volatile("cp.async.wait_group 0;" ::: "memory");
        }
        __syncthreads();
        const uint32_t* S = (const uint32_t*)(smv + (kc % 3) * STAGE_BYTES16);
#pragma unroll
        for (int ks = 0; ks < 4; ks++) {
            const int ko = ks * 8 + t;
            uint32_t ah[2][4], al[2][4];
#pragma unroll
            for (int i = 0; i < 2; i++) {
                const uint32_t* p = S + (wm + i * 16 + g) * 36 + ko;
                ah[i][0] = p[0]; ah[i][1] = p[288]; ah[i][2] = p[4]; ah[i][3] = p[292];
                const uint32_t* q = p + 128 * 36;
                al[i][0] = q[0]; al[i][1] = q[288]; al[i][2] = q[4]; al[i][3] = q[292];
            }
#pragma unroll
            for (int j = 0; j < 8; j++) {
                const uint32_t* pb = S + (256 + wn + j * 8 + g) * 36 + ko;
                uint32_t bhv[2] = {pb[0], pb[4]};
                uint32_t blv[2] = {pb[128 * 36], pb[128 * 36 + 4]};
#pragma unroll
                for (int i = 0; i < 2; i++) {
                    mma_bf16(acc[i][j], ah[i], blv);
                    mma_bf16(acc[i][j], al[i], bhv);
                    mma_bf16(acc[i][j], ah[i], bhv);
                }
            }
        }
        __syncthreads();
    }

#pragma unroll
    for (int i = 0; i < 2; i++) {
#pragma unroll
        for (int j = 0; j < 8; j++) {
            size_t r0 = (size_t)(m0 + wm + i * 16 + g);
            int c = n0 + wn + j * 8 + 2 * t;
            *(float2*)(C + r0 * Nc + c)       = make_float2(acc[i][j][0], acc[i][j][1]);
            *(float2*)(C + (r0 + 8) * Nc + c) = make_float2(acc[i][j][2], acc[i][j][3]);
        }
    }
}

// ================= attention-side 128x128xK=64 split-bf16 MMA =================
// smem layout identical to mma_gemm16 stage: rows 0-127 A_hi, 128-255 A_lo,
// 256-383 B_hi, 384-511 B_lo; 144 B row stride (64 halves + pad).
#define ATT_SMEM 73728

// qa: A = q (n rows), B = a*SCALE (m rows); fused softmax over m; writes g_qa[bh][n][m]
__global__ __launch_bounds__(256) void qa_mma(const float* __restrict__ agent) {
    extern __shared__ char smv[];
    __shared__ float smx[128][2];
    __shared__ float ssum[128][2];
    const int tid = threadIdx.x, wid = tid >> 5, lane = tid & 31;
    const int bh = blockIdx.y, b = bh >> 4, h = bh & 15;
    const int n0 = blockIdx.x * 128;
    const int wm = (wid & 3) * 32, wn = (wid >> 2) * 64;
    const int g = lane >> 2, t = lane & 3;
    const int half = wid >> 2;

    const float* qptr = g_qkv + ((size_t)(b * NTOK + n0)) * 3072 + h * 64;
    const float* aptr = agent + (size_t)h * MM * DHH;
#pragma unroll
    for (int i = 0; i < 8; i++) {
        int id = tid + i * 256;                 // 0..2047
        int r = id >> 4, f4 = id & 15;
        float4 v = *(const float4*)(qptr + (size_t)r * 3072 + f4 * 4);
        store_split4(smv + r * 144 + f4 * 8, smv + (128 + r) * 144 + f4 * 8, v);
    }
#pragma unroll
    for (int i = 0; i < 8; i++) {
        int id = tid + i * 256;
        int r = id >> 4, f4 = id & 15;
        float4 v = *(const float4*)(aptr + r * 64 + f4 * 4);
        v.x *= SCALE; v.y *= SCALE; v.z *= SCALE; v.w *= SCALE;
        store_split4(smv + (256 + r) * 144 + f4 * 8, smv + (384 + r) * 144 + f4 * 8, v);
    }
    __syncthreads();

    float acc[2][8][4];
#pragma unroll
    for (int i = 0; i < 2; i++)
#pragma unroll
        for (int j = 0; j < 8; j++)
#pragma unroll
            for (int q = 0; q < 4; q++) acc[i][j][q] = 0.f;
    const uint32_t* S = (const uint32_t*)smv;
#pragma unroll
    for (int ks = 0; ks < 4; ks++) {
        const int ko = ks * 8 + t;
        uint32_t ah[2][4], al[2][4];
#pragma unroll
        for (int i = 0; i < 2; i++) {
            const uint32_t* p = S + (wm + i * 16 + g) * 36 + ko;
            ah[i][0] = p[0]; ah[i][1] = p[288]; ah[i][2] = p[4]; ah[i][3] = p[292];
            const uint32_t* q = p + 128 * 36;
            al[i][0] = q[0]; al[i][1] = q[288]; al[i][2] = q[4]; al[i][3] = q[292];
        }
#pragma unroll
        for (int j = 0; j < 8; j++) {
            const uint32_t* pb = S + (256 + wn + j * 8 + g) * 36 + ko;
            uint32_t bhv[2] = {pb[0], pb[4]};
            uint32_t blv[2] = {pb[128 * 36], pb[128 * 36 + 4]};
#pragma unroll
            for (int i = 0; i < 2; i++) {
                mma_bf16(acc[i][j], ah[i], blv);
                mma_bf16(acc[i][j], al[i], bhv);
                mma_bf16(acc[i][j], ah[i], bhv);
            }
        }
    }

    // fused softmax over m (row spans two warps: halves at wn=0 / wn=64)
#pragma unroll
    for (int i = 0; i < 2; i++) {
#pragma unroll
        for (int qh = 0; qh < 2; qh++) {
            float lm = -1e30f;
#pragma unroll
            for (int j = 0; j < 8; j++)
                lm = fmaxf(lm, fmaxf(acc[i][j][qh * 2], acc[i][j][qh * 2 + 1]));
            lm = fmaxf(lm, __shfl_xor_sync(0xffffffffu, lm, 1));
            lm = fmaxf(lm, __shfl_xor_sync(0xffffffffu, lm, 2));
            if (t == 0) smx[wm + i * 16 + g + qh * 8][half] = lm;
        }
    }
    __syncthreads();
#pragma unroll
    for (int i = 0; i < 2; i++) {
#pragma unroll
        for (int qh = 0; qh < 2; qh++) {
            int r = wm + i * 16 + g + qh * 8;
            float mx = fmaxf(smx[r][0], smx[r][1]);
            float ls = 0.f;
#pragma unroll
            for (int j = 0; j < 8; j++) {
                acc[i][j][qh * 2]     = expf(acc[i][j][qh * 2] - mx);
                acc[i][j][qh * 2 + 1] = expf(acc[i][j][qh * 2 + 1] - mx);
                ls += acc[i][j][qh * 2] + acc[i][j][qh * 2 + 1];
            }
            ls += __shfl_xor_sync(0xffffffffu, ls, 1);
            ls += __shfl_xor_sync(0xffffffffu, ls, 2);
            if (t == 0) ssum[r][half] = ls;
        }
    }
    __syncthreads();
#pragma unroll
    for (int i = 0; i < 2; i++) {
#pragma unroll
        for (int qh = 0; qh < 2; qh++) {
            int r = wm + i * 16 + g + qh * 8;
            float inv = 1.f / (ssum[r][0] + ssum[r][1]);
            float* rp = g_qa + ((size_t)bh * NTOK + n0 + r) * 128 + wn + 2 * t;
#pragma unroll
            for (int j = 0; j < 8; j++)
                *(float2*)(rp + j * 8) = make_float2(acc[i][j][qh * 2] * inv,
                                                     acc[i][j][qh * 2 + 1] * inv);
        }
    }
}

// ak: A = a*SCALE (m rows), B = k (n rows); writes raw scores g_ak[bh][m][n]
__global__ __launch_bounds__(256) void ak_mma(const float* __restrict__ agent) {
    extern __shared__ char smv[];
    const int tid = threadIdx.x, wid = tid >> 5, lane = tid & 31;
    const int bh = blockIdx.y, b = bh >> 4, h = bh & 15;
    const int n0 = blockIdx.x * 128;
    const int wm = (wid & 3) * 32, wn = (wid >> 2) * 64;
    const int g = lane >> 2, t = lane & 3;

    const float* aptr = agent + (size_t)h * MM * DHH;
    const float* kptr = g_qkv + ((size_t)(b * NTOK + n0)) * 3072 + 1024 + h * 64;
#pragma unroll
    for (int i = 0; i < 8; i++) {
        int id = tid + i * 256;
        int r = id >> 4, f4 = id & 15;
        float4 v = *(const float4*)(aptr + r * 64 + f4 * 4);
        v.x *= SCALE; v.y *= SCALE; v.z *= SCALE; v.w *= SCALE;
        store_split4(smv + r * 144 + f4 * 8, smv + (128 + r) * 144 + f4 * 8, v);
    }
#pragma unroll
    for (int i = 0; i < 8; i++) {
        int id = tid + i * 256;
        int r = id >> 4, f4 = id & 15;
        float4 v = *(const float4*)(kptr + (size_t)r * 3072 + f4 * 4);
        store_split4(smv + (256 + r) * 144 + f4 * 8, smv + (384 + r) * 144 + f4 * 8, v);
    }
    __syncthreads();

    float acc[2][8][4];
#pragma unroll
    for (int i = 0; i < 2; i++)
#pragma unroll
        for (int j = 0; j < 8; j++)
#pragma unroll
            for (int q = 0; q < 4; q++) acc[i][j][q] = 0.f;
    const uint32_t* S = (const uint32_t*)smv;
#pragma unroll
    for (int ks = 0; ks < 4; ks++) {
        const int ko = ks * 8 + t;
        uint32_t ah[2][4], al[2][4];
#pragma unroll
        for (int i = 0; i < 2; i++) {
            const uint32_t* p = S + (wm + i * 16 + g) * 36 + ko;
            ah[i][0] = p[0]; ah[i][1] = p[288]; ah[i][2] = p[4]; ah[i][3] = p[292];
            const uint32_t* q = p + 128 * 36;
            al[i][0] = q[0]; al[i][1] = q[288]; al[i][2] = q[4]; al[i][3] = q[292];
        }
#pragma unroll
        for (int j = 0; j < 8; j++) {
            const uint32_t* pb = S + (256 + wn + j * 8 + g) * 36 + ko;
            uint32_t bhv[2] = {pb[0], pb[4]};
            uint32_t blv[2] = {pb[128 * 36], pb[128 * 36 + 4]};
#pragma unroll
            for (int i = 0; i < 2; i++) {
                mma_bf16(acc[i][j], ah[i], blv);
                mma_bf16(acc[i][j], al[i], bhv);
                mma_bf16(acc[i][j], ah[i], bhv);
            }
        }
    }

#pragma unroll
    for (int i = 0; i < 2; i++) {
#pragma unroll
        for (int j = 0; j < 8; j++) {
            int m = wm + i * 16 + g;
            int c = n0 + wn + j * 8 + 2 * t;
            *(float2*)(g_ak + ((size_t)bh * MM + m) * NTOK + c) =
                make_float2(acc[i][j][0], acc[i][j][1]);
            *(float2*)(g_ak + ((size_t)bh * MM + m + 8) * NTOK + c) =
                make_float2(acc[i][j][2], acc[i][j][3]);
        }
    }
}

// ---------------- elementwise bf16 split ----------------
__global__ __launch_bounds__(256) void split_bf16(const float* __restrict__ src,
                                                  bf16* __restrict__ hi,
                                                  bf16* __restrict__ lo) {
    size_t i = (size_t)blockIdx.x * 256 + threadIdx.x;
    float4 v = ((const float4*)src)[i];
    bf16 hx = __float2bfloat16_rn(v.x), hy = __float2bfloat16_rn(v.y);
    bf16 hz = __float2bfloat16_rn(v.z), hw = __float2bfloat16_rn(v.w);
    ((__nv_bfloat162*)hi)[2 * i]     = __nv_bfloat162(hx, hy);
    ((__nv_bfloat162*)hi)[2 * i + 1] = __nv_bfloat162(hz, hw);
    ((__nv_bfloat162*)lo)[2 * i]     = __nv_bfloat162(
        __float2bfloat16_rn(v.x - __bfloat162float(hx)),
        __float2bfloat16_rn(v.y - __bfloat162float(hy)));
    ((__nv_bfloat162*)lo)[2 * i + 1] = __nv_bfloat162(
        __float2bfloat16_rn(v.z - __bfloat162float(hz)),
        __float2bfloat16_rn(v.w - __bfloat162float(hw)));
}

// ---------------- transpose + bf16 split ----------------
__global__ __launch_bounds__(256) void transpose_split(const float* __restrict__ src,
                                                       bf16* __restrict__ dh,
                                                       bf16* __restrict__ dl,
                                                       int K, int N) {
    __shared__ float t[32][33];
    int bx = blockIdx.x * 32, by = blockIdx.y * 32;
    int lx = threadIdx.x & 31, ly = threadIdx.x >> 5;
#pragma unroll
    for (int i = 0; i < 32; i += 8)
        t[ly + i][lx] = src[(size_t)(by + ly + i) * N + bx + lx];
    __syncthreads();
#pragma unroll
    for (int i = 0; i < 32; i += 8) {
        float v = t[lx][ly + i];
        bf16 h = __float2bfloat16_rn(v);
        size_t o = (size_t)(bx + ly + i) * K + by + lx;
        dh[o] = h;
        dl[o] = __float2bfloat16_rn(v - __bfloat162float(h));
    }
}

// ---------------- W_gate transpose ----------------
__global__ __launch_bounds__(256) void wgate_t(const float* __restrict__ Wg) {
    int t = blockIdx.x * 256 + threadIdx.x;
    int d = t >> 4, h = t & 15;
    g_wgt[h * 1024 + d] = Wg[t];
}

// ---------------- gates ----------------
__global__ __launch_bounds__(256) void gates_kernel(const float* __restrict__ x,
                                                    const float* __restrict__ bg) {
    int wid = threadIdx.x >> 5, lane = threadIdx.x & 31;
    int row = blockIdx.x * 8 + wid;
    const float* xr = x + (size_t)row * 1024;
    float acc[16];
#pragma unroll
    for (int h = 0; h < 16; h++) acc[h] = 0.f;
#pragma unroll 4
    for (int i = 0; i < 32; i++) {
        int d = i * 32 + lane;
        float xv = xr[d];
#pragma unroll
        for (int h = 0; h < 16; h++) acc[h] += xv * g_wgt[h * 1024 + d];
    }
#pragma unroll
    for (int h = 0; h < 16; h++) {
#pragma unroll
        for (int o = 16; o; o >>= 1) acc[h] += __shfl_xor_sync(0xffffffffu, acc[h], o);
    }
    if (lane < 16)
        g_gates[(size_t)row * 16 + lane] = 1.f / (1.f + expf(-(acc[lane] + bg[lane])));
}

// ---------------- ak row stats (max + inv-sum) ----------------
__global__ __launch_bounds__(256) void ak_stats() {
    __shared__ float redm[8];
    __shared__ float reds[8];
    const float4* rp = (const float4*)(g_ak + (size_t)blockIdx.x * 4096);
    int tid = threadIdx.x, lane = tid & 31, w = tid >> 5;
    float4 v[4];
    float mx = -1e30f;
#pragma unroll
    for (int l = 0; l < 4; l++) {
        v[l] = rp[tid + l * 256];
        mx = fmaxf(mx, fmaxf(fmaxf(v[l].x, v[l].y), fmaxf(v[l].z, v[l].w)));
    }
#pragma unroll
    for (int o = 16; o; o >>= 1) mx = fmaxf(mx, __shfl_xor_sync(0xffffffffu, mx, o));
    if (lane == 0) redm[w] = mx;
    __syncthreads();
    mx = redm[0];
#pragma unroll
    for (int i = 1; i < 8; i++) mx = fmaxf(mx, redm[i]);
    float s = 0.f;
#pragma unroll
    for (int l = 0; l < 4; l++)
        s += expf(v[l].x - mx) + expf(v[l].y - mx) + expf(v[l].z - mx) + expf(v[l].w - mx);
#pragma unroll
    for (int o = 16; o; o >>= 1) s += __shfl_xor_sync(0xffffffffu, s, o);
    if (lane == 0) reds[w] = s;
    __syncthreads();
    if (tid == 0) {
        s = 0.f;
#pragma unroll
        for (int i = 0; i < 8; i++) s += reds[i];
        g_akmx[blockIdx.x] = mx;
        g_akinv[blockIdx.x] = 1.f / s;
    }
}

// ---------------- fused ak softmax-apply + talking heads ----------------
__global__ __launch_bounds__(256) void th_mix_ak(const float* __restrict__ W) {
    __shared__ float Ws[256];
    __shared__ float smx[16], sinv[16];
    int tid = threadIdx.x;
    Ws[tid] = W[tid];
    size_t t = (size_t)blockIdx.x * 256 + tid;
    const size_t inner = (size_t)MM * NTOK;
    size_t b = t >> 19;
    size_t rdx = t & (inner - 1);
    int m = (int)(rdx >> 12);
    if (tid < 16) {
        int row = ((int)b * 16 + tid) * 128 + m;
        smx[tid] = g_akmx[row];
        sinv[tid] = g_akinv[row];
    }
    __syncthreads();
    float* p = g_ak + b * 16 * inner + rdx;
    float e[16];
#pragma unroll
    for (int h = 0; h < 16; h++)
        e[h] = expf(p[(size_t)h * inner] - smx[h]) * sinv[h];
#pragma unroll
    for (int g = 0; g < 16; g++) {
        float a = 0.f;
#pragma unroll
        for (int h = 0; h < 16; h++) a += Ws[g * 16 + h] * e[h];
        p[(size_t)g * inner] = a;
    }
}

// ---------------- talking heads for qa ----------------
__global__ __launch_bounds__(256) void th_mix(float* __restrict__ data,
                                              const float* __restrict__ W) {
    __shared__ float Ws[256];
    Ws[threadIdx.x] = W[threadIdx.x];
    __syncthreads();
    size_t t = (size_t)blockIdx.x * 256 + threadIdx.x;
    const size_t inner = (size_t)NTOK * MM;
    size_t b = t >> 19;
    size_t idx = t & (inner - 1);
    float* p = data + b * 16 * inner + idx;
    float in[16];
#pragma unroll
    for (int h = 0; h < 16; h++) in[h] = p[(size_t)h * inner];
#pragma unroll
    for (int g = 0; g < 16; g++) {
        float a = 0.f;
#pragma unroll
        for (int h = 0; h < 16; h++) a += Ws[g * 16 + h] * in[h];
        p[(size_t)g * inner] = a;
    }
}

// ---------------- agent_gathered partials (32-way k-split) ----------------
__global__ __launch_bounds__(256) void gather_kernel() {
    int bh = blockIdx.y, b = bh >> 4, h = bh & 15;
    int split = blockIdx.x;
    const float* At = g_ak + (size_t)bh * MM * NTOK;
    const float* Vb = g_qkv + (size_t)b * NTOK * 3072 + 2048 + h * 64;
    __shared__ float As[16][128];
    __shared__ float Vs[16][64];
    int tid = threadIdx.x, ty = tid >> 4, tx = tid & 15;
    float acc[8][4];
#pragma unroll
    for (int i = 0; i < 8; i++)
#pragma unroll
        for (int j = 0; j < 4; j++) acc[i][j] = 0.f;

    for (int n0 = split * 128; n0 < split * 128 + 128; n0 += 16) {
#pragma unroll
        for (int l = 0; l < 2; l++) {
            int idx = tid + l * 256;
            int m = idx >> 2, c = (idx & 3) << 2;
            float4 v = *(const float4*)(At + (size_t)m * NTOK + n0 + c);
            As[c + 0][m] = v.x; As[c + 1][m] = v.y; As[c + 2][m] = v.z; As[c + 3][m] = v.w;
        }
        {
            int rr = tid >> 4, cc = (tid & 15) << 2;
            *(float4*)&Vs[rr][cc] = *(const float4*)(Vb + (size_t)(n0 + rr) * 3072 + cc);
        }
        __syncthreads();
#pragma unroll
        for (int k = 0; k < 16; k++) {
            float4 a0 = *(float4*)&As[k][ty * 8];
            float4 a1 = *(float4*)&As[k][ty * 8 + 4];
            float ar[8] = {a0.x, a0.y, a0.z, a0.w, a1.x, a1.y, a1.z, a1.w};
            float4 bv = *(float4*)&Vs[k][tx * 4];
            float br[4] = {bv.x, bv.y, bv.z, bv.w};
#pragma unroll
            for (int i = 0; i < 8; i++)
#pragma unroll
                for (int j = 0; j < 4; j++) acc[i][j] += ar[i] * br[j];
        }
        __syncthreads();
    }
    float* Ob = g_gpart + (size_t)split * BH * MM * DHH + (size_t)bh * MM * DHH;
#pragma unroll
    for (int i = 0; i < 8; i++)
        *(float4*)(Ob + (size_t)(ty * 8 + i) * 64 + tx * 4) =
            make_float4(acc[i][0], acc[i][1], acc[i][2], acc[i][3]);
}

// ---------------- reduce partials ----------------
__global__ __launch_bounds__(256) void reduce_gather(float* __restrict__ outtail) {
    int t = blockIdx.x * 256 + threadIdx.x;
    float s = 0.f;
#pragma unroll
    for (int i = 0; i < GSPLIT; i++) s += g_gpart[(size_t)i * (BH * MM * DHH) + t];
    g_gather[t] = s;
    outtail[t] = s;
}

// ---------------- out stage ----------------
__global__ __launch_bounds__(256) void outstage_kernel() {
    int bh = blockIdx.y, b = bh >> 4, h = bh & 15;
    int n0 = blockIdx.x * 128;
    const float* At = g_qa + ((size_t)bh * NTOK + n0) * 128;
    const float* Gb = g_gather + (size_t)bh * MM * DHH;
    __shared__ float As[16][128];
    __shared__ float Gs[16][64];
    int tid = threadIdx.x, ty = tid >> 4, tx = tid & 15;
    float acc[8][4];
#pragma unroll
    for (int i = 0; i < 8; i++)
#pragma unroll
        for (int j = 0; j < 4; j++) acc[i][j] = 0.f;

    for (int m0 = 0; m0 < 128; m0 += 16) {
#pragma unroll
        for (int l = 0; l < 2; l++) {
            int idx = tid + l * 256;
            int n = idx >> 2, c = (idx & 3) << 2;
            float4 v = *(const float4*)(At + (size_t)n * 128 + m0 + c);
            As[c + 0][n] = v.x; As[c + 1][n] = v.y; As[c + 2][n] = v.z; As[c + 3][n] = v.w;
        }
        {
            int rr = tid >> 4, cc = (tid & 15) << 2;
            *(float4*)&Gs[rr][cc] = *(const float4*)(Gb + (size_t)(m0 + rr) * 64 + cc);
        }
        __syncthreads();
#pragma unroll
        for (int k = 0; k < 16; k++) {
            float4 a0 = *(float4*)&As[k][ty * 8];
            float4 a1 = *(float4*)&As[k][ty * 8 + 4];
            float ar[8] = {a0.x, a0.y, a0.z, a0.w, a1.x, a1.y, a1.z, a1.w};
            float4 bv = *(float4*)&Gs[k][tx * 4];
            float br[4] = {bv.x, bv.y, bv.z, bv.w};
#pragma unroll
            for (int i = 0; i < 8; i++)
#pragma unroll
                for (int j = 0; j < 4; j++) acc[i][j] += ar[i] * br[j];
        }
        __syncthreads();
    }
#pragma unroll
    for (int i = 0; i < 8; i++) {
        int n = n0 + ty * 8 + i;
        float gt = g_gates[((size_t)b * NTOK + n) * 16 + h];
        size_t o = ((size_t)b * NTOK + n) * 1024 + h * 64 + tx * 4;
#pragma unroll
        for (int q = 0; q < 2; q++) {
            float v0 = acc[i][2 * q] * gt, v1 = acc[i][2 * q + 1] * gt;
            bf16 h0 = __float2bfloat16_rn(v0), h1 = __float2bfloat16_rn(v1);
            *(__nv_bfloat162*)(g_o1h + o + 2 * q) = __nv_bfloat162(h0, h1);
            *(__nv_bfloat162*)(g_o1l + o + 2 * q) = __nv_bfloat162(
                __float2bfloat16_rn(v0 - __bfloat162float(h0)),
                __float2bfloat16_rn(v1 - __bfloat162float(h1)));
        }
    }
}

// ---------------- launch ----------------
extern "C" void kernel_launch(void* const* d_in, const int* in_sizes, int n_in,
                              void* d_out, int out_size) {
    const float* x      = (const float*)d_in[0];
    const float* W_qkv  = (const float*)d_in[1];
    const float* W_gate = (const float*)d_in[2];
    const float* b_gate = (const float*)d_in[3];
    const float* agent  = (const float*)d_in[4];
    const float* W_qa   = (const float*)d_in[5];
    const float* W_ak   = (const float*)d_in[6];
    const float* W_out  = (const float*)d_in[7];
    float* out = (float*)d_out;

    float *qkv, *qa;
    bf16 *xh, *xl, *w1h, *w1l, *w2h, *w2l, *o1h, *o1l;
    cudaGetSymbolAddress((void**)&qkv, g_qkv);
    cudaGetSymbolAddress((void**)&qa,  g_qa);
    cudaGetSymbolAddress((void**)&xh,  g_xh);
    cudaGetSymbolAddress((void**)&xl,  g_xl);
    cudaGetSymbolAddress((void**)&w1h, g_w1h);
    cudaGetSymbolAddress((void**)&w1l, g_w1l);
    cudaGetSymbolAddress((void**)&w2h, g_w2h);
    cudaGetSymbolAddress((void**)&w2l, g_w2l);
    cudaGetSymbolAddress((void**)&o1h, g_o1h);
    cudaGetSymbolAddress((void**)&o1l, g_o1l);

    cudaFuncSetAttribute(mma_gemm16, cudaFuncAttributeMaxDynamicSharedMemorySize, MMA16_SMEM);
    cudaFuncSetAttribute(qa_mma, cudaFuncAttributeMaxDynamicSharedMemorySize, ATT_SMEM);
    cudaFuncSetAttribute(ak_mma, cudaFuncAttributeMaxDynamicSharedMemorySize, ATT_SMEM);

    // 0. operand prep
    split_bf16<<<(ROWS * 1024 / 4) / 256, 256>>>(x, xh, xl);
    transpose_split<<<dim3(3072 / 32, 1024 / 32), 256>>>(W_qkv, w1h, w1l, 1024, 3072);
    transpose_split<<<dim3(1024 / 32, 1024 / 32), 256>>>(W_out, w2h, w2l, 1024, 1024);
    wgate_t<<<64, 256>>>(W_gate);
    // 1. QKV projection
    mma_gemm16<<<dim3(3072 / 128, ROWS / 128), 256, MMA16_SMEM>>>(xh, xl, w1h, w1l, qkv, 3072);
    // 2. gates
    gates_kernel<<<ROWS / 8, 256>>>(x, b_gate);
    // 3. qa (+fused softmax) and ak score MMAs
    qa_mma<<<dim3(NTOK / 128, BH), 256, ATT_SMEM>>>(agent);
    ak_mma<<<dim3(NTOK / 128, BH), 256, ATT_SMEM>>>(agent);
    // 4. ak stats + fused softmax-apply/talking-heads
    ak_stats<<<BH * MM, 256>>>();
    th_mix_ak<<<(BB * MM * NTOK) / 256, 256>>>(W_ak);
    // 5. talking heads for qa
    th_mix<<<(BB * NTOK * MM) / 256, 256>>>(qa, W_qa);
    // 6. agent_gathered
    gather_kernel<<<dim3(GSPLIT, BH), 256>>>();
    reduce_gather<<<(BH * MM * DHH) / 256, 256>>>(out + (size_t)ROWS * DD);
    // 7. out stage (fused gating + bf16 split)
    outstage_kernel<<<dim3(NTOK / 128, BH), 256>>>();
    // 8. final projection
    mma_gemm16<<<dim3(DD / 128, ROWS / 128), 256, MMA16_SMEM>>>(o1h, o1l, w2h, w2l, out, DD);
}

// round 9
// speedup vs baseline: 2.4219x; 1.0205x over previous
#include <cuda_runtime.h>
#include <cuda_bf16.h>
#include <math.h>
#include <stdint.h>

// Problem constants
#define BB    4
#define NTOK  4096
#define DD    1024
#define HH    16
#define MM    128
#define DHH   64
#define SCALE 0.125f
#define ROWS  (BB*NTOK)        // 16384
#define BH    (BB*HH)          // 64
#define GSPLIT 16

typedef __nv_bfloat16 bf16;

// ---------------- device scratch (static, allowed) ----------------
__device__ float g_qkv[ROWS * 3072];
__device__ float g_qa [BH * NTOK * MM];
__device__ float g_ak [BH * MM * NTOK];
__device__ float g_akmx[BH * MM];
__device__ float g_akinv[BH * MM];
__device__ float g_gpart[GSPLIT * BH * MM * DHH];
__device__ float g_gather[BH * MM * DHH];
__device__ float g_gates[ROWS * HH];
__device__ float g_wgt[HH * 1024];
__device__ bf16 g_xh[ROWS * 1024];
__device__ bf16 g_xl[ROWS * 1024];
__device__ bf16 g_w1h[3072 * 1024];
__device__ bf16 g_w1l[3072 * 1024];
__device__ bf16 g_w2h[1024 * 1024];
__device__ bf16 g_w2l[1024 * 1024];
__device__ bf16 g_o1h[ROWS * 1024];
__device__ bf16 g_o1l[ROWS * 1024];

__device__ __forceinline__ uint32_t smem_u32(const void* p) {
    uint32_t a;
    asm("{ .reg .u64 t; cvta.to.shared.u64 t, %1; cvt.u32.u64 %0, t; }" : "=r"(a) : "l"(p));
    return a;
}
__device__ __forceinline__ void cp16(uint32_t dst, const void* src) {
    asm volatile("cp.async.cg.shared.global [%0], [%1], 16;" :: "r"(dst), "l"(src) : "memory");
}
__device__ __forceinline__ void mma_bf16(float* d, const uint32_t* a, const uint32_t* b) {
    asm volatile(
        "mma.sync.aligned.m16n8k16.row.col.f32.bf16.bf16.f32 "
        "{%0,%1,%2,%3}, {%4,%5,%6,%7}, {%8,%9}, {%0,%1,%2,%3};\n"
        : "+f"(d[0]), "+f"(d[1]), "+f"(d[2]), "+f"(d[3])
        : "r"(a[0]), "r"(a[1]), "r"(a[2]), "r"(a[3]), "r"(b[0]), "r"(b[1]));
}
__device__ __forceinline__ void store_split4(char* hp, char* lp, float4 v) {
    bf16 h0 = __float2bfloat16_rn(v.x), h1 = __float2bfloat16_rn(v.y);
    bf16 h2 = __float2bfloat16_rn(v.z), h3 = __float2bfloat16_rn(v.w);
    *(__nv_bfloat162*)hp       = __nv_bfloat162(h0, h1);
    *(__nv_bfloat162*)(hp + 4) = __nv_bfloat162(h2, h3);
    *(__nv_bfloat162*)lp       = __nv_bfloat162(
        __float2bfloat16_rn(v.x - __bfloat162float(h0)),
        __float2bfloat16_rn(v.y - __bfloat162float(h1)));
    *(__nv_bfloat162*)(lp + 4) = __nv_bfloat162(
        __float2bfloat16_rn(v.z - __bfloat162float(h2)),
        __float2bfloat16_rn(v.w - __bfloat162float(h3)));
}
// split one float into bf16 hi/lo, store to two smem addrs (for transposed loads)
__device__ __forceinline__ void store_split1(char* hp, char* lp, float v) {
    bf16 h = __float2bfloat16_rn(v);
    *(bf16*)hp = h;
    *(bf16*)lp = __float2bfloat16_rn(v - __bfloat162float(h));
}

// ================= bf16 2-way split GEMM (dense projections) =================
#define KDIM 1024
#define NK16 16
#define STAGE_BYTES16 73728
#define MMA16_SMEM (3 * STAGE_BYTES16)

__device__ __forceinline__ void ld_stage16(const bf16* __restrict__ Ah,
                                           const bf16* __restrict__ Al,
                                           const bf16* __restrict__ Bh,
                                           const bf16* __restrict__ Bl,
                                           int m0, int n0, int kc,
                                           uint32_t sbase, int tid) {
    uint32_t sb = sbase + (uint32_t)(kc % 3) * STAGE_BYTES16;
#pragma unroll
    for (int i = 0; i < 4; i++) {
        int id = tid + i * 256; int r = id >> 3, f = id & 7;
        cp16(sb + (uint32_t)(r * 144 + f * 16), Ah + (size_t)(m0 + r) * KDIM + kc * 64 + f * 8);
    }
#pragma unroll
    for (int i = 0; i < 4; i++) {
        int id = tid + i * 256; int r = id >> 3, f = id & 7;
        cp16(sb + (uint32_t)((128 + r) * 144 + f * 16), Al + (size_t)(m0 + r) * KDIM + kc * 64 + f * 8);
    }
#pragma unroll
    for (int i = 0; i < 4; i++) {
        int id = tid + i * 256; int r = id >> 3, f = id & 7;
        cp16(sb + (uint32_t)((256 + r) * 144 + f * 16), Bh + (size_t)(n0 + r) * KDIM + kc * 64 + f * 8);
    }
#pragma unroll
    for (int i = 0; i < 4; i++) {
        int id = tid + i * 256; int r = id >> 3, f = id & 7;
        cp16(sb + (uint32_t)((384 + r) * 144 + f * 16), Bl + (size_t)(n0 + r) * KDIM + kc * 64 + f * 8);
    }
    asm volatile("cp.async.commit_group;" ::: "memory");
}

__global__ __launch_bounds__(256) void mma_gemm16(const bf16* __restrict__ Ah,
                                                  const bf16* __restrict__ Al,
                                                  const bf16* __restrict__ Bth,
                                                  const bf16* __restrict__ Btl,
                                                  float* __restrict__ C, int Nc) {
    extern __shared__ char smv[];
    const int tid = threadIdx.x, wid = tid >> 5, lane = tid & 31;
    const int m0 = blockIdx.y * 128, n0 = blockIdx.x * 128;
    const int wm = (wid & 3) * 32, wn = (wid >> 2) * 64;
    const int g = lane >> 2, t = lane & 3;
    uint32_t sbase = smem_u32(smv);

    ld_stage16(Ah, Al, Bth, Btl, m0, n0, 0, sbase, tid);
    ld_stage16(Ah, Al, Bth, Btl, m0, n0, 1, sbase, tid);

    float acc[2][8][4];
#pragma unroll
    for (int i = 0; i < 2; i++)
#pragma unroll
        for (int j = 0; j < 8; j++)
#pragma unroll
            for (int q = 0; q < 4; q++) acc[i][j][q] = 0.f;

    for (int kc = 0; kc < NK16; kc++) {
        if (kc + 2 < NK16) {
            ld_stage16(Ah, Al, Bth, Btl, m0, n0, kc + 2, sbase, tid);
            asm volatile("cp.async.wait_group 2;" ::: "memory");
        } else if (kc == NK16 - 2) {
            asm volatile("cp.async.wait_group 1;" ::: "memory");
        } else {
            asm volatile("cp.async.wait_group 0;" ::: "memory");
        }
        __syncthreads();
        const uint32_t* S = (const uint32_t*)(smv + (kc % 3) * STAGE_BYTES16);
#pragma unroll
        for (int ks = 0; ks < 4; ks++) {
            const int ko = ks * 8 + t;
            uint32_t ah[2][4], al[2][4];
#pragma unroll
            for (int i = 0; i < 2; i++) {
                const uint32_t* p = S + (wm + i * 16 + g) * 36 + ko;
                ah[i][0] = p[0]; ah[i][1] = p[288]; ah[i][2] = p[4]; ah[i][3] = p[292];
                const uint32_t* q = p + 128 * 36;
                al[i][0] = q[0]; al[i][1] = q[288]; al[i][2] = q[4]; al[i][3] = q[292];
            }
#pragma unroll
            for (int j = 0; j < 8; j++) {
                const uint32_t* pb = S + (256 + wn + j * 8 + g) * 36 + ko;
                uint32_t bhv[2] = {pb[0], pb[4]};
                uint32_t blv[2] = {pb[128 * 36], pb[128 * 36 + 4]};
#pragma unroll
                for (int i = 0; i < 2; i++) {
                    mma_bf16(acc[i][j], ah[i], blv);
                    mma_bf16(acc[i][j], al[i], bhv);
                    mma_bf16(acc[i][j], ah[i], bhv);
                }
            }
        }
        __syncthreads();
    }

#pragma unroll
    for (int i = 0; i < 2; i++) {
#pragma unroll
        for (int j = 0; j < 8; j++) {
            size_t r0 = (size_t)(m0 + wm + i * 16 + g);
            int c = n0 + wn + j * 8 + 2 * t;
            *(float2*)(C + r0 * Nc + c)       = make_float2(acc[i][j][0], acc[i][j][1]);
            *(float2*)(C + (r0 + 8) * Nc + c) = make_float2(acc[i][j][2], acc[i][j][3]);
        }
    }
}

// ================= attention-side 128x128xK=64 split-bf16 MMA =================
#define ATT_SMEM 73728

// qa: A = q, B = a*SCALE; fused softmax over m; writes g_qa[bh][n][m]
__global__ __launch_bounds__(256) void qa_mma(const float* __restrict__ agent) {
    extern __shared__ char smv[];
    __shared__ float smx[128][2];
    __shared__ float ssum[128][2];
    const int tid = threadIdx.x, wid = tid >> 5, lane = tid & 31;
    const int bh = blockIdx.y, b = bh >> 4, h = bh & 15;
    const int n0 = blockIdx.x * 128;
    const int wm = (wid & 3) * 32, wn = (wid >> 2) * 64;
    const int g = lane >> 2, t = lane & 3;
    const int half = wid >> 2;

    const float* qptr = g_qkv + ((size_t)(b * NTOK + n0)) * 3072 + h * 64;
    const float* aptr = agent + (size_t)h * MM * DHH;
#pragma unroll
    for (int i = 0; i < 8; i++) {
        int id = tid + i * 256;
        int r = id >> 4, f4 = id & 15;
        float4 v = *(const float4*)(qptr + (size_t)r * 3072 + f4 * 4);
        store_split4(smv + r * 144 + f4 * 8, smv + (128 + r) * 144 + f4 * 8, v);
    }
#pragma unroll
    for (int i = 0; i < 8; i++) {
        int id = tid + i * 256;
        int r = id >> 4, f4 = id & 15;
        float4 v = *(const float4*)(aptr + r * 64 + f4 * 4);
        v.x *= SCALE; v.y *= SCALE; v.z *= SCALE; v.w *= SCALE;
        store_split4(smv + (256 + r) * 144 + f4 * 8, smv + (384 + r) * 144 + f4 * 8, v);
    }
    __syncthreads();

    float acc[2][8][4];
#pragma unroll
    for (int i = 0; i < 2; i++)
#pragma unroll
        for (int j = 0; j < 8; j++)
#pragma unroll
            for (int q = 0; q < 4; q++) acc[i][j][q] = 0.f;
    const uint32_t* S = (const uint32_t*)smv;
#pragma unroll
    for (int ks = 0; ks < 4; ks++) {
        const int ko = ks * 8 + t;
        uint32_t ah[2][4], al[2][4];
#pragma unroll
        for (int i = 0; i < 2; i++) {
            const uint32_t* p = S + (wm + i * 16 + g) * 36 + ko;
            ah[i][0] = p[0]; ah[i][1] = p[288]; ah[i][2] = p[4]; ah[i][3] = p[292];
            const uint32_t* q = p + 128 * 36;
            al[i][0] = q[0]; al[i][1] = q[288]; al[i][2] = q[4]; al[i][3] = q[292];
        }
#pragma unroll
        for (int j = 0; j < 8; j++) {
            const uint32_t* pb = S + (256 + wn + j * 8 + g) * 36 + ko;
            uint32_t bhv[2] = {pb[0], pb[4]};
            uint32_t blv[2] = {pb[128 * 36], pb[128 * 36 + 4]};
#pragma unroll
            for (int i = 0; i < 2; i++) {
                mma_bf16(acc[i][j], ah[i], blv);
                mma_bf16(acc[i][j], al[i], bhv);
                mma_bf16(acc[i][j], ah[i], bhv);
            }
        }
    }

#pragma unroll
    for (int i = 0; i < 2; i++) {
#pragma unroll
        for (int qh = 0; qh < 2; qh++) {
            float lm = -1e30f;
#pragma unroll
            for (int j = 0; j < 8; j++)
                lm = fmaxf(lm, fmaxf(acc[i][j][qh * 2], acc[i][j][qh * 2 + 1]));
            lm = fmaxf(lm, __shfl_xor_sync(0xffffffffu, lm, 1));
            lm = fmaxf(lm, __shfl_xor_sync(0xffffffffu, lm, 2));
            if (t == 0) smx[wm + i * 16 + g + qh * 8][half] = lm;
        }
    }
    __syncthreads();
#pragma unroll
    for (int i = 0; i < 2; i++) {
#pragma unroll
        for (int qh = 0; qh < 2; qh++) {
            int r = wm + i * 16 + g + qh * 8;
            float mx = fmaxf(smx[r][0], smx[r][1]);
            float ls = 0.f;
#pragma unroll
            for (int j = 0; j < 8; j++) {
                acc[i][j][qh * 2]     = expf(acc[i][j][qh * 2] - mx);
                acc[i][j][qh * 2 + 1] = expf(acc[i][j][qh * 2 + 1] - mx);
                ls += acc[i][j][qh * 2] + acc[i][j][qh * 2 + 1];
            }
            ls += __shfl_xor_sync(0xffffffffu, ls, 1);
            ls += __shfl_xor_sync(0xffffffffu, ls, 2);
            if (t == 0) ssum[r][half] = ls;
        }
    }
    __syncthreads();
#pragma unroll
    for (int i = 0; i < 2; i++) {
#pragma unroll
        for (int qh = 0; qh < 2; qh++) {
            int r = wm + i * 16 + g + qh * 8;
            float inv = 1.f / (ssum[r][0] + ssum[r][1]);
            float* rp = g_qa + ((size_t)bh * NTOK + n0 + r) * 128 + wn + 2 * t;
#pragma unroll
            for (int j = 0; j < 8; j++)
                *(float2*)(rp + j * 8) = make_float2(acc[i][j][qh * 2] * inv,
                                                     acc[i][j][qh * 2 + 1] * inv);
        }
    }
}

// ak: A = a*SCALE, B = k; writes raw scores g_ak[bh][m][n]
__global__ __launch_bounds__(256) void ak_mma(const float* __restrict__ agent) {
    extern __shared__ char smv[];
    const int tid = threadIdx.x, wid = tid >> 5, lane = tid & 31;
    const int bh = blockIdx.y, b = bh >> 4, h = bh & 15;
    const int n0 = blockIdx.x * 128;
    const int wm = (wid & 3) * 32, wn = (wid >> 2) * 64;
    const int g = lane >> 2, t = lane & 3;

    const float* aptr = agent + (size_t)h * MM * DHH;
    const float* kptr = g_qkv + ((size_t)(b * NTOK + n0)) * 3072 + 1024 + h * 64;
#pragma unroll
    for (int i = 0; i < 8; i++) {
        int id = tid + i * 256;
        int r = id >> 4, f4 = id & 15;
        float4 v = *(const float4*)(aptr + r * 64 + f4 * 4);
        v.x *= SCALE; v.y *= SCALE; v.z *= SCALE; v.w *= SCALE;
        store_split4(smv + r * 144 + f4 * 8, smv + (128 + r) * 144 + f4 * 8, v);
    }
#pragma unroll
    for (int i = 0; i < 8; i++) {
        int id = tid + i * 256;
        int r = id >> 4, f4 = id & 15;
        float4 v = *(const float4*)(kptr + (size_t)r * 3072 + f4 * 4);
        store_split4(smv + (256 + r) * 144 + f4 * 8, smv + (384 + r) * 144 + f4 * 8, v);
    }
    __syncthreads();

    float acc[2][8][4];
#pragma unroll
    for (int i = 0; i < 2; i++)
#pragma unroll
        for (int j = 0; j < 8; j++)
#pragma unroll
            for (int q = 0; q < 4; q++) acc[i][j][q] = 0.f;
    const uint32_t* S = (const uint32_t*)smv;
#pragma unroll
    for (int ks = 0; ks < 4; ks++) {
        const int ko = ks * 8 + t;
        uint32_t ah[2][4], al[2][4];
#pragma unroll
        for (int i = 0; i < 2; i++) {
            const uint32_t* p = S + (wm + i * 16 + g) * 36 + ko;
            ah[i][0] = p[0]; ah[i][1] = p[288]; ah[i][2] = p[4]; ah[i][3] = p[292];
            const uint32_t* q = p + 128 * 36;
            al[i][0] = q[0]; al[i][1] = q[288]; al[i][2] = q[4]; al[i][3] = q[292];
        }
#pragma unroll
        for (int j = 0; j < 8; j++) {
            const uint32_t* pb = S + (256 + wn + j * 8 + g) * 36 + ko;
            uint32_t bhv[2] = {pb[0], pb[4]};
            uint32_t blv[2] = {pb[128 * 36], pb[128 * 36 + 4]};
#pragma unroll
            for (int i = 0; i < 2; i++) {
                mma_bf16(acc[i][j], ah[i], blv);
                mma_bf16(acc[i][j], al[i], bhv);
                mma_bf16(acc[i][j], ah[i], bhv);
            }
        }
    }

#pragma unroll
    for (int i = 0; i < 2; i++) {
#pragma unroll
        for (int j = 0; j < 8; j++) {
            int m = wm + i * 16 + g;
            int c = n0 + wn + j * 8 + 2 * t;
            *(float2*)(g_ak + ((size_t)bh * MM + m) * NTOK + c) =
                make_float2(acc[i][j][0], acc[i][j][1]);
            *(float2*)(g_ak + ((size_t)bh * MM + m + 8) * NTOK + c) =
                make_float2(acc[i][j][2], acc[i][j][3]);
        }
    }
}

// ================= gather: 128m x 64d, K-split over n (bf16 split MMA) ==========
// smem rows: A_hi 0-127, A_lo 128-255, B_hi 256-319, B_lo 320-383 (144B stride)
#define G_SMEM (384 * 144)

__global__ __launch_bounds__(256) void gather_mma() {
    extern __shared__ char smv[];
    const int tid = threadIdx.x, wid = tid >> 5, lane = tid & 31;
    const int bh = blockIdx.y, b = bh >> 4, h = bh & 15;
    const int split = blockIdx.x;        // 0..GSPLIT-1, K=256 tokens each
    const int wm = (wid & 3) * 32, wn = (wid >> 2) * 32;
    const int g = lane >> 2, t = lane & 3;

    const float* At = g_ak + (size_t)bh * MM * NTOK;                   // [m][n]
    const float* Vb = g_qkv + (size_t)b * NTOK * 3072 + 2048 + h * 64; // [n][d] stride 3072

    float acc[2][4][4];
#pragma unroll
    for (int i = 0; i < 2; i++)
#pragma unroll
        for (int j = 0; j < 4; j++)
#pragma unroll
            for (int q = 0; q < 4; q++) acc[i][j][q] = 0.f;

    for (int ch = 0; ch < 4; ch++) {
        int nb = split * 256 + ch * 64;
        // A: ak[m][nb..nb+63] -> split rows m / 128+m
#pragma unroll
        for (int i = 0; i < 8; i++) {
            int id = tid + i * 256;          // 0..2047
            int r = id >> 4, f4 = id & 15;
            float4 v = *(const float4*)(At + (size_t)r * NTOK + nb + f4 * 4);
            store_split4(smv + r * 144 + f4 * 8, smv + (128 + r) * 144 + f4 * 8, v);
        }
        // B: V[nb+n][d] transposed -> rows 256+d (hi) / 320+d (lo), col n
#pragma unroll
        for (int i = 0; i < 4; i++) {
            int id = tid + i * 256;          // 0..1023
            int n = id >> 4, d4 = (id & 15) * 4;
            float4 v = *(const float4*)(Vb + (size_t)(nb + n) * 3072 + d4);
            store_split1(smv + (256 + d4 + 0) * 144 + n * 2, smv + (320 + d4 + 0) * 144 + n * 2, v.x);
            store_split1(smv + (256 + d4 + 1) * 144 + n * 2, smv + (320 + d4 + 1) * 144 + n * 2, v.y);
            store_split1(smv + (256 + d4 + 2) * 144 + n * 2, smv + (320 + d4 + 2) * 144 + n * 2, v.z);
            store_split1(smv + (256 + d4 + 3) * 144 + n * 2, smv + (320 + d4 + 3) * 144 + n * 2, v.w);
        }
        __syncthreads();
        const uint32_t* S = (const uint32_t*)smv;
#pragma unroll
        for (int ks = 0; ks < 4; ks++) {
            const int ko = ks * 8 + t;
            uint32_t ah[2][4], al[2][4];
#pragma unroll
            for (int i = 0; i < 2; i++) {
                const uint32_t* p = S + (wm + i * 16 + g) * 36 + ko;
                ah[i][0] = p[0]; ah[i][1] = p[288]; ah[i][2] = p[4]; ah[i][3] = p[292];
                const uint32_t* q = p + 128 * 36;
                al[i][0] = q[0]; al[i][1] = q[288]; al[i][2] = q[4]; al[i][3] = q[292];
            }
#pragma unroll
            for (int j = 0; j < 4; j++) {
                const uint32_t* pb = S + (256 + wn + j * 8 + g) * 36 + ko;
                uint32_t bhv[2] = {pb[0], pb[4]};
                uint32_t blv[2] = {pb[64 * 36], pb[64 * 36 + 4]};
#pragma unroll
                for (int i = 0; i < 2; i++) {
                    mma_bf16(acc[i][j], ah[i], blv);
                    mma_bf16(acc[i][j], al[i], bhv);
                    mma_bf16(acc[i][j], ah[i], bhv);
                }
            }
        }
        __syncthreads();
    }
    float* Ob = g_gpart + (size_t)split * BH * MM * DHH + (size_t)bh * MM * DHH;
#pragma unroll
    for (int i = 0; i < 2; i++) {
#pragma unroll
        for (int j = 0; j < 4; j++) {
            int m = wm + i * 16 + g;
            int d = wn + j * 8 + 2 * t;
            *(float2*)(Ob + (size_t)m * 64 + d)       = make_float2(acc[i][j][0], acc[i][j][1]);
            *(float2*)(Ob + (size_t)(m + 8) * 64 + d) = make_float2(acc[i][j][2], acc[i][j][3]);
        }
    }
}

// ---------------- reduce partials ----------------
__global__ __launch_bounds__(256) void reduce_gather(float* __restrict__ outtail) {
    int t = blockIdx.x * 256 + threadIdx.x;
    float s = 0.f;
#pragma unroll
    for (int i = 0; i < GSPLIT; i++) s += g_gpart[(size_t)i * (BH * MM * DHH) + t];
    g_gather[t] = s;
    outtail[t] = s;
}

// ================= outstage: 128n x 64d, K=128 (bf16 split MMA) + gate + split write ==
__global__ __launch_bounds__(256) void outstage_mma() {
    extern __shared__ char smv[];
    const int tid = threadIdx.x, wid = tid >> 5, lane = tid & 31;
    const int bh = blockIdx.y, b = bh >> 4, h = bh & 15;
    const int n0 = blockIdx.x * 128;
    const int wm = (wid & 3) * 32, wn = (wid >> 2) * 32;
    const int g = lane >> 2, t = lane & 3;

    const float* At = g_qa + ((size_t)bh * NTOK + n0) * 128;   // [n][m]
    const float* Gb = g_gather + (size_t)bh * MM * DHH;        // [m][d]

    float acc[2][4][4];
#pragma unroll
    for (int i = 0; i < 2; i++)
#pragma unroll
        for (int j = 0; j < 4; j++)
#pragma unroll
            for (int q = 0; q < 4; q++) acc[i][j][q] = 0.f;

    for (int ch = 0; ch < 2; ch++) {
        int mb = ch * 64;
        // A: qa[n][mb..mb+63]
#pragma unroll
        for (int i = 0; i < 8; i++) {
            int id = tid + i * 256;
            int r = id >> 4, f4 = id & 15;
            float4 v = *(const float4*)(At + (size_t)r * 128 + mb + f4 * 4);
            store_split4(smv + r * 144 + f4 * 8, smv + (128 + r) * 144 + f4 * 8, v);
        }
        // B: gather[mb+m][d] transposed -> rows 256+d / 320+d, col m
#pragma unroll
        for (int i = 0; i < 4; i++) {
            int id = tid + i * 256;
            int m = id >> 4, d4 = (id & 15) * 4;
            float4 v = *(const float4*)(Gb + (size_t)(mb + m) * 64 + d4);
            store_split1(smv + (256 + d4 + 0) * 144 + m * 2, smv + (320 + d4 + 0) * 144 + m * 2, v.x);
            store_split1(smv + (256 + d4 + 1) * 144 + m * 2, smv + (320 + d4 + 1) * 144 + m * 2, v.y);
            store_split1(smv + (256 + d4 + 2) * 144 + m * 2, smv + (320 + d4 + 2) * 144 + m * 2, v.z);
            store_split1(smv + (256 + d4 + 3) * 144 + m * 2, smv + (320 + d4 + 3) * 144 + m * 2, v.w);
        }
        __syncthreads();
        const uint32_t* S = (const uint32_t*)smv;
#pragma unroll
        for (int ks = 0; ks < 4; ks++) {
            const int ko = ks * 8 + t;
            uint32_t ah[2][4], al[2][4];
#pragma unroll
            for (int i = 0; i < 2; i++) {
                const uint32_t* p = S + (wm + i * 16 + g) * 36 + ko;
                ah[i][0] = p[0]; ah[i][1] = p[288]; ah[i][2] = p[4]; ah[i][3] = p[292];
                const uint32_t* q = p + 128 * 36;
                al[i][0] = q[0]; al[i][1] = q[288]; al[i][2] = q[4]; al[i][3] = q[292];
            }
#pragma unroll
            for (int j = 0; j < 4; j++) {
                const uint32_t* pb = S + (256 + wn + j * 8 + g) * 36 + ko;
                uint32_t bhv[2] = {pb[0], pb[4]};
                uint32_t blv[2] = {pb[64 * 36], pb[64 * 36 + 4]};
#pragma unroll
                for (int i = 0; i < 2; i++) {
                    mma_bf16(acc[i][j], ah[i], blv);
                    mma_bf16(acc[i][j], al[i], bhv);
                    mma_bf16(acc[i][j], ah[i], bhv);
                }
            }
        }
        __syncthreads();
    }
    // epilogue: gate + bf16 split write
#pragma unroll
    for (int i = 0; i < 2; i++) {
        int n_lo = n0 + wm + i * 16 + g;
        float gt0 = g_gates[((size_t)b * NTOK + n_lo) * 16 + h];
        float gt1 = g_gates[((size_t)b * NTOK + n_lo + 8) * 16 + h];
#pragma unroll
        for (int j = 0; j < 4; j++) {
            int d = wn + j * 8 + 2 * t;
            size_t o0 = ((size_t)b * NTOK + n_lo) * 1024 + h * 64 + d;
            size_t o1 = o0 + (size_t)8 * 1024;
            {
                float v0 = acc[i][j][0] * gt0, v1 = acc[i][j][1] * gt0;
                bf16 h0 = __float2bfloat16_rn(v0), h1 = __float2bfloat16_rn(v1);
                *(__nv_bfloat162*)(g_o1h + o0) = __nv_bfloat162(h0, h1);
                *(__nv_bfloat162*)(g_o1l + o0) = __nv_bfloat162(
                    __float2bfloat16_rn(v0 - __bfloat162float(h0)),
                    __float2bfloat16_rn(v1 - __bfloat162float(h1)));
            }
            {
                float v0 = acc[i][j][2] * gt1, v1 = acc[i][j][3] * gt1;
                bf16 h0 = __float2bfloat16_rn(v0), h1 = __float2bfloat16_rn(v1);
                *(__nv_bfloat162*)(g_o1h + o1) = __nv_bfloat162(h0, h1);
                *(__nv_bfloat162*)(g_o1l + o1) = __nv_bfloat162(
                    __float2bfloat16_rn(v0 - __bfloat162float(h0)),
                    __float2bfloat16_rn(v1 - __bfloat162float(h1)));
            }
        }
    }
}

// ---------------- elementwise bf16 split ----------------
__global__ __launch_bounds__(256) void split_bf16(const float* __restrict__ src,
                                                  bf16* __restrict__ hi,
                                                  bf16* __restrict__ lo) {
    size_t i = (size_t)blockIdx.x * 256 + threadIdx.x;
    float4 v = ((const float4*)src)[i];
    bf16 hx = __float2bfloat16_rn(v.x), hy = __float2bfloat16_rn(v.y);
    bf16 hz = __float2bfloat16_rn(v.z), hw = __float2bfloat16_rn(v.w);
    ((__nv_bfloat162*)hi)[2 * i]     = __nv_bfloat162(hx, hy);
    ((__nv_bfloat162*)hi)[2 * i + 1] = __nv_bfloat162(hz, hw);
    ((__nv_bfloat162*)lo)[2 * i]     = __nv_bfloat162(
        __float2bfloat16_rn(v.x - __bfloat162float(hx)),
        __float2bfloat16_rn(v.y - __bfloat162float(hy)));
    ((__nv_bfloat162*)lo)[2 * i + 1] = __nv_bfloat162(
        __float2bfloat16_rn(v.z - __bfloat162float(hz)),
        __float2bfloat16_rn(v.w - __bfloat162float(hw)));
}

// ---------------- transpose + bf16 split ----------------
__global__ __launch_bounds__(256) void transpose_split(const float* __restrict__ src,
                                                       bf16* __restrict__ dh,
                                                       bf16* __restrict__ dl,
                                                       int K, int N) {
    __shared__ float t[32][33];
    int bx = blockIdx.x * 32, by = blockIdx.y * 32;
    int lx = threadIdx.x & 31, ly = threadIdx.x >> 5;
#pragma unroll
    for (int i = 0; i < 32; i += 8)
        t[ly + i][lx] = src[(size_t)(by + ly + i) * N + bx + lx];
    __syncthreads();
#pragma unroll
    for (int i = 0; i < 32; i += 8) {
        float v = t[lx][ly + i];
        bf16 h = __float2bfloat16_rn(v);
        size_t o = (size_t)(bx + ly + i) * K + by + lx;
        dh[o] = h;
        dl[o] = __float2bfloat16_rn(v - __bfloat162float(h));
    }
}

// ---------------- W_gate transpose ----------------
__global__ __launch_bounds__(256) void wgate_t(const float* __restrict__ Wg) {
    int t = blockIdx.x * 256 + threadIdx.x;
    int d = t >> 4, h = t & 15;
    g_wgt[h * 1024 + d] = Wg[t];
}

// ---------------- gates ----------------
__global__ __launch_bounds__(256) void gates_kernel(const float* __restrict__ x,
                                                    const float* __restrict__ bg) {
    int wid = threadIdx.x >> 5, lane = threadIdx.x & 31;
    int row = blockIdx.x * 8 + wid;
    const float* xr = x + (size_t)row * 1024;
    float acc[16];
#pragma unroll
    for (int h = 0; h < 16; h++) acc[h] = 0.f;
#pragma unroll 4
    for (int i = 0; i < 32; i++) {
        int d = i * 32 + lane;
        float xv = xr[d];
#pragma unroll
        for (int h = 0; h < 16; h++) acc[h] += xv * g_wgt[h * 1024 + d];
    }
#pragma unroll
    for (int h = 0; h < 16; h++) {
#pragma unroll
        for (int o = 16; o; o >>= 1) acc[h] += __shfl_xor_sync(0xffffffffu, acc[h], o);
    }
    if (lane < 16)
        g_gates[(size_t)row * 16 + lane] = 1.f / (1.f + expf(-(acc[lane] + bg[lane])));
}

// ---------------- ak row stats ----------------
__global__ __launch_bounds__(256) void ak_stats() {
    __shared__ float redm[8];
    __shared__ float reds[8];
    const float4* rp = (const float4*)(g_ak + (size_t)blockIdx.x * 4096);
    int tid = threadIdx.x, lane = tid & 31, w = tid >> 5;
    float4 v[4];
    float mx = -1e30f;
#pragma unroll
    for (int l = 0; l < 4; l++) {
        v[l] = rp[tid + l * 256];
        mx = fmaxf(mx, fmaxf(fmaxf(v[l].x, v[l].y), fmaxf(v[l].z, v[l].w)));
    }
#pragma unroll
    for (int o = 16; o; o >>= 1) mx = fmaxf(mx, __shfl_xor_sync(0xffffffffu, mx, o));
    if (lane == 0) redm[w] = mx;
    __syncthreads();
    mx = redm[0];
#pragma unroll
    for (int i = 1; i < 8; i++) mx = fmaxf(mx, redm[i]);
    float s = 0.f;
#pragma unroll
    for (int l = 0; l < 4; l++)
        s += expf(v[l].x - mx) + expf(v[l].y - mx) + expf(v[l].z - mx) + expf(v[l].w - mx);
#pragma unroll
    for (int o = 16; o; o >>= 1) s += __shfl_xor_sync(0xffffffffu, s, o);
    if (lane == 0) reds[w] = s;
    __syncthreads();
    if (tid == 0) {
        s = 0.f;
#pragma unroll
        for (int i = 0; i < 8; i++) s += reds[i];
        g_akmx[blockIdx.x] = mx;
        g_akinv[blockIdx.x] = 1.f / s;
    }
}

// ---------------- fused ak softmax-apply + talking heads ----------------
__global__ __launch_bounds__(256) void th_mix_ak(const float* __restrict__ W) {
    __shared__ float Ws[256];
    __shared__ float smx[16], sinv[16];
    int tid = threadIdx.x;
    Ws[tid] = W[tid];
    size_t t = (size_t)blockIdx.x * 256 + tid;
    const size_t inner = (size_t)MM * NTOK;
    size_t b = t >> 19;
    size_t rdx = t & (inner - 1);
    int m = (int)(rdx >> 12);
    if (tid < 16) {
        int row = ((int)b * 16 + tid) * 128 + m;
        smx[tid] = g_akmx[row];
        sinv[tid] = g_akinv[row];
    }
    __syncthreads();
    float* p = g_ak + b * 16 * inner + rdx;
    float e[16];
#pragma unroll
    for (int h = 0; h < 16; h++)
        e[h] = expf(p[(size_t)h * inner] - smx[h]) * sinv[h];
#pragma unroll
    for (int g = 0; g < 16; g++) {
        float a = 0.f;
#pragma unroll
        for (int h = 0; h < 16; h++) a += Ws[g * 16 + h] * e[h];
        p[(size_t)g * inner] = a;
    }
}

// ---------------- talking heads for qa ----------------
__global__ __launch_bounds__(256) void th_mix(float* __restrict__ data,
                                              const float* __restrict__ W) {
    __shared__ float Ws[256];
    Ws[threadIdx.x] = W[threadIdx.x];
    __syncthreads();
    size_t t = (size_t)blockIdx.x * 256 + threadIdx.x;
    const size_t inner = (size_t)NTOK * MM;
    size_t b = t >> 19;
    size_t idx = t & (inner - 1);
    float* p = data + b * 16 * inner + idx;
    float in[16];
#pragma unroll
    for (int h = 0; h < 16; h++) in[h] = p[(size_t)h * inner];
#pragma unroll
    for (int g = 0; g < 16; g++) {
        float a = 0.f;
#pragma unroll
        for (int h = 0; h < 16; h++) a += Ws[g * 16 + h] * in[h];
        p[(size_t)g * inner] = a;
    }
}

// ---------------- launch ----------------
extern "C" void kernel_launch(void* const* d_in, const int* in_sizes, int n_in,
                              void* d_out, int out_size) {
    const float* x      = (const float*)d_in[0];
    const float* W_qkv  = (const float*)d_in[1];
    const float* W_gate = (const float*)d_in[2];
    const float* b_gate = (const float*)d_in[3];
    const float* agent  = (const float*)d_in[4];
    const float* W_qa   = (const float*)d_in[5];
    const float* W_ak   = (const float*)d_in[6];
    const float* W_out  = (const float*)d_in[7];
    float* out = (float*)d_out;

    float *qkv, *qa;
    bf16 *xh, *xl, *w1h, *w1l, *w2h, *w2l, *o1h, *o1l;
    cudaGetSymbolAddress((void**)&qkv, g_qkv);
    cudaGetSymbolAddress((void**)&qa,  g_qa);
    cudaGetSymbolAddress((void**)&xh,  g_xh);
    cudaGetSymbolAddress((void**)&xl,  g_xl);
    cudaGetSymbolAddress((void**)&w1h, g_w1h);
    cudaGetSymbolAddress((void**)&w1l, g_w1l);
    cudaGetSymbolAddress((void**)&w2h, g_w2h);
    cudaGetSymbolAddress((void**)&w2l, g_w2l);
    cudaGetSymbolAddress((void**)&o1h, g_o1h);
    cudaGetSymbolAddress((void**)&o1l, g_o1l);

    cudaFuncSetAttribute(mma_gemm16, cudaFuncAttributeMaxDynamicSharedMemorySize, MMA16_SMEM);
    cudaFuncSetAttribute(qa_mma, cudaFuncAttributeMaxDynamicSharedMemorySize, ATT_SMEM);
    cudaFuncSetAttribute(ak_mma, cudaFuncAttributeMaxDynamicSharedMemorySize, ATT_SMEM);
    cudaFuncSetAttribute(gather_mma, cudaFuncAttributeMaxDynamicSharedMemorySize, G_SMEM);
    cudaFuncSetAttribute(outstage_mma, cudaFuncAttributeMaxDynamicSharedMemorySize, G_SMEM);

    // 0. operand prep
    split_bf16<<<(ROWS * 1024 / 4) / 256, 256>>>(x, xh, xl);
    transpose_split<<<dim3(3072 / 32, 1024 / 32), 256>>>(W_qkv, w1h, w1l, 1024, 3072);
    transpose_split<<<dim3(1024 / 32, 1024 / 32), 256>>>(W_out, w2h, w2l, 1024, 1024);
    wgate_t<<<64, 256>>>(W_gate);
    // 1. QKV projection
    mma_gemm16<<<dim3(3072 / 128, ROWS / 128), 256, MMA16_SMEM>>>(xh, xl, w1h, w1l, qkv, 3072);
    // 2. gates
    gates_kernel<<<ROWS / 8, 256>>>(x, b_gate);
    // 3. qa (+fused softmax) and ak score MMAs
    qa_mma<<<dim3(NTOK / 128, BH), 256, ATT_SMEM>>>(agent);
    ak_mma<<<dim3(NTOK / 128, BH), 256, ATT_SMEM>>>(agent);
    // 4. ak stats + fused softmax-apply/talking-heads
    ak_stats<<<BH * MM, 256>>>();
    th_mix_ak<<<(BB * MM * NTOK) / 256, 256>>>(W_ak);
    // 5. talking heads for qa
    th_mix<<<(BB * NTOK * MM) / 256, 256>>>(qa, W_qa);
    // 6. agent_gathered (tensor)
    gather_mma<<<dim3(GSPLIT, BH), 256, G_SMEM>>>();
    reduce_gather<<<(BH * MM * DHH) / 256, 256>>>(out + (size_t)ROWS * DD);
    // 7. out stage (tensor, fused gating + bf16 split)
    outstage_mma<<<dim3(NTOK / 128, BH), 256, G_SMEM>>>();
    // 8. final projection
    mma_gemm16<<<dim3(DD / 128, ROWS / 128), 256, MMA16_SMEM>>>(o1h, o1l, w2h, w2l, out, DD);
}